// round 5
// baseline (speedup 1.0000x reference)
#include <cuda_runtime.h>
#include <cuda_bf16.h>
#include <math.h>
#include <stdint.h>

#define BATCH 32
#define HW    1024
#define CDIM  256
#define FDIM  64

// ---------------- scratch (device globals; no allocations) ----------------
__device__ float g_sq[BATCH * HW];
__device__ float g_T[BATCH * HW];
__device__ __nv_bfloat16 g_Ehi[BATCH * HW * FDIM];       // [n][k]
__device__ __nv_bfloat16 g_Elo[BATCH * HW * FDIM];
__device__ __nv_bfloat16 g_EhiT[BATCH * FDIM * HW];      // [b][k][n]
__device__ __nv_bfloat16 g_EloT[BATCH * FDIM * HW];
__device__ __nv_bfloat16 g_xhi[BATCH * HW * CDIM];
__device__ __nv_bfloat16 g_xlo[BATCH * HW * CDIM];
__device__ __nv_bfloat16 g_SChi[BATCH * HW * CDIM];
__device__ __nv_bfloat16 g_SClo[BATCH * HW * CDIM];
__device__ __nv_bfloat16 g_Ahi[(size_t)BATCH * HW * HW];
__device__ __nv_bfloat16 g_Alo[(size_t)BATCH * HW * HW];
__device__ __nv_bfloat16 g_Wthi[CDIM * CDIM];            // attn_W^T split [cin][cout]
__device__ __nv_bfloat16 g_Wtlo[CDIM * CDIM];
__device__ float g_emb_Wt[CDIM * FDIM];

// ---------------- small helpers ----------------
__device__ __forceinline__ uint32_t smem_u32(const void* p) {
    return (uint32_t)__cvta_generic_to_shared(p);
}
__device__ __forceinline__ void cp16(uint32_t dst, const void* src) {
    asm volatile("cp.async.cg.shared.global [%0], [%1], 16;\n" :: "r"(dst), "l"(src));
}
__device__ __forceinline__ void cp_commit() { asm volatile("cp.async.commit_group;\n"); }
__device__ __forceinline__ void cp_wait1() { asm volatile("cp.async.wait_group 1;\n"); }
__device__ __forceinline__ void cp_wait0() { asm volatile("cp.async.wait_group 0;\n"); }
__device__ __forceinline__ void ldm_x4(uint32_t (&r)[4], uint32_t addr) {
    asm volatile("ldmatrix.sync.aligned.m8n8.x4.shared.b16 {%0,%1,%2,%3}, [%4];"
                 : "=r"(r[0]), "=r"(r[1]), "=r"(r[2]), "=r"(r[3]) : "r"(addr));
}
__device__ __forceinline__ void ldm_x4_t(uint32_t (&r)[4], uint32_t addr) {
    asm volatile("ldmatrix.sync.aligned.m8n8.x4.trans.shared.b16 {%0,%1,%2,%3}, [%4];"
                 : "=r"(r[0]), "=r"(r[1]), "=r"(r[2]), "=r"(r[3]) : "r"(addr));
}
__device__ __forceinline__ void mma16816(float (&d)[4], const uint32_t (&a)[4],
                                         uint32_t b0, uint32_t b1) {
    asm volatile("mma.sync.aligned.m16n8k16.row.col.f32.bf16.bf16.f32 "
                 "{%0,%1,%2,%3}, {%4,%5,%6,%7}, {%8,%9}, {%0,%1,%2,%3};"
                 : "+f"(d[0]), "+f"(d[1]), "+f"(d[2]), "+f"(d[3])
                 : "r"(a[0]), "r"(a[1]), "r"(a[2]), "r"(a[3]), "r"(b0), "r"(b1));
}
union BPack2 { __nv_bfloat16 h[2]; uint32_t u; };
union BPack4 { __nv_bfloat16 h[4]; uint2 u; };

// ---------------- prep: weight transposes + bf16 splits ----------------
__global__ void prep_kernel(const float* __restrict__ attn_W,
                            const float* __restrict__ emb_W) {
    int t = blockIdx.x * 256 + threadIdx.x;
    if (t < CDIM * CDIM) {
        int ci = t >> 8, co = t & 255;
        float v = attn_W[co * CDIM + ci];
        __nv_bfloat16 h = __float2bfloat16(v);
        g_Wthi[ci * CDIM + co] = h;
        g_Wtlo[ci * CDIM + co] = __float2bfloat16(v - __bfloat162float(h));
    }
    if (t < FDIM * CDIM) {
        int f = t >> 8, ci = t & 255;
        g_emb_Wt[ci * FDIM + f] = emb_W[f * CDIM + ci];
    }
}

// ---------------- emb: x @ emb_W^T + b -> bf16 hi/lo (+transposed) + sq + x-split ----------------
#define EMB_SMEM ((32 * 256 + 256 * 64) * 4)
__global__ __launch_bounds__(256) void emb_kernel(const float* __restrict__ x,
                                                  const float* __restrict__ emb_b) {
    extern __shared__ float sm[];
    float* xs = sm;              // [32][256]
    float* we = sm + 32 * 256;   // [256][64]
    int tid = threadIdx.x;
    int row0 = blockIdx.x * 32;
    int bb = row0 >> 10, n0 = row0 & 1023;

    const float4* xg = (const float4*)(x + (size_t)row0 * CDIM);
    float4* xs4 = (float4*)xs;
    for (int i = tid; i < 32 * 64; i += 256) xs4[i] = xg[i];
    const float4* wg = (const float4*)g_emb_Wt;
    float4* we4 = (float4*)we;
    for (int i = tid; i < 256 * 16; i += 256) we4[i] = wg[i];
    __syncthreads();

    // fused x -> bf16 hi/lo split (saves a separate 128MB-read kernel)
    for (int i = tid; i < 2048; i += 256) {
        float4 v = xs4[i];
        float vv[4] = {v.x, v.y, v.z, v.w};
        BPack4 ph, pl;
#pragma unroll
        for (int q = 0; q < 4; q++) {
            __nv_bfloat16 h = __float2bfloat16(vv[q]);
            ph.h[q] = h;
            pl.h[q] = __float2bfloat16(vv[q] - __bfloat162float(h));
        }
        ((uint2*)g_xhi)[(size_t)row0 * 64 + i] = ph.u;
        ((uint2*)g_xlo)[(size_t)row0 * 64 + i] = pl.u;
    }

    int w = tid >> 5, lane = tid & 31;
    int ig = w * 4, fg = lane * 2;
    float acc[4][2] = {};
#pragma unroll 4
    for (int c = 0; c < 256; c++) {
        float2 wv = *(const float2*)&we[c * 64 + fg];
#pragma unroll
        for (int q = 0; q < 4; q++) {
            float a = xs[(ig + q) * 256 + c];
            acc[q][0] = fmaf(a, wv.x, acc[q][0]);
            acc[q][1] = fmaf(a, wv.y, acc[q][1]);
        }
    }
    float b0 = emb_b[fg], b1 = emb_b[fg + 1];
    float e0r[4], e1r[4];
#pragma unroll
    for (int q = 0; q < 4; q++) {
        float e0 = acc[q][0] + b0, e1 = acc[q][1] + b1;
        e0r[q] = e0; e1r[q] = e1;
        int n = row0 + ig + q;
        BPack2 ph, pl;
        ph.h[0] = __float2bfloat16(e0);
        ph.h[1] = __float2bfloat16(e1);
        pl.h[0] = __float2bfloat16(e0 - __bfloat162float(ph.h[0]));
        pl.h[1] = __float2bfloat16(e1 - __bfloat162float(ph.h[1]));
        *(uint32_t*)&g_Ehi[(size_t)n * FDIM + fg] = ph.u;
        *(uint32_t*)&g_Elo[(size_t)n * FDIM + fg] = pl.u;
        float p = e0 * e0 + e1 * e1;
#pragma unroll
        for (int o = 16; o; o >>= 1) p += __shfl_xor_sync(0xffffffffu, p, o);
        if (lane == 0) g_sq[n] = p;
    }

    // transposed bf16 copies via smem staging: [64][33]
    __nv_bfloat16* st = (__nv_bfloat16*)sm;
    __syncthreads();
#pragma unroll
    for (int q = 0; q < 4; q++) {
        st[fg * 33 + ig + q] = __float2bfloat16(e0r[q]);
        st[(fg + 1) * 33 + ig + q] = __float2bfloat16(e1r[q]);
    }
    __syncthreads();
    for (int idx = tid; idx < 2048; idx += 256) {
        int k = idx >> 5, i2 = idx & 31;
        g_EhiT[(((size_t)bb * 64 + k) << 10) + n0 + i2] = st[k * 33 + i2];
    }
    __syncthreads();
#pragma unroll
    for (int q = 0; q < 4; q++) {
        float h0 = __bfloat162float(__float2bfloat16(e0r[q]));
        float h1 = __bfloat162float(__float2bfloat16(e1r[q]));
        st[fg * 33 + ig + q] = __float2bfloat16(e0r[q] - h0);
        st[(fg + 1) * 33 + ig + q] = __float2bfloat16(e1r[q] - h1);
    }
    __syncthreads();
    for (int idx = tid; idx < 2048; idx += 256) {
        int k = idx >> 5, i2 = idx & 31;
        g_EloT[(((size_t)bb * 64 + k) << 10) + n0 + i2] = st[k * 33 + i2];
    }
}

// ---------------- shortcut: SC = x @ W^T + b (3-term), plus T — 3-stage ring ----------------
#define SC_OFF_A 0
#define SC_OFF_B 15360
#define SC_OFF_T 66048
#define SC_SMEM  66304
__global__ __launch_bounds__(256) void shortcut_kernel(const float* __restrict__ attn_b,
                                                       const float* __restrict__ thr_W,
                                                       const float* __restrict__ thr_b) {
    extern __shared__ char smc[];
    __nv_bfloat16* Asp = (__nv_bfloat16*)(smc + SC_OFF_A);   // [3][64][40]
    __nv_bfloat16* Bsp = (__nv_bfloat16*)(smc + SC_OFF_B);   // [3][32][264]
    float* Tp = (float*)(smc + SC_OFF_T);
    int tid = threadIdx.x, w = tid >> 5, lane = tid & 31;
    int m0 = blockIdx.x * 64;
    int lrow = lane & 7, q1 = (lane >> 3) & 1, q2 = lane >> 4;

    if (tid < 64) Tp[tid] = 0.0f;

    float acc[4][4][4];
#pragma unroll
    for (int a = 0; a < 4; a++)
#pragma unroll
        for (int n = 0; n < 4; n++)
#pragma unroll
            for (int r = 0; r < 4; r++) acc[a][n][r] = 0.0f;

#define SC_ISSUE(s, bf_)                                                          \
    {                                                                             \
        int term_ = (s) >> 3, kc_ = (s) & 7;                                      \
        const __nv_bfloat16* Ap_ = (term_ == 1) ? g_xlo : g_xhi;                  \
        const __nv_bfloat16* Bp_ = (term_ == 2) ? g_Wtlo : g_Wthi;                \
        int ar_ = tid >> 2, aseg_ = tid & 3;                                      \
        cp16(smem_u32(&Asp[(bf_) * 2560 + ar_ * 40 + aseg_ * 8]),                 \
             Ap_ + (size_t)(m0 + ar_) * CDIM + kc_ * 32 + aseg_ * 8);             \
        for (int u_ = 0; u_ < 4; u_++) {                                          \
            int id_ = tid + u_ * 256;                                             \
            int br_ = id_ >> 5, bseg_ = id_ & 31;                                 \
            cp16(smem_u32(&Bsp[(bf_) * 8448 + br_ * 264 + bseg_ * 8]),            \
                 Bp_ + (size_t)(kc_ * 32 + br_) * CDIM + bseg_ * 8);              \
        }                                                                         \
        cp_commit();                                                              \
    }

    SC_ISSUE(0, 0);
    SC_ISSUE(1, 1);
    for (int s = 0; s < 24; s++) {
        if (s < 23) cp_wait1(); else cp_wait0();
        __syncthreads();
        int buf = s % 3;
#pragma unroll
        for (int kk = 0; kk < 2; kk++) {
            uint32_t af[4][4];
#pragma unroll
            for (int mt = 0; mt < 4; mt++)
                ldm_x4(af[mt], smem_u32(&Asp[buf * 2560 + (mt * 16 + lrow + q1 * 8) * 40 + kk * 16 + q2 * 8]));
            uint32_t bfr[2][4];
#pragma unroll
            for (int ng = 0; ng < 2; ng++)
                ldm_x4_t(bfr[ng], smem_u32(&Bsp[buf * 8448 + (kk * 16 + lrow + q1 * 8) * 264 + w * 32 + ng * 16 + q2 * 8]));
#pragma unroll
            for (int mt = 0; mt < 4; mt++)
#pragma unroll
                for (int nt = 0; nt < 4; nt++)
                    mma16816(acc[mt][nt], af[mt],
                             bfr[nt >> 1][(nt & 1) * 2], bfr[nt >> 1][(nt & 1) * 2 + 1]);
        }
        if (s + 2 < 24) SC_ISSUE(s + 2, (s + 2) % 3);
    }
#undef SC_ISSUE

    // epilogue: bias, bf16 hi/lo stores, T partials
    float pr0[4] = {}, pr1[4] = {};
#pragma unroll
    for (int nt = 0; nt < 4; nt++) {
        int c0 = w * 32 + nt * 8 + (lane & 3) * 2;
        float bb0 = attn_b[c0], bb1 = attn_b[c0 + 1];
        float tw0 = thr_W[c0], tw1 = thr_W[c0 + 1];
#pragma unroll
        for (int mt = 0; mt < 4; mt++) {
            int r0g = m0 + mt * 16 + (lane >> 2);
            float v00 = acc[mt][nt][0] + bb0, v01 = acc[mt][nt][1] + bb1;
            float v10 = acc[mt][nt][2] + bb0, v11 = acc[mt][nt][3] + bb1;
            BPack2 h, l;
            h.h[0] = __float2bfloat16(v00); h.h[1] = __float2bfloat16(v01);
            l.h[0] = __float2bfloat16(v00 - __bfloat162float(h.h[0]));
            l.h[1] = __float2bfloat16(v01 - __bfloat162float(h.h[1]));
            *(uint32_t*)&g_SChi[(size_t)r0g * CDIM + c0] = h.u;
            *(uint32_t*)&g_SClo[(size_t)r0g * CDIM + c0] = l.u;
            h.h[0] = __float2bfloat16(v10); h.h[1] = __float2bfloat16(v11);
            l.h[0] = __float2bfloat16(v10 - __bfloat162float(h.h[0]));
            l.h[1] = __float2bfloat16(v11 - __bfloat162float(h.h[1]));
            *(uint32_t*)&g_SChi[(size_t)(r0g + 8) * CDIM + c0] = h.u;
            *(uint32_t*)&g_SClo[(size_t)(r0g + 8) * CDIM + c0] = l.u;
            pr0[mt] += v00 * tw0 + v01 * tw1;
            pr1[mt] += v10 * tw0 + v11 * tw1;
        }
    }
#pragma unroll
    for (int mt = 0; mt < 4; mt++) {
        pr0[mt] += __shfl_xor_sync(0xffffffffu, pr0[mt], 1);
        pr0[mt] += __shfl_xor_sync(0xffffffffu, pr0[mt], 2);
        pr1[mt] += __shfl_xor_sync(0xffffffffu, pr1[mt], 1);
        pr1[mt] += __shfl_xor_sync(0xffffffffu, pr1[mt], 2);
        if ((lane & 3) == 0) {
            atomicAdd(&Tp[mt * 16 + (lane >> 2)], pr0[mt]);
            atomicAdd(&Tp[mt * 16 + (lane >> 2) + 8], pr1[mt]);
        }
    }
    __syncthreads();
    if (tid < 64) g_T[m0 + tid] = Tp[tid] + thr_b[0];
}

// ---------------- attention matrix kernel: 16-row tiles, 2 CTA/SM ----------------
#define S_PITCH 1032
#define OFF_BH  66048
#define OFF_BL  83456
#define OFF_TSH 100864
#define OFF_SQJ 104960
#define ATTN_SMEM 109056

__global__ __launch_bounds__(256) void attn_A_kernel() {
    extern __shared__ char smc[];
    float* S = (float*)smc;                                  // [16][1032] fp32
    __nv_bfloat16* Bh = (__nv_bfloat16*)(smc + OFF_BH);      // [2][32][136]
    __nv_bfloat16* Bl = (__nv_bfloat16*)(smc + OFF_BL);
    float* Tsh = (float*)(smc + OFF_TSH);
    float* Sqj = (float*)(smc + OFF_SQJ);
    __nv_bfloat16* Eistage = (__nv_bfloat16*)smc;            // [2][16][72] staged in S head

    int tid = threadIdx.x;
    int tile = blockIdx.x, b = blockIdx.y;
    int i0 = tile * 16;
    int base = b * HW;
    int w = tid >> 5, lane = tid & 31;
    int lrow = lane & 7, q1 = (lane >> 3) & 1, q2 = lane >> 4;

    for (int i = tid; i < 1024; i += 256) {
        Tsh[i] = g_T[base + i];
        Sqj[i] = g_sq[base + i];
    }

#define AT_ISSUE(s, bf_)                                                          \
    {                                                                             \
        int kh_ = (s) & 1, jc_ = (s) >> 1;                                        \
        for (int u_ = 0; u_ < 4; u_++) {                                          \
            int id_ = tid + u_ * 256;                                             \
            int arr_ = id_ >> 9, rem_ = id_ & 511;                                \
            int r_ = rem_ >> 4, seg_ = rem_ & 15;                                 \
            __nv_bfloat16* dst_ = (arr_ ? Bl : Bh) + (bf_) * 4352 + r_ * 136 + seg_ * 8; \
            const __nv_bfloat16* src_ = (arr_ ? g_EloT : g_EhiT) +                \
                (((size_t)b * 64 + kh_ * 32 + r_) << 10) + jc_ * 128 + seg_ * 8;  \
            cp16(smem_u32(dst_), src_);                                           \
        }                                                                         \
        cp_commit();                                                              \
    }

    // prologue: Ei (joins group 0) + stages 0,1
    {
        int arr = tid >> 7, rem = tid & 127;
        int r = rem >> 3, seg = rem & 7;
        __nv_bfloat16* dst = Eistage + arr * 1152 + r * 72 + seg * 8;
        const __nv_bfloat16* src = (arr ? g_Elo : g_Ehi) + (size_t)(base + i0 + r) * 64 + seg * 8;
        cp16(smem_u32(dst), src);
    }
    AT_ISSUE(0, 0);
    AT_ISSUE(1, 1);

    // per-lane row constants
    int r0 = lane >> 2;
    int ig0 = i0 + r0, ig1 = ig0 + 8;
    int yi0 = ig0 >> 5, xi0 = ig0 & 31;
    int yi1 = ig1 >> 5, xi1 = ig1 & 31;
    float sqi0 = g_sq[base + ig0];
    float sqi1 = g_sq[base + ig1];

    uint32_t Ah[4][4], Al[4][4];
    float acc[2][4];

    for (int s = 0; s < 16; s++) {
        if (s < 15) cp_wait1(); else cp_wait0();
        __syncthreads();
        if (s == 0) {
#pragma unroll
            for (int kc = 0; kc < 4; kc++) {
                ldm_x4(Ah[kc], smem_u32(&Eistage[(lrow + q1 * 8) * 72 + kc * 16 + q2 * 8]));
                ldm_x4(Al[kc], smem_u32(&Eistage[1152 + (lrow + q1 * 8) * 72 + kc * 16 + q2 * 8]));
            }
        }
        int kh = s & 1, jc = s >> 1, buf = s & 1;
        if (kh == 0) {
#pragma unroll
            for (int n = 0; n < 2; n++)
#pragma unroll
                for (int r = 0; r < 4; r++) acc[n][r] = 0.0f;
        }
#pragma unroll
        for (int kcl = 0; kcl < 2; kcl++) {
            int kc = kh * 2 + kcl;
            uint32_t bh[4];
            ldm_x4_t(bh, smem_u32(&Bh[buf * 4352 + (kcl * 16 + lrow + q1 * 8) * 136 + w * 16 + q2 * 8]));
            mma16816(acc[0], Ah[kc], bh[0], bh[1]);
            mma16816(acc[1], Ah[kc], bh[2], bh[3]);
            mma16816(acc[0], Al[kc], bh[0], bh[1]);
            mma16816(acc[1], Al[kc], bh[2], bh[3]);
            uint32_t bl[4];
            ldm_x4_t(bl, smem_u32(&Bl[buf * 4352 + (kcl * 16 + lrow + q1 * 8) * 136 + w * 16 + q2 * 8]));
            mma16816(acc[0], Ah[kc], bl[0], bl[1]);
            mma16816(acc[1], Ah[kc], bl[2], bl[3]);
        }
        if (kh == 1) {
            int jb = jc * 128;
#pragma unroll
            for (int nt = 0; nt < 2; nt++) {
                int j0 = jb + w * 16 + nt * 8 + (lane & 3) * 2;
                int yj0 = j0 >> 5, xj0 = j0 & 31;
                int yj1 = (j0 + 1) >> 5, xj1 = (j0 + 1) & 31;
                float sq0 = Sqj[j0], sq1 = Sqj[j0 + 1];
                {
                    float d2a = fmaxf(sqi0 + sq0 - 2.0f * acc[nt][0], 0.0f);
                    float d2b = fmaxf(sqi0 + sq1 - 2.0f * acc[nt][1], 0.0f);
                    int da = abs(yi0 - yj0) + abs(xi0 - xj0);
                    int db = abs(yi0 - yj1) + abs(xi0 - xj1);
                    float ma = (da <= 32) ? (float)da * (1.0f / 32.0f) : 0.0f;
                    float mb = (db <= 32) ? (float)db * (1.0f / 32.0f) : 0.0f;
                    *(float2*)&S[r0 * S_PITCH + j0] =
                        make_float2(__expf(-d2a) - 1.0f + ma, __expf(-d2b) - 1.0f + mb);
                }
                {
                    float d2a = fmaxf(sqi1 + sq0 - 2.0f * acc[nt][2], 0.0f);
                    float d2b = fmaxf(sqi1 + sq1 - 2.0f * acc[nt][3], 0.0f);
                    int da = abs(yi1 - yj0) + abs(xi1 - xj0);
                    int db = abs(yi1 - yj1) + abs(xi1 - xj1);
                    float ma = (da <= 32) ? (float)da * (1.0f / 32.0f) : 0.0f;
                    float mb = (db <= 32) ? (float)db * (1.0f / 32.0f) : 0.0f;
                    *(float2*)&S[(r0 + 8) * S_PITCH + j0] =
                        make_float2(__expf(-d2a) - 1.0f + ma, __expf(-d2b) - 1.0f + mb);
                }
            }
        }
        __syncthreads();
        if (s < 14) AT_ISSUE(s + 2, s & 1);
    }
#undef AT_ISSUE

    // ---- Phase B: register softmax, 2 rows per warp, packed coalesced A stores ----
#pragma unroll
    for (int q = 0; q < 2; q++) {
        int r = w * 2 + q;
        float* Sr = S + r * S_PITCH;
        float v[32];
#pragma unroll
        for (int t = 0; t < 32; t++) v[t] = Sr[lane + t * 32];
        float m = -1e30f;
#pragma unroll
        for (int t = 0; t < 32; t++) m = fmaxf(m, v[t]);
#pragma unroll
        for (int o = 16; o; o >>= 1) m = fmaxf(m, __shfl_xor_sync(0xffffffffu, m, o));
        float s1 = 0.0f;
#pragma unroll
        for (int t = 0; t < 32; t++) { v[t] = __expf(v[t] - m); s1 += v[t]; }
#pragma unroll
        for (int o = 16; o; o >>= 1) s1 += __shfl_xor_sync(0xffffffffu, s1, o);
        float inv1 = 1.0f / s1;
        float m2 = 0.0f;
#pragma unroll
        for (int t = 0; t < 32; t++) {
            v[t] = fmaxf(v[t] * inv1 - Tsh[lane + t * 32], 0.0f);
            m2 = fmaxf(m2, v[t]);
        }
#pragma unroll
        for (int o = 16; o; o >>= 1) m2 = fmaxf(m2, __shfl_xor_sync(0xffffffffu, m2, o));
        float s2 = 0.0f;
#pragma unroll
        for (int t = 0; t < 32; t++) { v[t] = __expf(v[t] - m2); s2 += v[t]; }
#pragma unroll
        for (int o = 16; o; o >>= 1) s2 += __shfl_xor_sync(0xffffffffu, s2, o);
        float inv2 = 1.0f / s2;

        // repack hi/lo bf16 into this (dead) S row, then coalesced copy out
        __nv_bfloat16* rowh = (__nv_bfloat16*)Sr;
        __nv_bfloat16* rowl = rowh + 1024;
#pragma unroll
        for (int t = 0; t < 32; t++) {
            float val = v[t] * inv2;
            __nv_bfloat16 h = __float2bfloat16(val);
            rowh[lane + t * 32] = h;
            rowl[lane + t * 32] = __float2bfloat16(val - __bfloat162float(h));
        }
        __syncwarp();
        size_t Ab = ((size_t)b << 20) + ((size_t)(i0 + r) << 10);
        uint4* gh = (uint4*)&g_Ahi[Ab];
        uint4* gl = (uint4*)&g_Alo[Ab];
        const uint4* sh = (const uint4*)rowh;
        const uint4* sl = (const uint4*)rowl;
#pragma unroll
        for (int it = 0; it < 4; it++) gh[lane + it * 32] = sh[lane + it * 32];
#pragma unroll
        for (int it = 0; it < 4; it++) gl[lane + it * 32] = sl[lane + it * 32];
    }
}

// ---------------- tensor-core bmm: out = x + A @ SC — 3-stage ring ----------------
#define BMM_OFF_A 0
#define BMM_OFF_S 30720
#define BMM_SMEM  56832
__global__ __launch_bounds__(256) void bmm_kernel(const float* __restrict__ x,
                                                  float* __restrict__ out) {
    extern __shared__ char smc[];
    __nv_bfloat16* Asp = (__nv_bfloat16*)(smc + BMM_OFF_A);  // [3][128][40]
    __nv_bfloat16* Ssp = (__nv_bfloat16*)(smc + BMM_OFF_S);  // [3][32][136]
    int tid = threadIdx.x, w = tid >> 5, lane = tid & 31;
    int ct = blockIdx.x, mtb = blockIdx.y, b = blockIdx.z;
    int i0 = mtb * 128, c0 = ct * 128;

    const __nv_bfloat16* Ahi = g_Ahi + ((size_t)b << 20) + (size_t)i0 * 1024;
    const __nv_bfloat16* Alo = g_Alo + ((size_t)b << 20) + (size_t)i0 * 1024;
    const __nv_bfloat16* Shi = g_SChi + ((size_t)b << 18) + c0;
    const __nv_bfloat16* Slo = g_SClo + ((size_t)b << 18) + c0;

    float acc[4][4][4];
#pragma unroll
    for (int a = 0; a < 4; a++)
#pragma unroll
        for (int n = 0; n < 4; n++)
#pragma unroll
            for (int r = 0; r < 4; r++) acc[a][n][r] = 0.0f;

    int wm = w >> 2, wn = w & 3;
    int lrow = lane & 7, q1 = (lane >> 3) & 1, q2 = lane >> 4;
    int ar0 = tid >> 2, aseg = tid & 3;
    int sr0 = tid >> 4, sseg = tid & 15;

#define ISSUE(cc, bf_)                                                            \
    {                                                                             \
        int term_ = (cc) >> 5, jc_ = (cc) & 31;                                   \
        const __nv_bfloat16* Ap_ = (term_ == 1) ? Alo : Ahi;                      \
        const __nv_bfloat16* Sp_ = (term_ == 2) ? Slo : Shi;                      \
        cp16(smem_u32(&Asp[(bf_) * 5120 + ar0 * 40 + aseg * 8]),                  \
             Ap_ + (size_t)ar0 * 1024 + jc_ * 32 + aseg * 8);                     \
        cp16(smem_u32(&Asp[(bf_) * 5120 + (ar0 + 64) * 40 + aseg * 8]),           \
             Ap_ + (size_t)(ar0 + 64) * 1024 + jc_ * 32 + aseg * 8);              \
        cp16(smem_u32(&Ssp[(bf_) * 4352 + sr0 * 136 + sseg * 8]),                 \
             Sp_ + (size_t)(jc_ * 32 + sr0) * 256 + sseg * 8);                    \
        cp16(smem_u32(&Ssp[(bf_) * 4352 + (sr0 + 16) * 136 + sseg * 8]),          \
             Sp_ + (size_t)(jc_ * 32 + sr0 + 16) * 256 + sseg * 8);               \
        cp_commit();                                                              \
    }

    ISSUE(0, 0);
    ISSUE(1, 1);
    for (int cc = 0; cc < 96; cc++) {
        if (cc < 95) cp_wait1(); else cp_wait0();
        __syncthreads();
        int buf = cc % 3;
#pragma unroll
        for (int kk = 0; kk < 2; kk++) {
            uint32_t af[4][4];
#pragma unroll
            for (int mtl = 0; mtl < 4; mtl++)
                ldm_x4(af[mtl], smem_u32(&Asp[buf * 5120 + (wm * 64 + mtl * 16 + lrow + q1 * 8) * 40 + kk * 16 + q2 * 8]));
            uint32_t bfr[2][4];
#pragma unroll
            for (int ng = 0; ng < 2; ng++)
                ldm_x4_t(bfr[ng], smem_u32(&Ssp[buf * 4352 + (kk * 16 + lrow + q1 * 8) * 136 + wn * 32 + ng * 16 + q2 * 8]));
#pragma unroll
            for (int mtl = 0; mtl < 4; mtl++)
#pragma unroll
                for (int nt = 0; nt < 4; nt++)
                    mma16816(acc[mtl][nt], af[mtl],
                             bfr[nt >> 1][(nt & 1) * 2], bfr[nt >> 1][(nt & 1) * 2 + 1]);
        }
        if (cc + 2 < 96) ISSUE(cc + 2, (cc + 2) % 3);
    }
#undef ISSUE

    int g = lane >> 2, t2 = lane & 3;
#pragma unroll
    for (int mtl = 0; mtl < 4; mtl++) {
#pragma unroll
        for (int nt = 0; nt < 4; nt++) {
            int row = i0 + wm * 64 + mtl * 16 + g;
            int col = c0 + wn * 32 + nt * 8 + 2 * t2;
            size_t o0 = ((size_t)b * 1024 + row) * 256 + col;
            size_t o1 = o0 + 8 * 256;
            float2 xv0 = *(const float2*)&x[o0];
            float2 xv1 = *(const float2*)&x[o1];
            *(float2*)&out[o0] = make_float2(xv0.x + acc[mtl][nt][0], xv0.y + acc[mtl][nt][1]);
            *(float2*)&out[o1] = make_float2(xv1.x + acc[mtl][nt][2], xv1.y + acc[mtl][nt][3]);
        }
    }
}

// ---------------- launch ----------------
extern "C" void kernel_launch(void* const* d_in, const int* in_sizes, int n_in,
                              void* d_out, int out_size) {
    const float* x      = (const float*)d_in[0];
    const float* emb_W  = (const float*)d_in[1];
    const float* emb_b  = (const float*)d_in[2];
    const float* attn_W = (const float*)d_in[3];
    const float* attn_b = (const float*)d_in[4];
    const float* thr_W  = (const float*)d_in[5];
    const float* thr_b  = (const float*)d_in[6];
    float* out = (float*)d_out;

    cudaFuncSetAttribute(emb_kernel, cudaFuncAttributeMaxDynamicSharedMemorySize, EMB_SMEM);
    cudaFuncSetAttribute(shortcut_kernel, cudaFuncAttributeMaxDynamicSharedMemorySize, SC_SMEM);
    cudaFuncSetAttribute(attn_A_kernel, cudaFuncAttributeMaxDynamicSharedMemorySize, ATTN_SMEM);
    cudaFuncSetAttribute(bmm_kernel, cudaFuncAttributeMaxDynamicSharedMemorySize, BMM_SMEM);

    prep_kernel<<<256, 256>>>(attn_W, emb_W);
    emb_kernel<<<BATCH * HW / 32, 256, EMB_SMEM>>>(x, emb_b);
    shortcut_kernel<<<BATCH * HW / 64, 256, SC_SMEM>>>(attn_b, thr_W, thr_b);
    attn_A_kernel<<<dim3(HW / 16, BATCH), 256, ATTN_SMEM>>>();
    bmm_kernel<<<dim3(CDIM / 128, HW / 128, BATCH), 256, BMM_SMEM>>>(x, out);
}

// round 6
// speedup vs baseline: 1.1423x; 1.1423x over previous
#include <cuda_runtime.h>
#include <cuda_bf16.h>
#include <math.h>
#include <stdint.h>

#define BATCH 32
#define HW    1024
#define CDIM  256
#define FDIM  64

// ---------------- scratch (device globals; no allocations) ----------------
__device__ float g_sq[BATCH * HW];
__device__ float g_T[BATCH * HW];
__device__ __nv_bfloat16 g_Ehi[BATCH * HW * FDIM];       // [n][k]
__device__ __nv_bfloat16 g_Elo[BATCH * HW * FDIM];
__device__ __nv_bfloat16 g_EhiT[BATCH * FDIM * HW];      // [b][k][n]
__device__ __nv_bfloat16 g_EloT[BATCH * FDIM * HW];
__device__ __nv_bfloat16 g_xhi[BATCH * HW * CDIM];
__device__ __nv_bfloat16 g_xlo[BATCH * HW * CDIM];
__device__ __nv_bfloat16 g_SChi[BATCH * HW * CDIM];
__device__ __nv_bfloat16 g_SClo[BATCH * HW * CDIM];
__device__ __nv_bfloat16 g_Ahi[(size_t)BATCH * HW * HW];
__device__ __nv_bfloat16 g_Alo[(size_t)BATCH * HW * HW];
__device__ __nv_bfloat16 g_Wthi[CDIM * CDIM];            // attn_W^T split [cin][cout]
__device__ __nv_bfloat16 g_Wtlo[CDIM * CDIM];
__device__ float g_emb_Wt[CDIM * FDIM];

// ---------------- small helpers ----------------
__device__ __forceinline__ uint32_t smem_u32(const void* p) {
    return (uint32_t)__cvta_generic_to_shared(p);
}
__device__ __forceinline__ void cp16(uint32_t dst, const void* src) {
    asm volatile("cp.async.cg.shared.global [%0], [%1], 16;\n" :: "r"(dst), "l"(src));
}
__device__ __forceinline__ void cp_commit() { asm volatile("cp.async.commit_group;\n"); }
__device__ __forceinline__ void cp_wait1() { asm volatile("cp.async.wait_group 1;\n"); }
__device__ __forceinline__ void cp_wait0() { asm volatile("cp.async.wait_group 0;\n"); }
__device__ __forceinline__ void ldm_x4(uint32_t (&r)[4], uint32_t addr) {
    asm volatile("ldmatrix.sync.aligned.m8n8.x4.shared.b16 {%0,%1,%2,%3}, [%4];"
                 : "=r"(r[0]), "=r"(r[1]), "=r"(r[2]), "=r"(r[3]) : "r"(addr));
}
__device__ __forceinline__ void ldm_x4_t(uint32_t (&r)[4], uint32_t addr) {
    asm volatile("ldmatrix.sync.aligned.m8n8.x4.trans.shared.b16 {%0,%1,%2,%3}, [%4];"
                 : "=r"(r[0]), "=r"(r[1]), "=r"(r[2]), "=r"(r[3]) : "r"(addr));
}
__device__ __forceinline__ void mma16816(float (&d)[4], const uint32_t (&a)[4],
                                         uint32_t b0, uint32_t b1) {
    asm volatile("mma.sync.aligned.m16n8k16.row.col.f32.bf16.bf16.f32 "
                 "{%0,%1,%2,%3}, {%4,%5,%6,%7}, {%8,%9}, {%0,%1,%2,%3};"
                 : "+f"(d[0]), "+f"(d[1]), "+f"(d[2]), "+f"(d[3])
                 : "r"(a[0]), "r"(a[1]), "r"(a[2]), "r"(a[3]), "r"(b0), "r"(b1));
}
union BPack2 { __nv_bfloat16 h[2]; uint32_t u; };
union BPack4 { __nv_bfloat16 h[4]; uint2 u; };

// ---------------- prep: weight transposes + bf16 splits ----------------
__global__ void prep_kernel(const float* __restrict__ attn_W,
                            const float* __restrict__ emb_W) {
    int t = blockIdx.x * 256 + threadIdx.x;
    if (t < CDIM * CDIM) {
        int ci = t >> 8, co = t & 255;
        float v = attn_W[co * CDIM + ci];
        __nv_bfloat16 h = __float2bfloat16(v);
        g_Wthi[ci * CDIM + co] = h;
        g_Wtlo[ci * CDIM + co] = __float2bfloat16(v - __bfloat162float(h));
    }
    if (t < FDIM * CDIM) {
        int f = t >> 8, ci = t & 255;
        g_emb_Wt[ci * FDIM + f] = emb_W[f * CDIM + ci];
    }
}

// ---------------- emb: x @ emb_W^T + b -> bf16 hi/lo (+transposed) + sq + x-split ----------------
#define EMB_SMEM ((32 * 256 + 256 * 64) * 4)
__global__ __launch_bounds__(256) void emb_kernel(const float* __restrict__ x,
                                                  const float* __restrict__ emb_b) {
    extern __shared__ float sm[];
    float* xs = sm;              // [32][256]
    float* we = sm + 32 * 256;   // [256][64]
    int tid = threadIdx.x;
    int row0 = blockIdx.x * 32;
    int bb = row0 >> 10, n0 = row0 & 1023;

    const float4* xg = (const float4*)(x + (size_t)row0 * CDIM);
    float4* xs4 = (float4*)xs;
    for (int i = tid; i < 32 * 64; i += 256) xs4[i] = xg[i];
    const float4* wg = (const float4*)g_emb_Wt;
    float4* we4 = (float4*)we;
    for (int i = tid; i < 256 * 16; i += 256) we4[i] = wg[i];
    __syncthreads();

    // fused x -> bf16 hi/lo split
    for (int i = tid; i < 2048; i += 256) {
        float4 v = xs4[i];
        float vv[4] = {v.x, v.y, v.z, v.w};
        BPack4 ph, pl;
#pragma unroll
        for (int q = 0; q < 4; q++) {
            __nv_bfloat16 h = __float2bfloat16(vv[q]);
            ph.h[q] = h;
            pl.h[q] = __float2bfloat16(vv[q] - __bfloat162float(h));
        }
        ((uint2*)g_xhi)[(size_t)row0 * 64 + i] = ph.u;
        ((uint2*)g_xlo)[(size_t)row0 * 64 + i] = pl.u;
    }

    int w = tid >> 5, lane = tid & 31;
    int ig = w * 4, fg = lane * 2;
    float acc[4][2] = {};
#pragma unroll 4
    for (int c = 0; c < 256; c++) {
        float2 wv = *(const float2*)&we[c * 64 + fg];
#pragma unroll
        for (int q = 0; q < 4; q++) {
            float a = xs[(ig + q) * 256 + c];
            acc[q][0] = fmaf(a, wv.x, acc[q][0]);
            acc[q][1] = fmaf(a, wv.y, acc[q][1]);
        }
    }
    float b0 = emb_b[fg], b1 = emb_b[fg + 1];
    float e0r[4], e1r[4];
#pragma unroll
    for (int q = 0; q < 4; q++) {
        float e0 = acc[q][0] + b0, e1 = acc[q][1] + b1;
        e0r[q] = e0; e1r[q] = e1;
        int n = row0 + ig + q;
        BPack2 ph, pl;
        ph.h[0] = __float2bfloat16(e0);
        ph.h[1] = __float2bfloat16(e1);
        pl.h[0] = __float2bfloat16(e0 - __bfloat162float(ph.h[0]));
        pl.h[1] = __float2bfloat16(e1 - __bfloat162float(ph.h[1]));
        *(uint32_t*)&g_Ehi[(size_t)n * FDIM + fg] = ph.u;
        *(uint32_t*)&g_Elo[(size_t)n * FDIM + fg] = pl.u;
        float p = e0 * e0 + e1 * e1;
#pragma unroll
        for (int o = 16; o; o >>= 1) p += __shfl_xor_sync(0xffffffffu, p, o);
        if (lane == 0) g_sq[n] = p;
    }

    // transposed bf16 copies via smem staging: [64][33]
    __nv_bfloat16* st = (__nv_bfloat16*)sm;
    __syncthreads();
#pragma unroll
    for (int q = 0; q < 4; q++) {
        st[fg * 33 + ig + q] = __float2bfloat16(e0r[q]);
        st[(fg + 1) * 33 + ig + q] = __float2bfloat16(e1r[q]);
    }
    __syncthreads();
    for (int idx = tid; idx < 2048; idx += 256) {
        int k = idx >> 5, i2 = idx & 31;
        g_EhiT[(((size_t)bb * 64 + k) << 10) + n0 + i2] = st[k * 33 + i2];
    }
    __syncthreads();
#pragma unroll
    for (int q = 0; q < 4; q++) {
        float h0 = __bfloat162float(__float2bfloat16(e0r[q]));
        float h1 = __bfloat162float(__float2bfloat16(e1r[q]));
        st[fg * 33 + ig + q] = __float2bfloat16(e0r[q] - h0);
        st[(fg + 1) * 33 + ig + q] = __float2bfloat16(e1r[q] - h1);
    }
    __syncthreads();
    for (int idx = tid; idx < 2048; idx += 256) {
        int k = idx >> 5, i2 = idx & 31;
        g_EloT[(((size_t)bb * 64 + k) << 10) + n0 + i2] = st[k * 33 + i2];
    }
}

// ---------------- shortcut: SC = x @ W^T + b (3-term), plus T — 3-stage ring ----------------
#define SC_OFF_A 0
#define SC_OFF_B 15360
#define SC_OFF_T 66048
#define SC_SMEM  66304
__global__ __launch_bounds__(256) void shortcut_kernel(const float* __restrict__ attn_b,
                                                       const float* __restrict__ thr_W,
                                                       const float* __restrict__ thr_b) {
    extern __shared__ char smc[];
    __nv_bfloat16* Asp = (__nv_bfloat16*)(smc + SC_OFF_A);   // [3][64][40]
    __nv_bfloat16* Bsp = (__nv_bfloat16*)(smc + SC_OFF_B);   // [3][32][264]
    float* Tp = (float*)(smc + SC_OFF_T);
    int tid = threadIdx.x, w = tid >> 5, lane = tid & 31;
    int m0 = blockIdx.x * 64;
    int lrow = lane & 7, q1 = (lane >> 3) & 1, q2 = lane >> 4;

    if (tid < 64) Tp[tid] = 0.0f;

    float acc[4][4][4];
#pragma unroll
    for (int a = 0; a < 4; a++)
#pragma unroll
        for (int n = 0; n < 4; n++)
#pragma unroll
            for (int r = 0; r < 4; r++) acc[a][n][r] = 0.0f;

#define SC_ISSUE(s, bf_)                                                          \
    {                                                                             \
        int term_ = (s) >> 3, kc_ = (s) & 7;                                      \
        const __nv_bfloat16* Ap_ = (term_ == 1) ? g_xlo : g_xhi;                  \
        const __nv_bfloat16* Bp_ = (term_ == 2) ? g_Wtlo : g_Wthi;                \
        int ar_ = tid >> 2, aseg_ = tid & 3;                                      \
        cp16(smem_u32(&Asp[(bf_) * 2560 + ar_ * 40 + aseg_ * 8]),                 \
             Ap_ + (size_t)(m0 + ar_) * CDIM + kc_ * 32 + aseg_ * 8);             \
        for (int u_ = 0; u_ < 4; u_++) {                                          \
            int id_ = tid + u_ * 256;                                             \
            int br_ = id_ >> 5, bseg_ = id_ & 31;                                 \
            cp16(smem_u32(&Bsp[(bf_) * 8448 + br_ * 264 + bseg_ * 8]),            \
                 Bp_ + (size_t)(kc_ * 32 + br_) * CDIM + bseg_ * 8);              \
        }                                                                         \
        cp_commit();                                                              \
    }

    SC_ISSUE(0, 0);
    SC_ISSUE(1, 1);
    for (int s = 0; s < 24; s++) {
        if (s < 23) cp_wait1(); else cp_wait0();
        __syncthreads();
        int buf = s % 3;
#pragma unroll
        for (int kk = 0; kk < 2; kk++) {
            uint32_t af[4][4];
#pragma unroll
            for (int mt = 0; mt < 4; mt++)
                ldm_x4(af[mt], smem_u32(&Asp[buf * 2560 + (mt * 16 + lrow + q1 * 8) * 40 + kk * 16 + q2 * 8]));
            uint32_t bfr[2][4];
#pragma unroll
            for (int ng = 0; ng < 2; ng++)
                ldm_x4_t(bfr[ng], smem_u32(&Bsp[buf * 8448 + (kk * 16 + lrow + q1 * 8) * 264 + w * 32 + ng * 16 + q2 * 8]));
#pragma unroll
            for (int mt = 0; mt < 4; mt++)
#pragma unroll
                for (int nt = 0; nt < 4; nt++)
                    mma16816(acc[mt][nt], af[mt],
                             bfr[nt >> 1][(nt & 1) * 2], bfr[nt >> 1][(nt & 1) * 2 + 1]);
        }
        if (s + 2 < 24) SC_ISSUE(s + 2, (s + 2) % 3);
    }
#undef SC_ISSUE

    // epilogue: bias, bf16 hi/lo stores, T partials
    float pr0[4] = {}, pr1[4] = {};
#pragma unroll
    for (int nt = 0; nt < 4; nt++) {
        int c0 = w * 32 + nt * 8 + (lane & 3) * 2;
        float bb0 = attn_b[c0], bb1 = attn_b[c0 + 1];
        float tw0 = thr_W[c0], tw1 = thr_W[c0 + 1];
#pragma unroll
        for (int mt = 0; mt < 4; mt++) {
            int r0g = m0 + mt * 16 + (lane >> 2);
            float v00 = acc[mt][nt][0] + bb0, v01 = acc[mt][nt][1] + bb1;
            float v10 = acc[mt][nt][2] + bb0, v11 = acc[mt][nt][3] + bb1;
            BPack2 h, l;
            h.h[0] = __float2bfloat16(v00); h.h[1] = __float2bfloat16(v01);
            l.h[0] = __float2bfloat16(v00 - __bfloat162float(h.h[0]));
            l.h[1] = __float2bfloat16(v01 - __bfloat162float(h.h[1]));
            *(uint32_t*)&g_SChi[(size_t)r0g * CDIM + c0] = h.u;
            *(uint32_t*)&g_SClo[(size_t)r0g * CDIM + c0] = l.u;
            h.h[0] = __float2bfloat16(v10); h.h[1] = __float2bfloat16(v11);
            l.h[0] = __float2bfloat16(v10 - __bfloat162float(h.h[0]));
            l.h[1] = __float2bfloat16(v11 - __bfloat162float(h.h[1]));
            *(uint32_t*)&g_SChi[(size_t)(r0g + 8) * CDIM + c0] = h.u;
            *(uint32_t*)&g_SClo[(size_t)(r0g + 8) * CDIM + c0] = l.u;
            pr0[mt] += v00 * tw0 + v01 * tw1;
            pr1[mt] += v10 * tw0 + v11 * tw1;
        }
    }
#pragma unroll
    for (int mt = 0; mt < 4; mt++) {
        pr0[mt] += __shfl_xor_sync(0xffffffffu, pr0[mt], 1);
        pr0[mt] += __shfl_xor_sync(0xffffffffu, pr0[mt], 2);
        pr1[mt] += __shfl_xor_sync(0xffffffffu, pr1[mt], 1);
        pr1[mt] += __shfl_xor_sync(0xffffffffu, pr1[mt], 2);
        if ((lane & 3) == 0) {
            atomicAdd(&Tp[mt * 16 + (lane >> 2)], pr0[mt]);
            atomicAdd(&Tp[mt * 16 + (lane >> 2) + 8], pr1[mt]);
        }
    }
    __syncthreads();
    if (tid < 64) g_T[m0 + tid] = Tp[tid] + thr_b[0];
}

// ---------------- attention matrix kernel (round-4 shape + packed A stores) ----------------
#define S_PITCH 1044
#define OFF_S    0
#define OFF_EIH  133632
#define OFF_EIL  138240
#define OFF_BH   142848
#define OFF_BL   177664
#define OFF_TSH  212480
#define OFF_SQJ  216576
#define ATTN_SMEM 220672

__global__ __launch_bounds__(512) void attn_A_kernel() {
    extern __shared__ char smc[];
    float* S = (float*)(smc + OFF_S);                         // [32][1044]
    __nv_bfloat16* Eih = (__nv_bfloat16*)(smc + OFF_EIH);     // [32][72]
    __nv_bfloat16* Eil = (__nv_bfloat16*)(smc + OFF_EIL);
    __nv_bfloat16* BhS = (__nv_bfloat16*)(smc + OFF_BH);      // [2][64][136]
    __nv_bfloat16* BlS = (__nv_bfloat16*)(smc + OFF_BL);
    float* Tsh = (float*)(smc + OFF_TSH);
    float* Sqj = (float*)(smc + OFF_SQJ);

    int tid = threadIdx.x;
    int tile = blockIdx.x, b = blockIdx.y;
    int i0 = tile * 32;
    int base = b * HW;
    int w = tid >> 5, lane = tid & 31;
    int lrow = lane & 7, q1 = (lane >> 3) & 1, q2 = lane >> 4;
    int mt = w & 1, npair = w >> 1;

    for (int i = tid; i < 1024; i += 512) {
        Tsh[i] = g_T[base + i];
        Sqj[i] = g_sq[base + i];
    }

#define AT_ISSUE(jc, buf)                                                         \
    {                                                                             \
        for (int u_ = 0; u_ < 4; u_++) {                                          \
            int id_ = tid + u_ * 512;                                             \
            int arr_ = id_ >> 10, rem_ = id_ & 1023;                              \
            int r_ = rem_ >> 4, seg_ = rem_ & 15;                                 \
            __nv_bfloat16* dst_ = (arr_ ? BlS : BhS) + (buf) * 8704 + r_ * 136 + seg_ * 8; \
            const __nv_bfloat16* src_ = (arr_ ? g_EloT : g_EhiT) +                \
                (((size_t)b * 64 + r_) << 10) + (jc) * 128 + seg_ * 8;            \
            cp16(smem_u32(dst_), src_);                                           \
        }                                                                         \
        cp_commit();                                                              \
    }

    // prologue: Ei hi/lo joins group 0
    {
        int arr = tid >> 8, rem = tid & 255;
        int r = rem >> 3, seg = rem & 7;
        __nv_bfloat16* dst = (arr ? Eil : Eih) + r * 72 + seg * 8;
        const __nv_bfloat16* src = (arr ? g_Elo : g_Ehi) + (size_t)(base + i0 + r) * 64 + seg * 8;
        cp16(smem_u32(dst), src);
    }
    AT_ISSUE(0, 0);
    AT_ISSUE(1, 1);
    cp_wait1();
    __syncthreads();

    // hoisted A fragments
    uint32_t Ah[4][4], Al[4][4];
#pragma unroll
    for (int kc = 0; kc < 4; kc++) {
        ldm_x4(Ah[kc], smem_u32(&Eih[(mt * 16 + lrow + q1 * 8) * 72 + kc * 16 + q2 * 8]));
        ldm_x4(Al[kc], smem_u32(&Eil[(mt * 16 + lrow + q1 * 8) * 72 + kc * 16 + q2 * 8]));
    }

    // per-lane row constants
    int r0 = mt * 16 + (lane >> 2);
    int ig0 = i0 + r0, ig1 = ig0 + 8;
    int yi0 = ig0 >> 5, xi0 = ig0 & 31;
    int yi1 = ig1 >> 5, xi1 = ig1 & 31;
    float sqi0 = g_sq[base + ig0];
    float sqi1 = g_sq[base + ig1];

    // ---- Phase A ----
    for (int jc = 0; jc < 8; jc++) {
        if (jc >= 1) {
            if (jc < 7) cp_wait1(); else cp_wait0();
            __syncthreads();
        }
        int buf = jc & 1;
        float acc[2][4] = {};
#pragma unroll
        for (int kc = 0; kc < 4; kc++) {
            uint32_t bh[4];
            ldm_x4_t(bh, smem_u32(&BhS[buf * 8704 + (kc * 16 + lrow + q1 * 8) * 136 + npair * 16 + q2 * 8]));
            mma16816(acc[0], Ah[kc], bh[0], bh[1]);
            mma16816(acc[1], Ah[kc], bh[2], bh[3]);
            mma16816(acc[0], Al[kc], bh[0], bh[1]);
            mma16816(acc[1], Al[kc], bh[2], bh[3]);
            uint32_t bl[4];
            ldm_x4_t(bl, smem_u32(&BlS[buf * 8704 + (kc * 16 + lrow + q1 * 8) * 136 + npair * 16 + q2 * 8]));
            mma16816(acc[0], Ah[kc], bl[0], bl[1]);
            mma16816(acc[1], Ah[kc], bl[2], bl[3]);
        }
        int jb = jc * 128;
#pragma unroll
        for (int nt = 0; nt < 2; nt++) {
            int cA = npair * 16 + nt * 8 + (lane & 3) * 2;
            int j0 = jb + cA;
            int yj0 = j0 >> 5, xj0 = j0 & 31;
            int yj1 = (j0 + 1) >> 5, xj1 = (j0 + 1) & 31;
            float sq0 = Sqj[j0], sq1 = Sqj[j0 + 1];
            {
                float d2a = fmaxf(sqi0 + sq0 - 2.0f * acc[nt][0], 0.0f);
                float d2b = fmaxf(sqi0 + sq1 - 2.0f * acc[nt][1], 0.0f);
                int da = abs(yi0 - yj0) + abs(xi0 - xj0);
                int db = abs(yi0 - yj1) + abs(xi0 - xj1);
                float ma = (da <= 32) ? (float)da * (1.0f / 32.0f) : 0.0f;
                float mb = (db <= 32) ? (float)db * (1.0f / 32.0f) : 0.0f;
                *(float2*)&S[r0 * S_PITCH + j0] =
                    make_float2(__expf(-d2a) - 1.0f + ma, __expf(-d2b) - 1.0f + mb);
            }
            {
                float d2a = fmaxf(sqi1 + sq0 - 2.0f * acc[nt][2], 0.0f);
                float d2b = fmaxf(sqi1 + sq1 - 2.0f * acc[nt][3], 0.0f);
                int da = abs(yi1 - yj0) + abs(xi1 - xj0);
                int db = abs(yi1 - yj1) + abs(xi1 - xj1);
                float ma = (da <= 32) ? (float)da * (1.0f / 32.0f) : 0.0f;
                float mb = (db <= 32) ? (float)db * (1.0f / 32.0f) : 0.0f;
                *(float2*)&S[(r0 + 8) * S_PITCH + j0] =
                    make_float2(__expf(-d2a) - 1.0f + ma, __expf(-d2b) - 1.0f + mb);
            }
        }
        __syncthreads();
        if (jc < 6) AT_ISSUE(jc + 2, jc & 1);
    }
#undef AT_ISSUE

    // ---- Phase B: register softmax, 2 rows per warp, packed coalesced A stores ----
#pragma unroll
    for (int q = 0; q < 2; q++) {
        int r = w * 2 + q;
        float* Sr = S + r * S_PITCH;
        float v[32];
#pragma unroll
        for (int t = 0; t < 32; t++) v[t] = Sr[lane + t * 32];
        float m = -1e30f;
#pragma unroll
        for (int t = 0; t < 32; t++) m = fmaxf(m, v[t]);
#pragma unroll
        for (int o = 16; o; o >>= 1) m = fmaxf(m, __shfl_xor_sync(0xffffffffu, m, o));
        float s1 = 0.0f;
#pragma unroll
        for (int t = 0; t < 32; t++) { v[t] = __expf(v[t] - m); s1 += v[t]; }
#pragma unroll
        for (int o = 16; o; o >>= 1) s1 += __shfl_xor_sync(0xffffffffu, s1, o);
        float inv1 = 1.0f / s1;
        float m2 = 0.0f;
#pragma unroll
        for (int t = 0; t < 32; t++) {
            v[t] = fmaxf(v[t] * inv1 - Tsh[lane + t * 32], 0.0f);
            m2 = fmaxf(m2, v[t]);
        }
#pragma unroll
        for (int o = 16; o; o >>= 1) m2 = fmaxf(m2, __shfl_xor_sync(0xffffffffu, m2, o));
        float s2 = 0.0f;
#pragma unroll
        for (int t = 0; t < 32; t++) { v[t] = __expf(v[t] - m2); s2 += v[t]; }
#pragma unroll
        for (int o = 16; o; o >>= 1) s2 += __shfl_xor_sync(0xffffffffu, s2, o);
        float inv2 = 1.0f / s2;

        // repack hi/lo bf16 into this (now-dead) S row, then coalesced copy out
        __nv_bfloat16* rowh = (__nv_bfloat16*)Sr;
        __nv_bfloat16* rowl = rowh + 1024;
#pragma unroll
        for (int t = 0; t < 32; t++) {
            float val = v[t] * inv2;
            __nv_bfloat16 h = __float2bfloat16(val);
            rowh[lane + t * 32] = h;
            rowl[lane + t * 32] = __float2bfloat16(val - __bfloat162float(h));
        }
        __syncwarp();
        size_t Ab = ((size_t)b << 20) + ((size_t)(i0 + r) << 10);
        uint4* gh = (uint4*)&g_Ahi[Ab];
        uint4* gl = (uint4*)&g_Alo[Ab];
        const uint4* sh = (const uint4*)rowh;
        const uint4* sl = (const uint4*)rowl;
#pragma unroll
        for (int it = 0; it < 4; it++) gh[lane + it * 32] = sh[lane + it * 32];
#pragma unroll
        for (int it = 0; it < 4; it++) gl[lane + it * 32] = sl[lane + it * 32];
    }
}

// ---------------- tensor-core bmm: out = x + A @ SC — 3-stage ring ----------------
#define BMM_OFF_A 0
#define BMM_OFF_S 30720
#define BMM_SMEM  56832
__global__ __launch_bounds__(256) void bmm_kernel(const float* __restrict__ x,
                                                  float* __restrict__ out) {
    extern __shared__ char smc[];
    __nv_bfloat16* Asp = (__nv_bfloat16*)(smc + BMM_OFF_A);  // [3][128][40]
    __nv_bfloat16* Ssp = (__nv_bfloat16*)(smc + BMM_OFF_S);  // [3][32][136]
    int tid = threadIdx.x, w = tid >> 5, lane = tid & 31;
    int ct = blockIdx.x, mtb = blockIdx.y, b = blockIdx.z;
    int i0 = mtb * 128, c0 = ct * 128;

    const __nv_bfloat16* Ahi = g_Ahi + ((size_t)b << 20) + (size_t)i0 * 1024;
    const __nv_bfloat16* Alo = g_Alo + ((size_t)b << 20) + (size_t)i0 * 1024;
    const __nv_bfloat16* Shi = g_SChi + ((size_t)b << 18) + c0;
    const __nv_bfloat16* Slo = g_SClo + ((size_t)b << 18) + c0;

    float acc[4][4][4];
#pragma unroll
    for (int a = 0; a < 4; a++)
#pragma unroll
        for (int n = 0; n < 4; n++)
#pragma unroll
            for (int r = 0; r < 4; r++) acc[a][n][r] = 0.0f;

    int wm = w >> 2, wn = w & 3;
    int lrow = lane & 7, q1 = (lane >> 3) & 1, q2 = lane >> 4;
    int ar0 = tid >> 2, aseg = tid & 3;
    int sr0 = tid >> 4, sseg = tid & 15;

#define ISSUE(cc, bf_)                                                            \
    {                                                                             \
        int term_ = (cc) >> 5, jc_ = (cc) & 31;                                   \
        const __nv_bfloat16* Ap_ = (term_ == 1) ? Alo : Ahi;                      \
        const __nv_bfloat16* Sp_ = (term_ == 2) ? Slo : Shi;                      \
        cp16(smem_u32(&Asp[(bf_) * 5120 + ar0 * 40 + aseg * 8]),                  \
             Ap_ + (size_t)ar0 * 1024 + jc_ * 32 + aseg * 8);                     \
        cp16(smem_u32(&Asp[(bf_) * 5120 + (ar0 + 64) * 40 + aseg * 8]),           \
             Ap_ + (size_t)(ar0 + 64) * 1024 + jc_ * 32 + aseg * 8);              \
        cp16(smem_u32(&Ssp[(bf_) * 4352 + sr0 * 136 + sseg * 8]),                 \
             Sp_ + (size_t)(jc_ * 32 + sr0) * 256 + sseg * 8);                    \
        cp16(smem_u32(&Ssp[(bf_) * 4352 + (sr0 + 16) * 136 + sseg * 8]),          \
             Sp_ + (size_t)(jc_ * 32 + sr0 + 16) * 256 + sseg * 8);               \
        cp_commit();                                                              \
    }

    ISSUE(0, 0);
    ISSUE(1, 1);
    for (int cc = 0; cc < 96; cc++) {
        if (cc < 95) cp_wait1(); else cp_wait0();
        __syncthreads();
        int buf = cc % 3;
#pragma unroll
        for (int kk = 0; kk < 2; kk++) {
            uint32_t af[4][4];
#pragma unroll
            for (int mtl = 0; mtl < 4; mtl++)
                ldm_x4(af[mtl], smem_u32(&Asp[buf * 5120 + (wm * 64 + mtl * 16 + lrow + q1 * 8) * 40 + kk * 16 + q2 * 8]));
            uint32_t bfr[2][4];
#pragma unroll
            for (int ng = 0; ng < 2; ng++)
                ldm_x4_t(bfr[ng], smem_u32(&Ssp[buf * 4352 + (kk * 16 + lrow + q1 * 8) * 136 + wn * 32 + ng * 16 + q2 * 8]));
#pragma unroll
            for (int mtl = 0; mtl < 4; mtl++)
#pragma unroll
                for (int nt = 0; nt < 4; nt++)
                    mma16816(acc[mtl][nt], af[mtl],
                             bfr[nt >> 1][(nt & 1) * 2], bfr[nt >> 1][(nt & 1) * 2 + 1]);
        }
        if (cc + 2 < 96) ISSUE(cc + 2, (cc + 2) % 3);
    }
#undef ISSUE

    int g = lane >> 2, t2 = lane & 3;
#pragma unroll
    for (int mtl = 0; mtl < 4; mtl++) {
#pragma unroll
        for (int nt = 0; nt < 4; nt++) {
            int row = i0 + wm * 64 + mtl * 16 + g;
            int col = c0 + wn * 32 + nt * 8 + 2 * t2;
            size_t o0 = ((size_t)b * 1024 + row) * 256 + col;
            size_t o1 = o0 + 8 * 256;
            float2 xv0 = *(const float2*)&x[o0];
            float2 xv1 = *(const float2*)&x[o1];
            *(float2*)&out[o0] = make_float2(xv0.x + acc[mtl][nt][0], xv0.y + acc[mtl][nt][1]);
            *(float2*)&out[o1] = make_float2(xv1.x + acc[mtl][nt][2], xv1.y + acc[mtl][nt][3]);
        }
    }
}

// ---------------- launch ----------------
extern "C" void kernel_launch(void* const* d_in, const int* in_sizes, int n_in,
                              void* d_out, int out_size) {
    const float* x      = (const float*)d_in[0];
    const float* emb_W  = (const float*)d_in[1];
    const float* emb_b  = (const float*)d_in[2];
    const float* attn_W = (const float*)d_in[3];
    const float* attn_b = (const float*)d_in[4];
    const float* thr_W  = (const float*)d_in[5];
    const float* thr_b  = (const float*)d_in[6];
    float* out = (float*)d_out;

    cudaFuncSetAttribute(emb_kernel, cudaFuncAttributeMaxDynamicSharedMemorySize, EMB_SMEM);
    cudaFuncSetAttribute(shortcut_kernel, cudaFuncAttributeMaxDynamicSharedMemorySize, SC_SMEM);
    cudaFuncSetAttribute(attn_A_kernel, cudaFuncAttributeMaxDynamicSharedMemorySize, ATTN_SMEM);
    cudaFuncSetAttribute(bmm_kernel, cudaFuncAttributeMaxDynamicSharedMemorySize, BMM_SMEM);

    prep_kernel<<<256, 256>>>(attn_W, emb_W);
    emb_kernel<<<BATCH * HW / 32, 256, EMB_SMEM>>>(x, emb_b);
    shortcut_kernel<<<BATCH * HW / 64, 256, SC_SMEM>>>(attn_b, thr_W, thr_b);
    attn_A_kernel<<<dim3(HW / 32, BATCH), 512, ATTN_SMEM>>>();
    bmm_kernel<<<dim3(CDIM / 128, HW / 128, BATCH), 256, BMM_SMEM>>>(x, out);
}

// round 7
// speedup vs baseline: 1.1754x; 1.0289x over previous
#include <cuda_runtime.h>
#include <cuda_bf16.h>
#include <math.h>
#include <stdint.h>

#define BATCH 32
#define HW    1024
#define CDIM  256
#define FDIM  64

// ---------------- scratch (device globals; no allocations) ----------------
__device__ float g_sq[BATCH * HW];
__device__ float g_T[BATCH * HW];
__device__ __nv_bfloat16 g_Ehi[BATCH * HW * FDIM];       // [n][k]
__device__ __nv_bfloat16 g_Elo[BATCH * HW * FDIM];
__device__ __nv_bfloat16 g_EhiT[BATCH * FDIM * HW];      // [b][k][n]
__device__ __nv_bfloat16 g_EloT[BATCH * FDIM * HW];
__device__ __nv_bfloat16 g_xhi[BATCH * HW * CDIM];
__device__ __nv_bfloat16 g_xlo[BATCH * HW * CDIM];
__device__ __nv_bfloat16 g_SChi[BATCH * HW * CDIM];
__device__ __nv_bfloat16 g_SClo[BATCH * HW * CDIM];
__device__ __nv_bfloat16 g_Ahi[(size_t)BATCH * HW * HW];
__device__ __nv_bfloat16 g_Alo[(size_t)BATCH * HW * HW];
__device__ __nv_bfloat16 g_Wthi[CDIM * CDIM];            // attn_W^T split [cin][cout]
__device__ __nv_bfloat16 g_Wtlo[CDIM * CDIM];
__device__ float g_emb_Wt[CDIM * FDIM];

// ---------------- small helpers ----------------
__device__ __forceinline__ uint32_t smem_u32(const void* p) {
    return (uint32_t)__cvta_generic_to_shared(p);
}
__device__ __forceinline__ void cp16(uint32_t dst, const void* src) {
    asm volatile("cp.async.cg.shared.global [%0], [%1], 16;\n" :: "r"(dst), "l"(src));
}
__device__ __forceinline__ void cp_commit() { asm volatile("cp.async.commit_group;\n"); }
__device__ __forceinline__ void cp_wait1() { asm volatile("cp.async.wait_group 1;\n"); }
__device__ __forceinline__ void cp_wait0() { asm volatile("cp.async.wait_group 0;\n"); }
__device__ __forceinline__ void ldm_x4(uint32_t (&r)[4], uint32_t addr) {
    asm volatile("ldmatrix.sync.aligned.m8n8.x4.shared.b16 {%0,%1,%2,%3}, [%4];"
                 : "=r"(r[0]), "=r"(r[1]), "=r"(r[2]), "=r"(r[3]) : "r"(addr));
}
__device__ __forceinline__ void ldm_x4_t(uint32_t (&r)[4], uint32_t addr) {
    asm volatile("ldmatrix.sync.aligned.m8n8.x4.trans.shared.b16 {%0,%1,%2,%3}, [%4];"
                 : "=r"(r[0]), "=r"(r[1]), "=r"(r[2]), "=r"(r[3]) : "r"(addr));
}
__device__ __forceinline__ void mma16816(float (&d)[4], const uint32_t (&a)[4],
                                         uint32_t b0, uint32_t b1) {
    asm volatile("mma.sync.aligned.m16n8k16.row.col.f32.bf16.bf16.f32 "
                 "{%0,%1,%2,%3}, {%4,%5,%6,%7}, {%8,%9}, {%0,%1,%2,%3};"
                 : "+f"(d[0]), "+f"(d[1]), "+f"(d[2]), "+f"(d[3])
                 : "r"(a[0]), "r"(a[1]), "r"(a[2]), "r"(a[3]), "r"(b0), "r"(b1));
}
union BPack2 { __nv_bfloat16 h[2]; uint32_t u; };
union BPack4 { __nv_bfloat16 h[4]; uint2 u; };

// ---------------- prep: weight transposes + bf16 splits ----------------
__global__ void prep_kernel(const float* __restrict__ attn_W,
                            const float* __restrict__ emb_W) {
    int t = blockIdx.x * 256 + threadIdx.x;
    if (t < CDIM * CDIM) {
        int ci = t >> 8, co = t & 255;
        float v = attn_W[co * CDIM + ci];
        __nv_bfloat16 h = __float2bfloat16(v);
        g_Wthi[ci * CDIM + co] = h;
        g_Wtlo[ci * CDIM + co] = __float2bfloat16(v - __bfloat162float(h));
    }
    if (t < FDIM * CDIM) {
        int f = t >> 8, ci = t & 255;
        g_emb_Wt[ci * FDIM + f] = emb_W[f * CDIM + ci];
    }
}

// ---------------- emb: x @ emb_W^T + b -> bf16 hi/lo (+transposed) + sq + x-split ----------------
#define EMB_SMEM ((32 * 256 + 256 * 64) * 4)
__global__ __launch_bounds__(256) void emb_kernel(const float* __restrict__ x,
                                                  const float* __restrict__ emb_b) {
    extern __shared__ float sm[];
    float* xs = sm;              // [32][256]
    float* we = sm + 32 * 256;   // [256][64]
    int tid = threadIdx.x;
    int row0 = blockIdx.x * 32;
    int bb = row0 >> 10, n0 = row0 & 1023;

    const float4* xg = (const float4*)(x + (size_t)row0 * CDIM);
    float4* xs4 = (float4*)xs;
    for (int i = tid; i < 32 * 64; i += 256) xs4[i] = xg[i];
    const float4* wg = (const float4*)g_emb_Wt;
    float4* we4 = (float4*)we;
    for (int i = tid; i < 256 * 16; i += 256) we4[i] = wg[i];
    __syncthreads();

    // fused x -> bf16 hi/lo split
    for (int i = tid; i < 2048; i += 256) {
        float4 v = xs4[i];
        float vv[4] = {v.x, v.y, v.z, v.w};
        BPack4 ph, pl;
#pragma unroll
        for (int q = 0; q < 4; q++) {
            __nv_bfloat16 h = __float2bfloat16(vv[q]);
            ph.h[q] = h;
            pl.h[q] = __float2bfloat16(vv[q] - __bfloat162float(h));
        }
        ((uint2*)g_xhi)[(size_t)row0 * 64 + i] = ph.u;
        ((uint2*)g_xlo)[(size_t)row0 * 64 + i] = pl.u;
    }

    int w = tid >> 5, lane = tid & 31;
    int ig = w * 4, fg = lane * 2;
    float acc[4][2] = {};
#pragma unroll 4
    for (int c = 0; c < 256; c++) {
        float2 wv = *(const float2*)&we[c * 64 + fg];
#pragma unroll
        for (int q = 0; q < 4; q++) {
            float a = xs[(ig + q) * 256 + c];
            acc[q][0] = fmaf(a, wv.x, acc[q][0]);
            acc[q][1] = fmaf(a, wv.y, acc[q][1]);
        }
    }
    float b0 = emb_b[fg], b1 = emb_b[fg + 1];
    float e0r[4], e1r[4];
#pragma unroll
    for (int q = 0; q < 4; q++) {
        float e0 = acc[q][0] + b0, e1 = acc[q][1] + b1;
        e0r[q] = e0; e1r[q] = e1;
        int n = row0 + ig + q;
        BPack2 ph, pl;
        ph.h[0] = __float2bfloat16(e0);
        ph.h[1] = __float2bfloat16(e1);
        pl.h[0] = __float2bfloat16(e0 - __bfloat162float(ph.h[0]));
        pl.h[1] = __float2bfloat16(e1 - __bfloat162float(ph.h[1]));
        *(uint32_t*)&g_Ehi[(size_t)n * FDIM + fg] = ph.u;
        *(uint32_t*)&g_Elo[(size_t)n * FDIM + fg] = pl.u;
        float p = e0 * e0 + e1 * e1;
#pragma unroll
        for (int o = 16; o; o >>= 1) p += __shfl_xor_sync(0xffffffffu, p, o);
        if (lane == 0) g_sq[n] = p;
    }

    // transposed bf16 copies via smem staging: [64][33]
    __nv_bfloat16* st = (__nv_bfloat16*)sm;
    __syncthreads();
#pragma unroll
    for (int q = 0; q < 4; q++) {
        st[fg * 33 + ig + q] = __float2bfloat16(e0r[q]);
        st[(fg + 1) * 33 + ig + q] = __float2bfloat16(e1r[q]);
    }
    __syncthreads();
    for (int idx = tid; idx < 2048; idx += 256) {
        int k = idx >> 5, i2 = idx & 31;
        g_EhiT[(((size_t)bb * 64 + k) << 10) + n0 + i2] = st[k * 33 + i2];
    }
    __syncthreads();
#pragma unroll
    for (int q = 0; q < 4; q++) {
        float h0 = __bfloat162float(__float2bfloat16(e0r[q]));
        float h1 = __bfloat162float(__float2bfloat16(e1r[q]));
        st[fg * 33 + ig + q] = __float2bfloat16(e0r[q] - h0);
        st[(fg + 1) * 33 + ig + q] = __float2bfloat16(e1r[q] - h1);
    }
    __syncthreads();
    for (int idx = tid; idx < 2048; idx += 256) {
        int k = idx >> 5, i2 = idx & 31;
        g_EloT[(((size_t)bb * 64 + k) << 10) + n0 + i2] = st[k * 33 + i2];
    }
}

// ---------------- shortcut: SC = x @ W^T + b (3-term), plus T — 3-stage ring ----------------
#define SC_OFF_A 0
#define SC_OFF_B 15360
#define SC_OFF_T 66048
#define SC_SMEM  66304
__global__ __launch_bounds__(256) void shortcut_kernel(const float* __restrict__ attn_b,
                                                       const float* __restrict__ thr_W,
                                                       const float* __restrict__ thr_b) {
    extern __shared__ char smc[];
    __nv_bfloat16* Asp = (__nv_bfloat16*)(smc + SC_OFF_A);   // [3][64][40]
    __nv_bfloat16* Bsp = (__nv_bfloat16*)(smc + SC_OFF_B);   // [3][32][264]
    float* Tp = (float*)(smc + SC_OFF_T);
    int tid = threadIdx.x, w = tid >> 5, lane = tid & 31;
    int m0 = blockIdx.x * 64;
    int lrow = lane & 7, q1 = (lane >> 3) & 1, q2 = lane >> 4;

    if (tid < 64) Tp[tid] = 0.0f;

    float acc[4][4][4];
#pragma unroll
    for (int a = 0; a < 4; a++)
#pragma unroll
        for (int n = 0; n < 4; n++)
#pragma unroll
            for (int r = 0; r < 4; r++) acc[a][n][r] = 0.0f;

#define SC_ISSUE(s, bf_)                                                          \
    {                                                                             \
        int term_ = (s) >> 3, kc_ = (s) & 7;                                      \
        const __nv_bfloat16* Ap_ = (term_ == 1) ? g_xlo : g_xhi;                  \
        const __nv_bfloat16* Bp_ = (term_ == 2) ? g_Wtlo : g_Wthi;                \
        int ar_ = tid >> 2, aseg_ = tid & 3;                                      \
        cp16(smem_u32(&Asp[(bf_) * 2560 + ar_ * 40 + aseg_ * 8]),                 \
             Ap_ + (size_t)(m0 + ar_) * CDIM + kc_ * 32 + aseg_ * 8);             \
        for (int u_ = 0; u_ < 4; u_++) {                                          \
            int id_ = tid + u_ * 256;                                             \
            int br_ = id_ >> 5, bseg_ = id_ & 31;                                 \
            cp16(smem_u32(&Bsp[(bf_) * 8448 + br_ * 264 + bseg_ * 8]),            \
                 Bp_ + (size_t)(kc_ * 32 + br_) * CDIM + bseg_ * 8);              \
        }                                                                         \
        cp_commit();                                                              \
    }

    SC_ISSUE(0, 0);
    SC_ISSUE(1, 1);
    for (int s = 0; s < 24; s++) {
        if (s < 23) cp_wait1(); else cp_wait0();
        __syncthreads();
        int buf = s % 3;
#pragma unroll
        for (int kk = 0; kk < 2; kk++) {
            uint32_t af[4][4];
#pragma unroll
            for (int mt = 0; mt < 4; mt++)
                ldm_x4(af[mt], smem_u32(&Asp[buf * 2560 + (mt * 16 + lrow + q1 * 8) * 40 + kk * 16 + q2 * 8]));
            uint32_t bfr[2][4];
#pragma unroll
            for (int ng = 0; ng < 2; ng++)
                ldm_x4_t(bfr[ng], smem_u32(&Bsp[buf * 8448 + (kk * 16 + lrow + q1 * 8) * 264 + w * 32 + ng * 16 + q2 * 8]));
#pragma unroll
            for (int mt = 0; mt < 4; mt++)
#pragma unroll
                for (int nt = 0; nt < 4; nt++)
                    mma16816(acc[mt][nt], af[mt],
                             bfr[nt >> 1][(nt & 1) * 2], bfr[nt >> 1][(nt & 1) * 2 + 1]);
        }
        if (s + 2 < 24) SC_ISSUE(s + 2, (s + 2) % 3);
    }
#undef SC_ISSUE

    // epilogue: bias, bf16 hi/lo stores, T partials
    float pr0[4] = {}, pr1[4] = {};
#pragma unroll
    for (int nt = 0; nt < 4; nt++) {
        int c0 = w * 32 + nt * 8 + (lane & 3) * 2;
        float bb0 = attn_b[c0], bb1 = attn_b[c0 + 1];
        float tw0 = thr_W[c0], tw1 = thr_W[c0 + 1];
#pragma unroll
        for (int mt = 0; mt < 4; mt++) {
            int r0g = m0 + mt * 16 + (lane >> 2);
            float v00 = acc[mt][nt][0] + bb0, v01 = acc[mt][nt][1] + bb1;
            float v10 = acc[mt][nt][2] + bb0, v11 = acc[mt][nt][3] + bb1;
            BPack2 h, l;
            h.h[0] = __float2bfloat16(v00); h.h[1] = __float2bfloat16(v01);
            l.h[0] = __float2bfloat16(v00 - __bfloat162float(h.h[0]));
            l.h[1] = __float2bfloat16(v01 - __bfloat162float(h.h[1]));
            *(uint32_t*)&g_SChi[(size_t)r0g * CDIM + c0] = h.u;
            *(uint32_t*)&g_SClo[(size_t)r0g * CDIM + c0] = l.u;
            h.h[0] = __float2bfloat16(v10); h.h[1] = __float2bfloat16(v11);
            l.h[0] = __float2bfloat16(v10 - __bfloat162float(h.h[0]));
            l.h[1] = __float2bfloat16(v11 - __bfloat162float(h.h[1]));
            *(uint32_t*)&g_SChi[(size_t)(r0g + 8) * CDIM + c0] = h.u;
            *(uint32_t*)&g_SClo[(size_t)(r0g + 8) * CDIM + c0] = l.u;
            pr0[mt] += v00 * tw0 + v01 * tw1;
            pr1[mt] += v10 * tw0 + v11 * tw1;
        }
    }
#pragma unroll
    for (int mt = 0; mt < 4; mt++) {
        pr0[mt] += __shfl_xor_sync(0xffffffffu, pr0[mt], 1);
        pr0[mt] += __shfl_xor_sync(0xffffffffu, pr0[mt], 2);
        pr1[mt] += __shfl_xor_sync(0xffffffffu, pr1[mt], 1);
        pr1[mt] += __shfl_xor_sync(0xffffffffu, pr1[mt], 2);
        if ((lane & 3) == 0) {
            atomicAdd(&Tp[mt * 16 + (lane >> 2)], pr0[mt]);
            atomicAdd(&Tp[mt * 16 + (lane >> 2) + 8], pr1[mt]);
        }
    }
    __syncthreads();
    if (tid < 64) g_T[m0 + tid] = Tp[tid] + thr_b[0];
}

// ---------------- attention matrix kernel (round-4 shape + packed A stores) ----------------
#define S_PITCH 1044
#define OFF_S    0
#define OFF_EIH  133632
#define OFF_EIL  138240
#define OFF_BH   142848
#define OFF_BL   177664
#define OFF_TSH  212480
#define OFF_SQJ  216576
#define ATTN_SMEM 220672

__global__ __launch_bounds__(512) void attn_A_kernel() {
    extern __shared__ char smc[];
    float* S = (float*)(smc + OFF_S);                         // [32][1044]
    __nv_bfloat16* Eih = (__nv_bfloat16*)(smc + OFF_EIH);     // [32][72]
    __nv_bfloat16* Eil = (__nv_bfloat16*)(smc + OFF_EIL);
    __nv_bfloat16* BhS = (__nv_bfloat16*)(smc + OFF_BH);      // [2][64][136]
    __nv_bfloat16* BlS = (__nv_bfloat16*)(smc + OFF_BL);
    float* Tsh = (float*)(smc + OFF_TSH);
    float* Sqj = (float*)(smc + OFF_SQJ);

    int tid = threadIdx.x;
    int tile = blockIdx.x, b = blockIdx.y;
    int i0 = tile * 32;
    int base = b * HW;
    int w = tid >> 5, lane = tid & 31;
    int lrow = lane & 7, q1 = (lane >> 3) & 1, q2 = lane >> 4;
    int mt = w & 1, npair = w >> 1;

    for (int i = tid; i < 1024; i += 512) {
        Tsh[i] = g_T[base + i];
        Sqj[i] = g_sq[base + i];
    }

#define AT_ISSUE(jc, buf)                                                         \
    {                                                                             \
        for (int u_ = 0; u_ < 4; u_++) {                                          \
            int id_ = tid + u_ * 512;                                             \
            int arr_ = id_ >> 10, rem_ = id_ & 1023;                              \
            int r_ = rem_ >> 4, seg_ = rem_ & 15;                                 \
            __nv_bfloat16* dst_ = (arr_ ? BlS : BhS) + (buf) * 8704 + r_ * 136 + seg_ * 8; \
            const __nv_bfloat16* src_ = (arr_ ? g_EloT : g_EhiT) +                \
                (((size_t)b * 64 + r_) << 10) + (jc) * 128 + seg_ * 8;            \
            cp16(smem_u32(dst_), src_);                                           \
        }                                                                         \
        cp_commit();                                                              \
    }

    // prologue: Ei hi/lo joins group 0
    {
        int arr = tid >> 8, rem = tid & 255;
        int r = rem >> 3, seg = rem & 7;
        __nv_bfloat16* dst = (arr ? Eil : Eih) + r * 72 + seg * 8;
        const __nv_bfloat16* src = (arr ? g_Elo : g_Ehi) + (size_t)(base + i0 + r) * 64 + seg * 8;
        cp16(smem_u32(dst), src);
    }
    AT_ISSUE(0, 0);
    AT_ISSUE(1, 1);
    cp_wait1();
    __syncthreads();

    // hoisted A fragments
    uint32_t Ah[4][4], Al[4][4];
#pragma unroll
    for (int kc = 0; kc < 4; kc++) {
        ldm_x4(Ah[kc], smem_u32(&Eih[(mt * 16 + lrow + q1 * 8) * 72 + kc * 16 + q2 * 8]));
        ldm_x4(Al[kc], smem_u32(&Eil[(mt * 16 + lrow + q1 * 8) * 72 + kc * 16 + q2 * 8]));
    }

    // per-lane row constants
    int r0 = mt * 16 + (lane >> 2);
    int ig0 = i0 + r0, ig1 = ig0 + 8;
    int yi0 = ig0 >> 5, xi0 = ig0 & 31;
    int yi1 = ig1 >> 5, xi1 = ig1 & 31;
    float sqi0 = g_sq[base + ig0];
    float sqi1 = g_sq[base + ig1];

    // ---- Phase A ----
    for (int jc = 0; jc < 8; jc++) {
        if (jc >= 1) {
            if (jc < 7) cp_wait1(); else cp_wait0();
            __syncthreads();
        }
        int buf = jc & 1;
        float acc[2][4] = {};
#pragma unroll
        for (int kc = 0; kc < 4; kc++) {
            uint32_t bh[4];
            ldm_x4_t(bh, smem_u32(&BhS[buf * 8704 + (kc * 16 + lrow + q1 * 8) * 136 + npair * 16 + q2 * 8]));
            mma16816(acc[0], Ah[kc], bh[0], bh[1]);
            mma16816(acc[1], Ah[kc], bh[2], bh[3]);
            mma16816(acc[0], Al[kc], bh[0], bh[1]);
            mma16816(acc[1], Al[kc], bh[2], bh[3]);
            uint32_t bl[4];
            ldm_x4_t(bl, smem_u32(&BlS[buf * 8704 + (kc * 16 + lrow + q1 * 8) * 136 + npair * 16 + q2 * 8]));
            mma16816(acc[0], Ah[kc], bl[0], bl[1]);
            mma16816(acc[1], Ah[kc], bl[2], bl[3]);
        }
        int jb = jc * 128;
#pragma unroll
        for (int nt = 0; nt < 2; nt++) {
            int cA = npair * 16 + nt * 8 + (lane & 3) * 2;
            int j0 = jb + cA;
            int yj0 = j0 >> 5, xj0 = j0 & 31;
            int yj1 = (j0 + 1) >> 5, xj1 = (j0 + 1) & 31;
            float sq0 = Sqj[j0], sq1 = Sqj[j0 + 1];
            {
                float d2a = fmaxf(sqi0 + sq0 - 2.0f * acc[nt][0], 0.0f);
                float d2b = fmaxf(sqi0 + sq1 - 2.0f * acc[nt][1], 0.0f);
                int da = abs(yi0 - yj0) + abs(xi0 - xj0);
                int db = abs(yi0 - yj1) + abs(xi0 - xj1);
                float ma = (da <= 32) ? (float)da * (1.0f / 32.0f) : 0.0f;
                float mb = (db <= 32) ? (float)db * (1.0f / 32.0f) : 0.0f;
                *(float2*)&S[r0 * S_PITCH + j0] =
                    make_float2(__expf(-d2a) - 1.0f + ma, __expf(-d2b) - 1.0f + mb);
            }
            {
                float d2a = fmaxf(sqi1 + sq0 - 2.0f * acc[nt][2], 0.0f);
                float d2b = fmaxf(sqi1 + sq1 - 2.0f * acc[nt][3], 0.0f);
                int da = abs(yi1 - yj0) + abs(xi1 - xj0);
                int db = abs(yi1 - yj1) + abs(xi1 - xj1);
                float ma = (da <= 32) ? (float)da * (1.0f / 32.0f) : 0.0f;
                float mb = (db <= 32) ? (float)db * (1.0f / 32.0f) : 0.0f;
                *(float2*)&S[(r0 + 8) * S_PITCH + j0] =
                    make_float2(__expf(-d2a) - 1.0f + ma, __expf(-d2b) - 1.0f + mb);
            }
        }
        __syncthreads();
        if (jc < 6) AT_ISSUE(jc + 2, jc & 1);
    }
#undef AT_ISSUE

    // ---- Phase B: register softmax, 2 rows per warp, packed coalesced A stores ----
#pragma unroll
    for (int q = 0; q < 2; q++) {
        int r = w * 2 + q;
        float* Sr = S + r * S_PITCH;
        float v[32];
#pragma unroll
        for (int t = 0; t < 32; t++) v[t] = Sr[lane + t * 32];
        float m = -1e30f;
#pragma unroll
        for (int t = 0; t < 32; t++) m = fmaxf(m, v[t]);
#pragma unroll
        for (int o = 16; o; o >>= 1) m = fmaxf(m, __shfl_xor_sync(0xffffffffu, m, o));
        float s1 = 0.0f;
#pragma unroll
        for (int t = 0; t < 32; t++) { v[t] = __expf(v[t] - m); s1 += v[t]; }
#pragma unroll
        for (int o = 16; o; o >>= 1) s1 += __shfl_xor_sync(0xffffffffu, s1, o);
        float inv1 = 1.0f / s1;
        float m2 = 0.0f;
#pragma unroll
        for (int t = 0; t < 32; t++) {
            v[t] = fmaxf(v[t] * inv1 - Tsh[lane + t * 32], 0.0f);
            m2 = fmaxf(m2, v[t]);
        }
#pragma unroll
        for (int o = 16; o; o >>= 1) m2 = fmaxf(m2, __shfl_xor_sync(0xffffffffu, m2, o));
        float s2 = 0.0f;
#pragma unroll
        for (int t = 0; t < 32; t++) { v[t] = __expf(v[t] - m2); s2 += v[t]; }
#pragma unroll
        for (int o = 16; o; o >>= 1) s2 += __shfl_xor_sync(0xffffffffu, s2, o);
        float inv2 = 1.0f / s2;

        // repack hi/lo bf16 into this (now-dead) S row, then coalesced copy out
        __nv_bfloat16* rowh = (__nv_bfloat16*)Sr;
        __nv_bfloat16* rowl = rowh + 1024;
#pragma unroll
        for (int t = 0; t < 32; t++) {
            float val = v[t] * inv2;
            __nv_bfloat16 h = __float2bfloat16(val);
            rowh[lane + t * 32] = h;
            rowl[lane + t * 32] = __float2bfloat16(val - __bfloat162float(h));
        }
        __syncwarp();
        size_t Ab = ((size_t)b << 20) + ((size_t)(i0 + r) << 10);
        uint4* gh = (uint4*)&g_Ahi[Ab];
        uint4* gl = (uint4*)&g_Alo[Ab];
        const uint4* sh = (const uint4*)rowh;
        const uint4* sl = (const uint4*)rowl;
#pragma unroll
        for (int it = 0; it < 4; it++) gh[lane + it * 32] = sh[lane + it * 32];
#pragma unroll
        for (int it = 0; it < 4; it++) gl[lane + it * 32] = sl[lane + it * 32];
    }
}

// ---------------- tensor-core bmm: out = x + A @ SC — fused 3-term single k-sweep ----------------
// per stage (k=32 chunk): load Ahi/Alo[128][32] + Shi/Slo[32][128]; do all 3 terms.
#define BMM_OFF_AH 0
#define BMM_OFF_AL 20480
#define BMM_OFF_SH 40960
#define BMM_OFF_SL 58368
#define BMM_SMEM   75776
__global__ __launch_bounds__(256, 2) void bmm_kernel(const float* __restrict__ x,
                                                     float* __restrict__ out) {
    extern __shared__ char smc[];
    __nv_bfloat16* Ah_s = (__nv_bfloat16*)(smc + BMM_OFF_AH);  // [2][128][40]
    __nv_bfloat16* Al_s = (__nv_bfloat16*)(smc + BMM_OFF_AL);  // [2][128][40]
    __nv_bfloat16* Sh_s = (__nv_bfloat16*)(smc + BMM_OFF_SH);  // [2][32][136]
    __nv_bfloat16* Sl_s = (__nv_bfloat16*)(smc + BMM_OFF_SL);  // [2][32][136]
    int tid = threadIdx.x, w = tid >> 5, lane = tid & 31;
    int ct = blockIdx.x, mtb = blockIdx.y, b = blockIdx.z;
    int i0 = mtb * 128, c0 = ct * 128;

    const __nv_bfloat16* Ahi = g_Ahi + ((size_t)b << 20) + (size_t)i0 * 1024;
    const __nv_bfloat16* Alo = g_Alo + ((size_t)b << 20) + (size_t)i0 * 1024;
    const __nv_bfloat16* Shi = g_SChi + ((size_t)b << 18) + c0;
    const __nv_bfloat16* Slo = g_SClo + ((size_t)b << 18) + c0;

    float acc[4][4][4];
#pragma unroll
    for (int a = 0; a < 4; a++)
#pragma unroll
        for (int n = 0; n < 4; n++)
#pragma unroll
            for (int r = 0; r < 4; r++) acc[a][n][r] = 0.0f;

    int wm = w >> 2, wn = w & 3;
    int lrow = lane & 7, q1 = (lane >> 3) & 1, q2 = lane >> 4;

#define ISSUE(jc, bf_)                                                            \
    {                                                                             \
        for (int u_ = 0; u_ < 2; u_++) {                                          \
            int id_ = tid + u_ * 256;                                             \
            int ar_ = id_ >> 2, aseg_ = id_ & 3;                                  \
            cp16(smem_u32(&Ah_s[(bf_) * 5120 + ar_ * 40 + aseg_ * 8]),            \
                 Ahi + (size_t)ar_ * 1024 + (jc) * 32 + aseg_ * 8);               \
            cp16(smem_u32(&Al_s[(bf_) * 5120 + ar_ * 40 + aseg_ * 8]),            \
                 Alo + (size_t)ar_ * 1024 + (jc) * 32 + aseg_ * 8);               \
            int sr_ = id_ >> 4, sseg_ = id_ & 15;                                 \
            cp16(smem_u32(&Sh_s[(bf_) * 4352 + sr_ * 136 + sseg_ * 8]),           \
                 Shi + (size_t)((jc) * 32 + sr_) * 256 + sseg_ * 8);              \
            cp16(smem_u32(&Sl_s[(bf_) * 4352 + sr_ * 136 + sseg_ * 8]),           \
                 Slo + (size_t)((jc) * 32 + sr_) * 256 + sseg_ * 8);              \
        }                                                                         \
        cp_commit();                                                              \
    }

    ISSUE(0, 0);
    ISSUE(1, 1);
    for (int cc = 0; cc < 32; cc++) {
        if (cc < 31) cp_wait1(); else cp_wait0();
        __syncthreads();
        int buf = cc & 1;
#pragma unroll
        for (int kk = 0; kk < 2; kk++) {
            uint32_t afh[4][4], afl[4][4];
#pragma unroll
            for (int mtl = 0; mtl < 4; mtl++) {
                int row = wm * 64 + mtl * 16 + lrow + q1 * 8;
                int col = kk * 16 + q2 * 8;
                ldm_x4(afh[mtl], smem_u32(&Ah_s[buf * 5120 + row * 40 + col]));
                ldm_x4(afl[mtl], smem_u32(&Al_s[buf * 5120 + row * 40 + col]));
            }
            uint32_t bh[2][4], bl[2][4];
#pragma unroll
            for (int ng = 0; ng < 2; ng++) {
                int row = kk * 16 + lrow + q1 * 8;
                int col = wn * 32 + ng * 16 + q2 * 8;
                ldm_x4_t(bh[ng], smem_u32(&Sh_s[buf * 4352 + row * 136 + col]));
                ldm_x4_t(bl[ng], smem_u32(&Sl_s[buf * 4352 + row * 136 + col]));
            }
#pragma unroll
            for (int mtl = 0; mtl < 4; mtl++)
#pragma unroll
                for (int nt = 0; nt < 4; nt++) {
                    uint32_t h0 = bh[nt >> 1][(nt & 1) * 2], h1 = bh[nt >> 1][(nt & 1) * 2 + 1];
                    uint32_t l0 = bl[nt >> 1][(nt & 1) * 2], l1 = bl[nt >> 1][(nt & 1) * 2 + 1];
                    mma16816(acc[mtl][nt], afh[mtl], h0, h1);
                    mma16816(acc[mtl][nt], afl[mtl], h0, h1);
                    mma16816(acc[mtl][nt], afh[mtl], l0, l1);
                }
        }
        __syncthreads();   // all warps done with buf before it is overwritten
        if (cc + 2 < 32) ISSUE(cc + 2, cc & 1);
    }
#undef ISSUE

    int g = lane >> 2, t2 = lane & 3;
#pragma unroll
    for (int mtl = 0; mtl < 4; mtl++) {
#pragma unroll
        for (int nt = 0; nt < 4; nt++) {
            int row = i0 + wm * 64 + mtl * 16 + g;
            int col = c0 + wn * 32 + nt * 8 + 2 * t2;
            size_t o0 = ((size_t)b * 1024 + row) * 256 + col;
            size_t o1 = o0 + 8 * 256;
            float2 xv0 = *(const float2*)&x[o0];
            float2 xv1 = *(const float2*)&x[o1];
            *(float2*)&out[o0] = make_float2(xv0.x + acc[mtl][nt][0], xv0.y + acc[mtl][nt][1]);
            *(float2*)&out[o1] = make_float2(xv1.x + acc[mtl][nt][2], xv1.y + acc[mtl][nt][3]);
        }
    }
}

// ---------------- launch ----------------
extern "C" void kernel_launch(void* const* d_in, const int* in_sizes, int n_in,
                              void* d_out, int out_size) {
    const float* x      = (const float*)d_in[0];
    const float* emb_W  = (const float*)d_in[1];
    const float* emb_b  = (const float*)d_in[2];
    const float* attn_W = (const float*)d_in[3];
    const float* attn_b = (const float*)d_in[4];
    const float* thr_W  = (const float*)d_in[5];
    const float* thr_b  = (const float*)d_in[6];
    float* out = (float*)d_out;

    cudaFuncSetAttribute(emb_kernel, cudaFuncAttributeMaxDynamicSharedMemorySize, EMB_SMEM);
    cudaFuncSetAttribute(shortcut_kernel, cudaFuncAttributeMaxDynamicSharedMemorySize, SC_SMEM);
    cudaFuncSetAttribute(attn_A_kernel, cudaFuncAttributeMaxDynamicSharedMemorySize, ATTN_SMEM);
    cudaFuncSetAttribute(bmm_kernel, cudaFuncAttributeMaxDynamicSharedMemorySize, BMM_SMEM);

    prep_kernel<<<256, 256>>>(attn_W, emb_W);
    emb_kernel<<<BATCH * HW / 32, 256, EMB_SMEM>>>(x, emb_b);
    shortcut_kernel<<<BATCH * HW / 64, 256, SC_SMEM>>>(attn_b, thr_W, thr_b);
    attn_A_kernel<<<dim3(HW / 32, BATCH), 512, ATTN_SMEM>>>();
    bmm_kernel<<<dim3(CDIM / 128, HW / 128, BATCH), 256, BMM_SMEM>>>(x, out);
}

// round 8
// speedup vs baseline: 1.1872x; 1.0100x over previous
#include <cuda_runtime.h>
#include <cuda_bf16.h>
#include <math.h>
#include <stdint.h>

#define BATCH 32
#define HW    1024
#define CDIM  256
#define FDIM  64

// ---------------- scratch (device globals; no allocations) ----------------
__device__ float g_sq[BATCH * HW];
__device__ float g_T[BATCH * HW];
__device__ __nv_bfloat16 g_Ehi[BATCH * HW * FDIM];       // [n][k]
__device__ __nv_bfloat16 g_Elo[BATCH * HW * FDIM];
__device__ __nv_bfloat16 g_EhiT[BATCH * FDIM * HW];      // [b][k][n]
__device__ __nv_bfloat16 g_EloT[BATCH * FDIM * HW];
__device__ __nv_bfloat16 g_xhi[BATCH * HW * CDIM];
__device__ __nv_bfloat16 g_xlo[BATCH * HW * CDIM];
__device__ __nv_bfloat16 g_SChi[BATCH * HW * CDIM];
__device__ __nv_bfloat16 g_SClo[BATCH * HW * CDIM];
__device__ __nv_bfloat16 g_Ahi[(size_t)BATCH * HW * HW];
__device__ __nv_bfloat16 g_Alo[(size_t)BATCH * HW * HW];
__device__ __nv_bfloat16 g_Wthi[CDIM * CDIM];            // attn_W^T split [cin][cout]
__device__ __nv_bfloat16 g_Wtlo[CDIM * CDIM];
__device__ float g_emb_Wt[CDIM * FDIM];

// ---------------- small helpers ----------------
__device__ __forceinline__ uint32_t smem_u32(const void* p) {
    return (uint32_t)__cvta_generic_to_shared(p);
}
__device__ __forceinline__ void cp16(uint32_t dst, const void* src) {
    asm volatile("cp.async.cg.shared.global [%0], [%1], 16;\n" :: "r"(dst), "l"(src));
}
__device__ __forceinline__ void cp_commit() { asm volatile("cp.async.commit_group;\n"); }
__device__ __forceinline__ void cp_wait1() { asm volatile("cp.async.wait_group 1;\n"); }
__device__ __forceinline__ void cp_wait0() { asm volatile("cp.async.wait_group 0;\n"); }
__device__ __forceinline__ void ldm_x4(uint32_t (&r)[4], uint32_t addr) {
    asm volatile("ldmatrix.sync.aligned.m8n8.x4.shared.b16 {%0,%1,%2,%3}, [%4];"
                 : "=r"(r[0]), "=r"(r[1]), "=r"(r[2]), "=r"(r[3]) : "r"(addr));
}
__device__ __forceinline__ void ldm_x4_t(uint32_t (&r)[4], uint32_t addr) {
    asm volatile("ldmatrix.sync.aligned.m8n8.x4.trans.shared.b16 {%0,%1,%2,%3}, [%4];"
                 : "=r"(r[0]), "=r"(r[1]), "=r"(r[2]), "=r"(r[3]) : "r"(addr));
}
__device__ __forceinline__ void ldm_x2_t(uint32_t (&r)[2], uint32_t addr) {
    asm volatile("ldmatrix.sync.aligned.m8n8.x2.trans.shared.b16 {%0,%1}, [%2];"
                 : "=r"(r[0]), "=r"(r[1]) : "r"(addr));
}
__device__ __forceinline__ void mma16816(float (&d)[4], const uint32_t (&a)[4],
                                         uint32_t b0, uint32_t b1) {
    asm volatile("mma.sync.aligned.m16n8k16.row.col.f32.bf16.bf16.f32 "
                 "{%0,%1,%2,%3}, {%4,%5,%6,%7}, {%8,%9}, {%0,%1,%2,%3};"
                 : "+f"(d[0]), "+f"(d[1]), "+f"(d[2]), "+f"(d[3])
                 : "r"(a[0]), "r"(a[1]), "r"(a[2]), "r"(a[3]), "r"(b0), "r"(b1));
}
union BPack2 { __nv_bfloat16 h[2]; uint32_t u; };
union BPack4 { __nv_bfloat16 h[4]; uint2 u; };

// ---------------- prep: weight transposes + bf16 splits ----------------
__global__ void prep_kernel(const float* __restrict__ attn_W,
                            const float* __restrict__ emb_W) {
    int t = blockIdx.x * 256 + threadIdx.x;
    if (t < CDIM * CDIM) {
        int ci = t >> 8, co = t & 255;
        float v = attn_W[co * CDIM + ci];
        __nv_bfloat16 h = __float2bfloat16(v);
        g_Wthi[ci * CDIM + co] = h;
        g_Wtlo[ci * CDIM + co] = __float2bfloat16(v - __bfloat162float(h));
    }
    if (t < FDIM * CDIM) {
        int f = t >> 8, ci = t & 255;
        g_emb_Wt[ci * FDIM + f] = emb_W[f * CDIM + ci];
    }
}

// ---------------- emb: x @ emb_W^T + b -> bf16 hi/lo (+transposed) + sq + x-split ----------------
#define EMB_SMEM ((32 * 256 + 256 * 64) * 4)
__global__ __launch_bounds__(256) void emb_kernel(const float* __restrict__ x,
                                                  const float* __restrict__ emb_b) {
    extern __shared__ float sm[];
    float* xs = sm;              // [32][256]
    float* we = sm + 32 * 256;   // [256][64]
    int tid = threadIdx.x;
    int row0 = blockIdx.x * 32;
    int bb = row0 >> 10, n0 = row0 & 1023;

    const float4* xg = (const float4*)(x + (size_t)row0 * CDIM);
    float4* xs4 = (float4*)xs;
    for (int i = tid; i < 32 * 64; i += 256) xs4[i] = xg[i];
    const float4* wg = (const float4*)g_emb_Wt;
    float4* we4 = (float4*)we;
    for (int i = tid; i < 256 * 16; i += 256) we4[i] = wg[i];
    __syncthreads();

    // fused x -> bf16 hi/lo split
    for (int i = tid; i < 2048; i += 256) {
        float4 v = xs4[i];
        float vv[4] = {v.x, v.y, v.z, v.w};
        BPack4 ph, pl;
#pragma unroll
        for (int q = 0; q < 4; q++) {
            __nv_bfloat16 h = __float2bfloat16(vv[q]);
            ph.h[q] = h;
            pl.h[q] = __float2bfloat16(vv[q] - __bfloat162float(h));
        }
        ((uint2*)g_xhi)[(size_t)row0 * 64 + i] = ph.u;
        ((uint2*)g_xlo)[(size_t)row0 * 64 + i] = pl.u;
    }

    int w = tid >> 5, lane = tid & 31;
    int ig = w * 4, fg = lane * 2;
    float acc[4][2] = {};
#pragma unroll 4
    for (int c = 0; c < 256; c++) {
        float2 wv = *(const float2*)&we[c * 64 + fg];
#pragma unroll
        for (int q = 0; q < 4; q++) {
            float a = xs[(ig + q) * 256 + c];
            acc[q][0] = fmaf(a, wv.x, acc[q][0]);
            acc[q][1] = fmaf(a, wv.y, acc[q][1]);
        }
    }
    float b0 = emb_b[fg], b1 = emb_b[fg + 1];
    float e0r[4], e1r[4];
#pragma unroll
    for (int q = 0; q < 4; q++) {
        float e0 = acc[q][0] + b0, e1 = acc[q][1] + b1;
        e0r[q] = e0; e1r[q] = e1;
        int n = row0 + ig + q;
        BPack2 ph, pl;
        ph.h[0] = __float2bfloat16(e0);
        ph.h[1] = __float2bfloat16(e1);
        pl.h[0] = __float2bfloat16(e0 - __bfloat162float(ph.h[0]));
        pl.h[1] = __float2bfloat16(e1 - __bfloat162float(ph.h[1]));
        *(uint32_t*)&g_Ehi[(size_t)n * FDIM + fg] = ph.u;
        *(uint32_t*)&g_Elo[(size_t)n * FDIM + fg] = pl.u;
        float p = e0 * e0 + e1 * e1;
#pragma unroll
        for (int o = 16; o; o >>= 1) p += __shfl_xor_sync(0xffffffffu, p, o);
        if (lane == 0) g_sq[n] = p;
    }

    // transposed bf16 copies via smem staging: [64][33]
    __nv_bfloat16* st = (__nv_bfloat16*)sm;
    __syncthreads();
#pragma unroll
    for (int q = 0; q < 4; q++) {
        st[fg * 33 + ig + q] = __float2bfloat16(e0r[q]);
        st[(fg + 1) * 33 + ig + q] = __float2bfloat16(e1r[q]);
    }
    __syncthreads();
    for (int idx = tid; idx < 2048; idx += 256) {
        int k = idx >> 5, i2 = idx & 31;
        g_EhiT[(((size_t)bb * 64 + k) << 10) + n0 + i2] = st[k * 33 + i2];
    }
    __syncthreads();
#pragma unroll
    for (int q = 0; q < 4; q++) {
        float h0 = __bfloat162float(__float2bfloat16(e0r[q]));
        float h1 = __bfloat162float(__float2bfloat16(e1r[q]));
        st[fg * 33 + ig + q] = __float2bfloat16(e0r[q] - h0);
        st[(fg + 1) * 33 + ig + q] = __float2bfloat16(e1r[q] - h1);
    }
    __syncthreads();
    for (int idx = tid; idx < 2048; idx += 256) {
        int k = idx >> 5, i2 = idx & 31;
        g_EloT[(((size_t)bb * 64 + k) << 10) + n0 + i2] = st[k * 33 + i2];
    }
}

// ---------------- shortcut: SC = x @ W^T + b (3-term), plus T — 3-stage ring ----------------
#define SC_OFF_A 0
#define SC_OFF_B 15360
#define SC_OFF_T 66048
#define SC_SMEM  66304
__global__ __launch_bounds__(256) void shortcut_kernel(const float* __restrict__ attn_b,
                                                       const float* __restrict__ thr_W,
                                                       const float* __restrict__ thr_b) {
    extern __shared__ char smc[];
    __nv_bfloat16* Asp = (__nv_bfloat16*)(smc + SC_OFF_A);   // [3][64][40]
    __nv_bfloat16* Bsp = (__nv_bfloat16*)(smc + SC_OFF_B);   // [3][32][264]
    float* Tp = (float*)(smc + SC_OFF_T);
    int tid = threadIdx.x, w = tid >> 5, lane = tid & 31;
    int m0 = blockIdx.x * 64;
    int lrow = lane & 7, q1 = (lane >> 3) & 1, q2 = lane >> 4;

    if (tid < 64) Tp[tid] = 0.0f;

    float acc[4][4][4];
#pragma unroll
    for (int a = 0; a < 4; a++)
#pragma unroll
        for (int n = 0; n < 4; n++)
#pragma unroll
            for (int r = 0; r < 4; r++) acc[a][n][r] = 0.0f;

#define SC_ISSUE(s, bf_)                                                          \
    {                                                                             \
        int term_ = (s) >> 3, kc_ = (s) & 7;                                      \
        const __nv_bfloat16* Ap_ = (term_ == 1) ? g_xlo : g_xhi;                  \
        const __nv_bfloat16* Bp_ = (term_ == 2) ? g_Wtlo : g_Wthi;                \
        int ar_ = tid >> 2, aseg_ = tid & 3;                                      \
        cp16(smem_u32(&Asp[(bf_) * 2560 + ar_ * 40 + aseg_ * 8]),                 \
             Ap_ + (size_t)(m0 + ar_) * CDIM + kc_ * 32 + aseg_ * 8);             \
        for (int u_ = 0; u_ < 4; u_++) {                                          \
            int id_ = tid + u_ * 256;                                             \
            int br_ = id_ >> 5, bseg_ = id_ & 31;                                 \
            cp16(smem_u32(&Bsp[(bf_) * 8448 + br_ * 264 + bseg_ * 8]),            \
                 Bp_ + (size_t)(kc_ * 32 + br_) * CDIM + bseg_ * 8);              \
        }                                                                         \
        cp_commit();                                                              \
    }

    SC_ISSUE(0, 0);
    SC_ISSUE(1, 1);
    for (int s = 0; s < 24; s++) {
        if (s < 23) cp_wait1(); else cp_wait0();
        __syncthreads();
        int buf = s % 3;
#pragma unroll
        for (int kk = 0; kk < 2; kk++) {
            uint32_t af[4][4];
#pragma unroll
            for (int mt = 0; mt < 4; mt++)
                ldm_x4(af[mt], smem_u32(&Asp[buf * 2560 + (mt * 16 + lrow + q1 * 8) * 40 + kk * 16 + q2 * 8]));
            uint32_t bfr[2][4];
#pragma unroll
            for (int ng = 0; ng < 2; ng++)
                ldm_x4_t(bfr[ng], smem_u32(&Bsp[buf * 8448 + (kk * 16 + lrow + q1 * 8) * 264 + w * 32 + ng * 16 + q2 * 8]));
#pragma unroll
            for (int mt = 0; mt < 4; mt++)
#pragma unroll
                for (int nt = 0; nt < 4; nt++)
                    mma16816(acc[mt][nt], af[mt],
                             bfr[nt >> 1][(nt & 1) * 2], bfr[nt >> 1][(nt & 1) * 2 + 1]);
        }
        if (s + 2 < 24) SC_ISSUE(s + 2, (s + 2) % 3);
    }
#undef SC_ISSUE

    // epilogue: bias, bf16 hi/lo stores, T partials
    float pr0[4] = {}, pr1[4] = {};
#pragma unroll
    for (int nt = 0; nt < 4; nt++) {
        int c0 = w * 32 + nt * 8 + (lane & 3) * 2;
        float bb0 = attn_b[c0], bb1 = attn_b[c0 + 1];
        float tw0 = thr_W[c0], tw1 = thr_W[c0 + 1];
#pragma unroll
        for (int mt = 0; mt < 4; mt++) {
            int r0g = m0 + mt * 16 + (lane >> 2);
            float v00 = acc[mt][nt][0] + bb0, v01 = acc[mt][nt][1] + bb1;
            float v10 = acc[mt][nt][2] + bb0, v11 = acc[mt][nt][3] + bb1;
            BPack2 h, l;
            h.h[0] = __float2bfloat16(v00); h.h[1] = __float2bfloat16(v01);
            l.h[0] = __float2bfloat16(v00 - __bfloat162float(h.h[0]));
            l.h[1] = __float2bfloat16(v01 - __bfloat162float(h.h[1]));
            *(uint32_t*)&g_SChi[(size_t)r0g * CDIM + c0] = h.u;
            *(uint32_t*)&g_SClo[(size_t)r0g * CDIM + c0] = l.u;
            h.h[0] = __float2bfloat16(v10); h.h[1] = __float2bfloat16(v11);
            l.h[0] = __float2bfloat16(v10 - __bfloat162float(h.h[0]));
            l.h[1] = __float2bfloat16(v11 - __bfloat162float(h.h[1]));
            *(uint32_t*)&g_SChi[(size_t)(r0g + 8) * CDIM + c0] = h.u;
            *(uint32_t*)&g_SClo[(size_t)(r0g + 8) * CDIM + c0] = l.u;
            pr0[mt] += v00 * tw0 + v01 * tw1;
            pr1[mt] += v10 * tw0 + v11 * tw1;
        }
    }
#pragma unroll
    for (int mt = 0; mt < 4; mt++) {
        pr0[mt] += __shfl_xor_sync(0xffffffffu, pr0[mt], 1);
        pr0[mt] += __shfl_xor_sync(0xffffffffu, pr0[mt], 2);
        pr1[mt] += __shfl_xor_sync(0xffffffffu, pr1[mt], 1);
        pr1[mt] += __shfl_xor_sync(0xffffffffu, pr1[mt], 2);
        if ((lane & 3) == 0) {
            atomicAdd(&Tp[mt * 16 + (lane >> 2)], pr0[mt]);
            atomicAdd(&Tp[mt * 16 + (lane >> 2) + 8], pr1[mt]);
        }
    }
    __syncthreads();
    if (tid < 64) g_T[m0 + tid] = Tp[tid] + thr_b[0];
}

// ---------------- attention matrix kernel: 32 rows, 1024 threads / 32 warps ----------------
#define S_PITCH 1044
#define OFF_S    0
#define OFF_EIH  133632
#define OFF_EIL  138240
#define OFF_BH   142848
#define OFF_BL   177664
#define OFF_TSH  212480
#define OFF_SQJ  216576
#define ATTN_SMEM 220672

__global__ __launch_bounds__(1024) void attn_A_kernel() {
    extern __shared__ char smc[];
    float* S = (float*)(smc + OFF_S);                         // [32][1044]
    __nv_bfloat16* Eih = (__nv_bfloat16*)(smc + OFF_EIH);     // [32][72]
    __nv_bfloat16* Eil = (__nv_bfloat16*)(smc + OFF_EIL);
    __nv_bfloat16* BhS = (__nv_bfloat16*)(smc + OFF_BH);      // [2][64][136]
    __nv_bfloat16* BlS = (__nv_bfloat16*)(smc + OFF_BL);
    float* Tsh = (float*)(smc + OFF_TSH);
    float* Sqj = (float*)(smc + OFF_SQJ);

    int tid = threadIdx.x;
    int tile = blockIdx.x, b = blockIdx.y;
    int i0 = tile * 32;
    int base = b * HW;
    int w = tid >> 5, lane = tid & 31;
    int lrow = lane & 7, q1 = (lane >> 3) & 1, q2 = lane >> 4;
    int mt = w & 1, ncol = w >> 1;         // 32 warps: 2 row-halves x 16 col-tiles of 8

    for (int i = tid; i < 1024; i += 1024) {
        Tsh[i] = g_T[base + i];
        Sqj[i] = g_sq[base + i];
    }

#define AT_ISSUE(jc, buf)                                                         \
    {                                                                             \
        for (int u_ = 0; u_ < 2; u_++) {                                          \
            int id_ = tid + u_ * 1024;                                            \
            int arr_ = id_ >> 10, rem_ = id_ & 1023;                              \
            int r_ = rem_ >> 4, seg_ = rem_ & 15;                                 \
            __nv_bfloat16* dst_ = (arr_ ? BlS : BhS) + (buf) * 8704 + r_ * 136 + seg_ * 8; \
            const __nv_bfloat16* src_ = (arr_ ? g_EloT : g_EhiT) +                \
                (((size_t)b * 64 + r_) << 10) + (jc) * 128 + seg_ * 8;            \
            cp16(smem_u32(dst_), src_);                                           \
        }                                                                         \
        cp_commit();                                                              \
    }

    // prologue: Ei hi/lo joins group 0
    if (tid < 512) {
        int arr = tid >> 8, rem = tid & 255;
        int r = rem >> 3, seg = rem & 7;
        __nv_bfloat16* dst = (arr ? Eil : Eih) + r * 72 + seg * 8;
        const __nv_bfloat16* src = (arr ? g_Elo : g_Ehi) + (size_t)(base + i0 + r) * 64 + seg * 8;
        cp16(smem_u32(dst), src);
    }
    AT_ISSUE(0, 0);
    AT_ISSUE(1, 1);
    cp_wait1();
    __syncthreads();

    // hoisted A fragments (each warp: its 16-row half, all k)
    uint32_t Ah[4][4], Al[4][4];
#pragma unroll
    for (int kc = 0; kc < 4; kc++) {
        ldm_x4(Ah[kc], smem_u32(&Eih[(mt * 16 + lrow + q1 * 8) * 72 + kc * 16 + q2 * 8]));
        ldm_x4(Al[kc], smem_u32(&Eil[(mt * 16 + lrow + q1 * 8) * 72 + kc * 16 + q2 * 8]));
    }

    // per-lane row constants
    int r0 = mt * 16 + (lane >> 2);
    int ig0 = i0 + r0, ig1 = ig0 + 8;
    int yi0 = ig0 >> 5, xi0 = ig0 & 31;
    int yi1 = ig1 >> 5, xi1 = ig1 & 31;
    float sqi0 = g_sq[base + ig0];
    float sqi1 = g_sq[base + ig1];
    // B ldmatrix.x2 source row offset (lanes 0-15 supply addresses)
    int brow = (lane & 7) + ((lane >> 3) & 1) * 8;

    // ---- Phase A ----
    for (int jc = 0; jc < 8; jc++) {
        if (jc >= 1) {
            if (jc < 7) cp_wait1(); else cp_wait0();
            __syncthreads();
        }
        int buf = jc & 1;
        float acc[4] = {};
#pragma unroll
        for (int kc = 0; kc < 4; kc++) {
            uint32_t bh[2], bl[2];
            ldm_x2_t(bh, smem_u32(&BhS[buf * 8704 + (kc * 16 + brow) * 136 + ncol * 8]));
            ldm_x2_t(bl, smem_u32(&BlS[buf * 8704 + (kc * 16 + brow) * 136 + ncol * 8]));
            mma16816(acc, Ah[kc], bh[0], bh[1]);
            mma16816(acc, Al[kc], bh[0], bh[1]);
            mma16816(acc, Ah[kc], bl[0], bl[1]);
        }
        int j0 = jc * 128 + ncol * 8 + (lane & 3) * 2;
        int yj0 = j0 >> 5, xj0 = j0 & 31;
        int yj1 = (j0 + 1) >> 5, xj1 = (j0 + 1) & 31;
        float sq0 = Sqj[j0], sq1 = Sqj[j0 + 1];
        {
            float d2a = fmaxf(sqi0 + sq0 - 2.0f * acc[0], 0.0f);
            float d2b = fmaxf(sqi0 + sq1 - 2.0f * acc[1], 0.0f);
            int da = abs(yi0 - yj0) + abs(xi0 - xj0);
            int db = abs(yi0 - yj1) + abs(xi0 - xj1);
            float ma = (da <= 32) ? (float)da * (1.0f / 32.0f) : 0.0f;
            float mb = (db <= 32) ? (float)db * (1.0f / 32.0f) : 0.0f;
            *(float2*)&S[r0 * S_PITCH + j0] =
                make_float2(__expf(-d2a) - 1.0f + ma, __expf(-d2b) - 1.0f + mb);
        }
        {
            float d2a = fmaxf(sqi1 + sq0 - 2.0f * acc[2], 0.0f);
            float d2b = fmaxf(sqi1 + sq1 - 2.0f * acc[3], 0.0f);
            int da = abs(yi1 - yj0) + abs(xi1 - xj0);
            int db = abs(yi1 - yj1) + abs(xi1 - xj1);
            float ma = (da <= 32) ? (float)da * (1.0f / 32.0f) : 0.0f;
            float mb = (db <= 32) ? (float)db * (1.0f / 32.0f) : 0.0f;
            *(float2*)&S[(r0 + 8) * S_PITCH + j0] =
                make_float2(__expf(-d2a) - 1.0f + ma, __expf(-d2b) - 1.0f + mb);
        }
        __syncthreads();
        if (jc < 6) AT_ISSUE(jc + 2, jc & 1);
    }
#undef AT_ISSUE

    // ---- Phase B: register softmax, 1 row per warp, packed coalesced A stores ----
    {
        int r = w;
        float* Sr = S + r * S_PITCH;
        float v[32];
#pragma unroll
        for (int t = 0; t < 32; t++) v[t] = Sr[lane + t * 32];
        float m = -1e30f;
#pragma unroll
        for (int t = 0; t < 32; t++) m = fmaxf(m, v[t]);
#pragma unroll
        for (int o = 16; o; o >>= 1) m = fmaxf(m, __shfl_xor_sync(0xffffffffu, m, o));
        float s1 = 0.0f;
#pragma unroll
        for (int t = 0; t < 32; t++) { v[t] = __expf(v[t] - m); s1 += v[t]; }
#pragma unroll
        for (int o = 16; o; o >>= 1) s1 += __shfl_xor_sync(0xffffffffu, s1, o);
        float inv1 = 1.0f / s1;
        float m2 = 0.0f;
#pragma unroll
        for (int t = 0; t < 32; t++) {
            v[t] = fmaxf(v[t] * inv1 - Tsh[lane + t * 32], 0.0f);
            m2 = fmaxf(m2, v[t]);
        }
#pragma unroll
        for (int o = 16; o; o >>= 1) m2 = fmaxf(m2, __shfl_xor_sync(0xffffffffu, m2, o));
        float s2 = 0.0f;
#pragma unroll
        for (int t = 0; t < 32; t++) { v[t] = __expf(v[t] - m2); s2 += v[t]; }
#pragma unroll
        for (int o = 16; o; o >>= 1) s2 += __shfl_xor_sync(0xffffffffu, s2, o);
        float inv2 = 1.0f / s2;

        // repack hi/lo bf16 into this (now-dead) S row, then coalesced copy out
        __nv_bfloat16* rowh = (__nv_bfloat16*)Sr;
        __nv_bfloat16* rowl = rowh + 1024;
#pragma unroll
        for (int t = 0; t < 32; t++) {
            float val = v[t] * inv2;
            __nv_bfloat16 h = __float2bfloat16(val);
            rowh[lane + t * 32] = h;
            rowl[lane + t * 32] = __float2bfloat16(val - __bfloat162float(h));
        }
        __syncwarp();
        size_t Ab = ((size_t)b << 20) + ((size_t)(i0 + r) << 10);
        uint4* gh = (uint4*)&g_Ahi[Ab];
        uint4* gl = (uint4*)&g_Alo[Ab];
        const uint4* sh = (const uint4*)rowh;
        const uint4* sl = (const uint4*)rowl;
#pragma unroll
        for (int it = 0; it < 4; it++) gh[lane + it * 32] = sh[lane + it * 32];
#pragma unroll
        for (int it = 0; it < 4; it++) gl[lane + it * 32] = sl[lane + it * 32];
    }
}

// ---------------- tensor-core bmm: out = x + A @ SC — fused 3-term single k-sweep ----------------
#define BMM_OFF_AH 0
#define BMM_OFF_AL 20480
#define BMM_OFF_SH 40960
#define BMM_OFF_SL 58368
#define BMM_SMEM   75776
__global__ __launch_bounds__(256, 2) void bmm_kernel(const float* __restrict__ x,
                                                     float* __restrict__ out) {
    extern __shared__ char smc[];
    __nv_bfloat16* Ah_s = (__nv_bfloat16*)(smc + BMM_OFF_AH);  // [2][128][40]
    __nv_bfloat16* Al_s = (__nv_bfloat16*)(smc + BMM_OFF_AL);  // [2][128][40]
    __nv_bfloat16* Sh_s = (__nv_bfloat16*)(smc + BMM_OFF_SH);  // [2][32][136]
    __nv_bfloat16* Sl_s = (__nv_bfloat16*)(smc + BMM_OFF_SL);  // [2][32][136]
    int tid = threadIdx.x, w = tid >> 5, lane = tid & 31;
    int ct = blockIdx.x, mtb = blockIdx.y, b = blockIdx.z;
    int i0 = mtb * 128, c0 = ct * 128;

    const __nv_bfloat16* Ahi = g_Ahi + ((size_t)b << 20) + (size_t)i0 * 1024;
    const __nv_bfloat16* Alo = g_Alo + ((size_t)b << 20) + (size_t)i0 * 1024;
    const __nv_bfloat16* Shi = g_SChi + ((size_t)b << 18) + c0;
    const __nv_bfloat16* Slo = g_SClo + ((size_t)b << 18) + c0;

    float acc[4][4][4];
#pragma unroll
    for (int a = 0; a < 4; a++)
#pragma unroll
        for (int n = 0; n < 4; n++)
#pragma unroll
            for (int r = 0; r < 4; r++) acc[a][n][r] = 0.0f;

    int wm = w >> 2, wn = w & 3;
    int lrow = lane & 7, q1 = (lane >> 3) & 1, q2 = lane >> 4;

#define ISSUE(jc, bf_)                                                            \
    {                                                                             \
        for (int u_ = 0; u_ < 2; u_++) {                                          \
            int id_ = tid + u_ * 256;                                             \
            int ar_ = id_ >> 2, aseg_ = id_ & 3;                                  \
            cp16(smem_u32(&Ah_s[(bf_) * 5120 + ar_ * 40 + aseg_ * 8]),            \
                 Ahi + (size_t)ar_ * 1024 + (jc) * 32 + aseg_ * 8);               \
            cp16(smem_u32(&Al_s[(bf_) * 5120 + ar_ * 40 + aseg_ * 8]),            \
                 Alo + (size_t)ar_ * 1024 + (jc) * 32 + aseg_ * 8);               \
            int sr_ = id_ >> 4, sseg_ = id_ & 15;                                 \
            cp16(smem_u32(&Sh_s[(bf_) * 4352 + sr_ * 136 + sseg_ * 8]),           \
                 Shi + (size_t)((jc) * 32 + sr_) * 256 + sseg_ * 8);              \
            cp16(smem_u32(&Sl_s[(bf_) * 4352 + sr_ * 136 + sseg_ * 8]),           \
                 Slo + (size_t)((jc) * 32 + sr_) * 256 + sseg_ * 8);              \
        }                                                                         \
        cp_commit();                                                              \
    }

    ISSUE(0, 0);
    ISSUE(1, 1);
    for (int cc = 0; cc < 32; cc++) {
        if (cc < 31) cp_wait1(); else cp_wait0();
        __syncthreads();
        int buf = cc & 1;
#pragma unroll
        for (int kk = 0; kk < 2; kk++) {
            uint32_t afh[4][4], afl[4][4];
#pragma unroll
            for (int mtl = 0; mtl < 4; mtl++) {
                int row = wm * 64 + mtl * 16 + lrow + q1 * 8;
                int col = kk * 16 + q2 * 8;
                ldm_x4(afh[mtl], smem_u32(&Ah_s[buf * 5120 + row * 40 + col]));
                ldm_x4(afl[mtl], smem_u32(&Al_s[buf * 5120 + row * 40 + col]));
            }
            uint32_t bh[2][4], bl[2][4];
#pragma unroll
            for (int ng = 0; ng < 2; ng++) {
                int row = kk * 16 + lrow + q1 * 8;
                int col = wn * 32 + ng * 16 + q2 * 8;
                ldm_x4_t(bh[ng], smem_u32(&Sh_s[buf * 4352 + row * 136 + col]));
                ldm_x4_t(bl[ng], smem_u32(&Sl_s[buf * 4352 + row * 136 + col]));
            }
#pragma unroll
            for (int mtl = 0; mtl < 4; mtl++)
#pragma unroll
                for (int nt = 0; nt < 4; nt++) {
                    uint32_t h0 = bh[nt >> 1][(nt & 1) * 2], h1 = bh[nt >> 1][(nt & 1) * 2 + 1];
                    uint32_t l0 = bl[nt >> 1][(nt & 1) * 2], l1 = bl[nt >> 1][(nt & 1) * 2 + 1];
                    mma16816(acc[mtl][nt], afh[mtl], h0, h1);
                    mma16816(acc[mtl][nt], afl[mtl], h0, h1);
                    mma16816(acc[mtl][nt], afh[mtl], l0, l1);
                }
        }
        __syncthreads();   // all warps done with buf before it is overwritten
        if (cc + 2 < 32) ISSUE(cc + 2, cc & 1);
    }
#undef ISSUE

    int g = lane >> 2, t2 = lane & 3;
#pragma unroll
    for (int mtl = 0; mtl < 4; mtl++) {
#pragma unroll
        for (int nt = 0; nt < 4; nt++) {
            int row = i0 + wm * 64 + mtl * 16 + g;
            int col = c0 + wn * 32 + nt * 8 + 2 * t2;
            size_t o0 = ((size_t)b * 1024 + row) * 256 + col;
            size_t o1 = o0 + 8 * 256;
            float2 xv0 = *(const float2*)&x[o0];
            float2 xv1 = *(const float2*)&x[o1];
            *(float2*)&out[o0] = make_float2(xv0.x + acc[mtl][nt][0], xv0.y + acc[mtl][nt][1]);
            *(float2*)&out[o1] = make_float2(xv1.x + acc[mtl][nt][2], xv1.y + acc[mtl][nt][3]);
        }
    }
}

// ---------------- launch ----------------
extern "C" void kernel_launch(void* const* d_in, const int* in_sizes, int n_in,
                              void* d_out, int out_size) {
    const float* x      = (const float*)d_in[0];
    const float* emb_W  = (const float*)d_in[1];
    const float* emb_b  = (const float*)d_in[2];
    const float* attn_W = (const float*)d_in[3];
    const float* attn_b = (const float*)d_in[4];
    const float* thr_W  = (const float*)d_in[5];
    const float* thr_b  = (const float*)d_in[6];
    float* out = (float*)d_out;

    cudaFuncSetAttribute(emb_kernel, cudaFuncAttributeMaxDynamicSharedMemorySize, EMB_SMEM);
    cudaFuncSetAttribute(shortcut_kernel, cudaFuncAttributeMaxDynamicSharedMemorySize, SC_SMEM);
    cudaFuncSetAttribute(attn_A_kernel, cudaFuncAttributeMaxDynamicSharedMemorySize, ATTN_SMEM);
    cudaFuncSetAttribute(bmm_kernel, cudaFuncAttributeMaxDynamicSharedMemorySize, BMM_SMEM);

    prep_kernel<<<256, 256>>>(attn_W, emb_W);
    emb_kernel<<<BATCH * HW / 32, 256, EMB_SMEM>>>(x, emb_b);
    shortcut_kernel<<<BATCH * HW / 64, 256, SC_SMEM>>>(attn_b, thr_W, thr_b);
    attn_A_kernel<<<dim3(HW / 32, BATCH), 1024, ATTN_SMEM>>>();
    bmm_kernel<<<dim3(CDIM / 128, HW / 128, BATCH), 256, BMM_SMEM>>>(x, out);
}

// round 10
// speedup vs baseline: 1.4017x; 1.1807x over previous
#include <cuda_runtime.h>
#include <cuda_bf16.h>
#include <cuda_fp16.h>
#include <math.h>
#include <stdint.h>

#define BATCH 32
#define HW    1024
#define CDIM  256
#define FDIM  64

// ---------------- scratch (device globals; no allocations) ----------------
__device__ float g_sq[BATCH * HW];
__device__ float g_T[BATCH * HW];
__device__ __nv_bfloat16 g_Ehi[BATCH * HW * FDIM];       // [n][k]
__device__ __nv_bfloat16 g_Elo[BATCH * HW * FDIM];
__device__ __nv_bfloat16 g_EhiT[BATCH * FDIM * HW];      // [b][k][n]
__device__ __nv_bfloat16 g_EloT[BATCH * FDIM * HW];
__device__ __nv_bfloat16 g_xhi[BATCH * HW * CDIM];
__device__ __nv_bfloat16 g_xlo[BATCH * HW * CDIM];
__device__ __half g_SChi[BATCH * HW * CDIM];             // fp16 hi/lo split
__device__ __half g_SClo[BATCH * HW * CDIM];
__device__ __half g_Af[(size_t)BATCH * HW * HW];         // 64 MB, single fp16 A
__device__ __nv_bfloat16 g_Wthi[CDIM * CDIM];            // attn_W^T split [cin][cout]
__device__ __nv_bfloat16 g_Wtlo[CDIM * CDIM];
__device__ float g_emb_Wt[CDIM * FDIM];

// ---------------- small helpers ----------------
__device__ __forceinline__ uint32_t smem_u32(const void* p) {
    return (uint32_t)__cvta_generic_to_shared(p);
}
__device__ __forceinline__ void cp16(uint32_t dst, const void* src) {
    asm volatile("cp.async.cg.shared.global [%0], [%1], 16;\n" :: "r"(dst), "l"(src));
}
__device__ __forceinline__ void cp_commit() { asm volatile("cp.async.commit_group;\n"); }
__device__ __forceinline__ void cp_wait1() { asm volatile("cp.async.wait_group 1;\n"); }
__device__ __forceinline__ void cp_wait0() { asm volatile("cp.async.wait_group 0;\n"); }
__device__ __forceinline__ void ldm_x4(uint32_t (&r)[4], uint32_t addr) {
    asm volatile("ldmatrix.sync.aligned.m8n8.x4.shared.b16 {%0,%1,%2,%3}, [%4];"
                 : "=r"(r[0]), "=r"(r[1]), "=r"(r[2]), "=r"(r[3]) : "r"(addr));
}
__device__ __forceinline__ void ldm_x4_t(uint32_t (&r)[4], uint32_t addr) {
    asm volatile("ldmatrix.sync.aligned.m8n8.x4.trans.shared.b16 {%0,%1,%2,%3}, [%4];"
                 : "=r"(r[0]), "=r"(r[1]), "=r"(r[2]), "=r"(r[3]) : "r"(addr));
}
__device__ __forceinline__ void ldm_x2_t(uint32_t (&r)[2], uint32_t addr) {
    asm volatile("ldmatrix.sync.aligned.m8n8.x2.trans.shared.b16 {%0,%1}, [%2];"
                 : "=r"(r[0]), "=r"(r[1]) : "r"(addr));
}
// bf16 mma (Gram / shortcut path)
__device__ __forceinline__ void mma16816(float (&d)[4], const uint32_t (&a)[4],
                                         uint32_t b0, uint32_t b1) {
    asm volatile("mma.sync.aligned.m16n8k16.row.col.f32.bf16.bf16.f32 "
                 "{%0,%1,%2,%3}, {%4,%5,%6,%7}, {%8,%9}, {%0,%1,%2,%3};"
                 : "+f"(d[0]), "+f"(d[1]), "+f"(d[2]), "+f"(d[3])
                 : "r"(a[0]), "r"(a[1]), "r"(a[2]), "r"(a[3]), "r"(b0), "r"(b1));
}
// fp16 mma (bmm path)
__device__ __forceinline__ void mma16816h(float (&d)[4], const uint32_t (&a)[4],
                                          uint32_t b0, uint32_t b1) {
    asm volatile("mma.sync.aligned.m16n8k16.row.col.f32.f16.f16.f32 "
                 "{%0,%1,%2,%3}, {%4,%5,%6,%7}, {%8,%9}, {%0,%1,%2,%3};"
                 : "+f"(d[0]), "+f"(d[1]), "+f"(d[2]), "+f"(d[3])
                 : "r"(a[0]), "r"(a[1]), "r"(a[2]), "r"(a[3]), "r"(b0), "r"(b1));
}
union BPack2 { __nv_bfloat16 h[2]; uint32_t u; };
union BPack4 { __nv_bfloat16 h[4]; uint2 u; };
union HPack2 { __half h[2]; uint32_t u; };

// ---------------- prep: weight transposes + bf16 splits ----------------
__global__ void prep_kernel(const float* __restrict__ attn_W,
                            const float* __restrict__ emb_W) {
    int t = blockIdx.x * 256 + threadIdx.x;
    if (t < CDIM * CDIM) {
        int ci = t >> 8, co = t & 255;
        float v = attn_W[co * CDIM + ci];
        __nv_bfloat16 h = __float2bfloat16(v);
        g_Wthi[ci * CDIM + co] = h;
        g_Wtlo[ci * CDIM + co] = __float2bfloat16(v - __bfloat162float(h));
    }
    if (t < FDIM * CDIM) {
        int f = t >> 8, ci = t & 255;
        g_emb_Wt[ci * FDIM + f] = emb_W[f * CDIM + ci];
    }
}

// ---------------- emb: x @ emb_W^T + b -> bf16 hi/lo (+transposed) + sq + x-split ----------------
#define EMB_SMEM ((32 * 256 + 256 * 64) * 4)
__global__ __launch_bounds__(256) void emb_kernel(const float* __restrict__ x,
                                                  const float* __restrict__ emb_b) {
    extern __shared__ float sm[];
    float* xs = sm;              // [32][256]
    float* we = sm + 32 * 256;   // [256][64]
    int tid = threadIdx.x;
    int row0 = blockIdx.x * 32;
    int bb = row0 >> 10, n0 = row0 & 1023;

    const float4* xg = (const float4*)(x + (size_t)row0 * CDIM);
    float4* xs4 = (float4*)xs;
    for (int i = tid; i < 32 * 64; i += 256) xs4[i] = xg[i];
    const float4* wg = (const float4*)g_emb_Wt;
    float4* we4 = (float4*)we;
    for (int i = tid; i < 256 * 16; i += 256) we4[i] = wg[i];
    __syncthreads();

    // fused x -> bf16 hi/lo split
    for (int i = tid; i < 2048; i += 256) {
        float4 v = xs4[i];
        float vv[4] = {v.x, v.y, v.z, v.w};
        BPack4 ph, pl;
#pragma unroll
        for (int q = 0; q < 4; q++) {
            __nv_bfloat16 h = __float2bfloat16(vv[q]);
            ph.h[q] = h;
            pl.h[q] = __float2bfloat16(vv[q] - __bfloat162float(h));
        }
        ((uint2*)g_xhi)[(size_t)row0 * 64 + i] = ph.u;
        ((uint2*)g_xlo)[(size_t)row0 * 64 + i] = pl.u;
    }

    int w = tid >> 5, lane = tid & 31;
    int ig = w * 4, fg = lane * 2;
    float acc[4][2] = {};
#pragma unroll 4
    for (int c = 0; c < 256; c++) {
        float2 wv = *(const float2*)&we[c * 64 + fg];
#pragma unroll
        for (int q = 0; q < 4; q++) {
            float a = xs[(ig + q) * 256 + c];
            acc[q][0] = fmaf(a, wv.x, acc[q][0]);
            acc[q][1] = fmaf(a, wv.y, acc[q][1]);
        }
    }
    float b0 = emb_b[fg], b1 = emb_b[fg + 1];
    float e0r[4], e1r[4];
#pragma unroll
    for (int q = 0; q < 4; q++) {
        float e0 = acc[q][0] + b0, e1 = acc[q][1] + b1;
        e0r[q] = e0; e1r[q] = e1;
        int n = row0 + ig + q;
        BPack2 ph, pl;
        ph.h[0] = __float2bfloat16(e0);
        ph.h[1] = __float2bfloat16(e1);
        pl.h[0] = __float2bfloat16(e0 - __bfloat162float(ph.h[0]));
        pl.h[1] = __float2bfloat16(e1 - __bfloat162float(ph.h[1]));
        *(uint32_t*)&g_Ehi[(size_t)n * FDIM + fg] = ph.u;
        *(uint32_t*)&g_Elo[(size_t)n * FDIM + fg] = pl.u;
        float p = e0 * e0 + e1 * e1;
#pragma unroll
        for (int o = 16; o; o >>= 1) p += __shfl_xor_sync(0xffffffffu, p, o);
        if (lane == 0) g_sq[n] = p;
    }

    // transposed bf16 copies via smem staging: [64][33]
    __nv_bfloat16* st = (__nv_bfloat16*)sm;
    __syncthreads();
#pragma unroll
    for (int q = 0; q < 4; q++) {
        st[fg * 33 + ig + q] = __float2bfloat16(e0r[q]);
        st[(fg + 1) * 33 + ig + q] = __float2bfloat16(e1r[q]);
    }
    __syncthreads();
    for (int idx = tid; idx < 2048; idx += 256) {
        int k = idx >> 5, i2 = idx & 31;
        g_EhiT[(((size_t)bb * 64 + k) << 10) + n0 + i2] = st[k * 33 + i2];
    }
    __syncthreads();
#pragma unroll
    for (int q = 0; q < 4; q++) {
        float h0 = __bfloat162float(__float2bfloat16(e0r[q]));
        float h1 = __bfloat162float(__float2bfloat16(e1r[q]));
        st[fg * 33 + ig + q] = __float2bfloat16(e0r[q] - h0);
        st[(fg + 1) * 33 + ig + q] = __float2bfloat16(e1r[q] - h1);
    }
    __syncthreads();
    for (int idx = tid; idx < 2048; idx += 256) {
        int k = idx >> 5, i2 = idx & 31;
        g_EloT[(((size_t)bb * 64 + k) << 10) + n0 + i2] = st[k * 33 + i2];
    }
}

// ---------------- shortcut: SC = x @ W^T + b (3-term), plus T — 3-stage ring ----------------
// epilogue emits fp16 hi/lo SC (for the fp16 bmm)
#define SC_OFF_A 0
#define SC_OFF_B 15360
#define SC_OFF_T 66048
#define SC_SMEM  66304
__global__ __launch_bounds__(256) void shortcut_kernel(const float* __restrict__ attn_b,
                                                       const float* __restrict__ thr_W,
                                                       const float* __restrict__ thr_b) {
    extern __shared__ char smc[];
    __nv_bfloat16* Asp = (__nv_bfloat16*)(smc + SC_OFF_A);   // [3][64][40]
    __nv_bfloat16* Bsp = (__nv_bfloat16*)(smc + SC_OFF_B);   // [3][32][264]
    float* Tp = (float*)(smc + SC_OFF_T);
    int tid = threadIdx.x, w = tid >> 5, lane = tid & 31;
    int m0 = blockIdx.x * 64;
    int lrow = lane & 7, q1 = (lane >> 3) & 1, q2 = lane >> 4;

    if (tid < 64) Tp[tid] = 0.0f;

    float acc[4][4][4];
#pragma unroll
    for (int a = 0; a < 4; a++)
#pragma unroll
        for (int n = 0; n < 4; n++)
#pragma unroll
            for (int r = 0; r < 4; r++) acc[a][n][r] = 0.0f;

#define SC_ISSUE(s, bf_)                                                          \
    {                                                                             \
        int term_ = (s) >> 3, kc_ = (s) & 7;                                      \
        const __nv_bfloat16* Ap_ = (term_ == 1) ? g_xlo : g_xhi;                  \
        const __nv_bfloat16* Bp_ = (term_ == 2) ? g_Wtlo : g_Wthi;                \
        int ar_ = tid >> 2, aseg_ = tid & 3;                                      \
        cp16(smem_u32(&Asp[(bf_) * 2560 + ar_ * 40 + aseg_ * 8]),                 \
             Ap_ + (size_t)(m0 + ar_) * CDIM + kc_ * 32 + aseg_ * 8);             \
        for (int u_ = 0; u_ < 4; u_++) {                                          \
            int id_ = tid + u_ * 256;                                             \
            int br_ = id_ >> 5, bseg_ = id_ & 31;                                 \
            cp16(smem_u32(&Bsp[(bf_) * 8448 + br_ * 264 + bseg_ * 8]),            \
                 Bp_ + (size_t)(kc_ * 32 + br_) * CDIM + bseg_ * 8);              \
        }                                                                         \
        cp_commit();                                                              \
    }

    SC_ISSUE(0, 0);
    SC_ISSUE(1, 1);
    for (int s = 0; s < 24; s++) {
        if (s < 23) cp_wait1(); else cp_wait0();
        __syncthreads();
        int buf = s % 3;
#pragma unroll
        for (int kk = 0; kk < 2; kk++) {
            uint32_t af[4][4];
#pragma unroll
            for (int mt = 0; mt < 4; mt++)
                ldm_x4(af[mt], smem_u32(&Asp[buf * 2560 + (mt * 16 + lrow + q1 * 8) * 40 + kk * 16 + q2 * 8]));
            uint32_t bfr[2][4];
#pragma unroll
            for (int ng = 0; ng < 2; ng++)
                ldm_x4_t(bfr[ng], smem_u32(&Bsp[buf * 8448 + (kk * 16 + lrow + q1 * 8) * 264 + w * 32 + ng * 16 + q2 * 8]));
#pragma unroll
            for (int mt = 0; mt < 4; mt++)
#pragma unroll
                for (int nt = 0; nt < 4; nt++)
                    mma16816(acc[mt][nt], af[mt],
                             bfr[nt >> 1][(nt & 1) * 2], bfr[nt >> 1][(nt & 1) * 2 + 1]);
        }
        if (s + 2 < 24) SC_ISSUE(s + 2, (s + 2) % 3);
    }
#undef SC_ISSUE

    // epilogue: bias, fp16 hi/lo stores, T partials
    float pr0[4] = {}, pr1[4] = {};
#pragma unroll
    for (int nt = 0; nt < 4; nt++) {
        int c0 = w * 32 + nt * 8 + (lane & 3) * 2;
        float bb0 = attn_b[c0], bb1 = attn_b[c0 + 1];
        float tw0 = thr_W[c0], tw1 = thr_W[c0 + 1];
#pragma unroll
        for (int mt = 0; mt < 4; mt++) {
            int r0g = m0 + mt * 16 + (lane >> 2);
            float v00 = acc[mt][nt][0] + bb0, v01 = acc[mt][nt][1] + bb1;
            float v10 = acc[mt][nt][2] + bb0, v11 = acc[mt][nt][3] + bb1;
            HPack2 h, l;
            h.h[0] = __float2half_rn(v00); h.h[1] = __float2half_rn(v01);
            l.h[0] = __float2half_rn(v00 - __half2float(h.h[0]));
            l.h[1] = __float2half_rn(v01 - __half2float(h.h[1]));
            *(uint32_t*)&g_SChi[(size_t)r0g * CDIM + c0] = h.u;
            *(uint32_t*)&g_SClo[(size_t)r0g * CDIM + c0] = l.u;
            h.h[0] = __float2half_rn(v10); h.h[1] = __float2half_rn(v11);
            l.h[0] = __float2half_rn(v10 - __half2float(h.h[0]));
            l.h[1] = __float2half_rn(v11 - __half2float(h.h[1]));
            *(uint32_t*)&g_SChi[(size_t)(r0g + 8) * CDIM + c0] = h.u;
            *(uint32_t*)&g_SClo[(size_t)(r0g + 8) * CDIM + c0] = l.u;
            pr0[mt] += v00 * tw0 + v01 * tw1;
            pr1[mt] += v10 * tw0 + v11 * tw1;
        }
    }
#pragma unroll
    for (int mt = 0; mt < 4; mt++) {
        pr0[mt] += __shfl_xor_sync(0xffffffffu, pr0[mt], 1);
        pr0[mt] += __shfl_xor_sync(0xffffffffu, pr0[mt], 2);
        pr1[mt] += __shfl_xor_sync(0xffffffffu, pr1[mt], 1);
        pr1[mt] += __shfl_xor_sync(0xffffffffu, pr1[mt], 2);
        if ((lane & 3) == 0) {
            atomicAdd(&Tp[mt * 16 + (lane >> 2)], pr0[mt]);
            atomicAdd(&Tp[mt * 16 + (lane >> 2) + 8], pr1[mt]);
        }
    }
    __syncthreads();
    if (tid < 64) g_T[m0 + tid] = Tp[tid] + thr_b[0];
}

// ---------------- attention matrix kernel: 32 rows, 1024 threads / 32 warps ----------------
#define S_PITCH 1044
#define OFF_S    0
#define OFF_EIH  133632
#define OFF_EIL  138240
#define OFF_BH   142848
#define OFF_BL   177664
#define OFF_TSH  212480
#define OFF_SQJ  216576
#define ATTN_SMEM 220672

__global__ __launch_bounds__(1024) void attn_A_kernel() {
    extern __shared__ char smc[];
    float* S = (float*)(smc + OFF_S);                         // [32][1044]
    __nv_bfloat16* Eih = (__nv_bfloat16*)(smc + OFF_EIH);     // [32][72]
    __nv_bfloat16* Eil = (__nv_bfloat16*)(smc + OFF_EIL);
    __nv_bfloat16* BhS = (__nv_bfloat16*)(smc + OFF_BH);      // [2][64][136]
    __nv_bfloat16* BlS = (__nv_bfloat16*)(smc + OFF_BL);
    float* Tsh = (float*)(smc + OFF_TSH);
    float* Sqj = (float*)(smc + OFF_SQJ);

    int tid = threadIdx.x;
    int tile = blockIdx.x, b = blockIdx.y;
    int i0 = tile * 32;
    int base = b * HW;
    int w = tid >> 5, lane = tid & 31;
    int lrow = lane & 7, q1 = (lane >> 3) & 1, q2 = lane >> 4;
    int mt = w & 1, ncol = w >> 1;         // 32 warps: 2 row-halves x 16 col-tiles of 8

    for (int i = tid; i < 1024; i += 1024) {
        Tsh[i] = g_T[base + i];
        Sqj[i] = g_sq[base + i];
    }

#define AT_ISSUE(jc, buf)                                                         \
    {                                                                             \
        for (int u_ = 0; u_ < 2; u_++) {                                          \
            int id_ = tid + u_ * 1024;                                            \
            int arr_ = id_ >> 10, rem_ = id_ & 1023;                              \
            int r_ = rem_ >> 4, seg_ = rem_ & 15;                                 \
            __nv_bfloat16* dst_ = (arr_ ? BlS : BhS) + (buf) * 8704 + r_ * 136 + seg_ * 8; \
            const __nv_bfloat16* src_ = (arr_ ? g_EloT : g_EhiT) +                \
                (((size_t)b * 64 + r_) << 10) + (jc) * 128 + seg_ * 8;            \
            cp16(smem_u32(dst_), src_);                                           \
        }                                                                         \
        cp_commit();                                                              \
    }

    // prologue: Ei hi/lo joins group 0
    if (tid < 512) {
        int arr = tid >> 8, rem = tid & 255;
        int r = rem >> 3, seg = rem & 7;
        __nv_bfloat16* dst = (arr ? Eil : Eih) + r * 72 + seg * 8;
        const __nv_bfloat16* src = (arr ? g_Elo : g_Ehi) + (size_t)(base + i0 + r) * 64 + seg * 8;
        cp16(smem_u32(dst), src);
    }
    AT_ISSUE(0, 0);
    AT_ISSUE(1, 1);
    cp_wait1();
    __syncthreads();

    // hoisted A fragments (each warp: its 16-row half, all k)
    uint32_t Ah[4][4], Al[4][4];
#pragma unroll
    for (int kc = 0; kc < 4; kc++) {
        ldm_x4(Ah[kc], smem_u32(&Eih[(mt * 16 + lrow + q1 * 8) * 72 + kc * 16 + q2 * 8]));
        ldm_x4(Al[kc], smem_u32(&Eil[(mt * 16 + lrow + q1 * 8) * 72 + kc * 16 + q2 * 8]));
    }

    // per-lane row constants
    int r0 = mt * 16 + (lane >> 2);
    int ig0 = i0 + r0, ig1 = ig0 + 8;
    int yi0 = ig0 >> 5, xi0 = ig0 & 31;
    int yi1 = ig1 >> 5, xi1 = ig1 & 31;
    float sqi0 = g_sq[base + ig0];
    float sqi1 = g_sq[base + ig1];
    // B ldmatrix.x2 source row offset (lanes 0-15 supply addresses)
    int brow = (lane & 7) + ((lane >> 3) & 1) * 8;

    // ---- Phase A ----
    for (int jc = 0; jc < 8; jc++) {
        if (jc >= 1) {
            if (jc < 7) cp_wait1(); else cp_wait0();
            __syncthreads();
        }
        int buf = jc & 1;
        float acc[4] = {};
#pragma unroll
        for (int kc = 0; kc < 4; kc++) {
            uint32_t bh[2], bl[2];
            ldm_x2_t(bh, smem_u32(&BhS[buf * 8704 + (kc * 16 + brow) * 136 + ncol * 8]));
            ldm_x2_t(bl, smem_u32(&BlS[buf * 8704 + (kc * 16 + brow) * 136 + ncol * 8]));
            mma16816(acc, Ah[kc], bh[0], bh[1]);
            mma16816(acc, Al[kc], bh[0], bh[1]);
            mma16816(acc, Ah[kc], bl[0], bl[1]);
        }
        int j0 = jc * 128 + ncol * 8 + (lane & 3) * 2;
        int yj0 = j0 >> 5, xj0 = j0 & 31;
        int yj1 = (j0 + 1) >> 5, xj1 = (j0 + 1) & 31;
        float sq0 = Sqj[j0], sq1 = Sqj[j0 + 1];
        {
            float d2a = fmaxf(sqi0 + sq0 - 2.0f * acc[0], 0.0f);
            float d2b = fmaxf(sqi0 + sq1 - 2.0f * acc[1], 0.0f);
            int da = abs(yi0 - yj0) + abs(xi0 - xj0);
            int db = abs(yi0 - yj1) + abs(xi0 - xj1);
            float ma = (da <= 32) ? (float)da * (1.0f / 32.0f) : 0.0f;
            float mb = (db <= 32) ? (float)db * (1.0f / 32.0f) : 0.0f;
            *(float2*)&S[r0 * S_PITCH + j0] =
                make_float2(__expf(-d2a) - 1.0f + ma, __expf(-d2b) - 1.0f + mb);
        }
        {
            float d2a = fmaxf(sqi1 + sq0 - 2.0f * acc[2], 0.0f);
            float d2b = fmaxf(sqi1 + sq1 - 2.0f * acc[3], 0.0f);
            int da = abs(yi1 - yj0) + abs(xi1 - xj0);
            int db = abs(yi1 - yj1) + abs(xi1 - xj1);
            float ma = (da <= 32) ? (float)da * (1.0f / 32.0f) : 0.0f;
            float mb = (db <= 32) ? (float)db * (1.0f / 32.0f) : 0.0f;
            *(float2*)&S[(r0 + 8) * S_PITCH + j0] =
                make_float2(__expf(-d2a) - 1.0f + ma, __expf(-d2b) - 1.0f + mb);
        }
        __syncthreads();
        if (jc < 6) AT_ISSUE(jc + 2, jc & 1);
    }
#undef AT_ISSUE

    // ---- Phase B: register softmax, 1 row per warp, single fp16 A store ----
    {
        int r = w;
        float* Sr = S + r * S_PITCH;
        float v[32];
#pragma unroll
        for (int t = 0; t < 32; t++) v[t] = Sr[lane + t * 32];
        float m = -1e30f;
#pragma unroll
        for (int t = 0; t < 32; t++) m = fmaxf(m, v[t]);
#pragma unroll
        for (int o = 16; o; o >>= 1) m = fmaxf(m, __shfl_xor_sync(0xffffffffu, m, o));
        float s1 = 0.0f;
#pragma unroll
        for (int t = 0; t < 32; t++) { v[t] = __expf(v[t] - m); s1 += v[t]; }
#pragma unroll
        for (int o = 16; o; o >>= 1) s1 += __shfl_xor_sync(0xffffffffu, s1, o);
        float inv1 = 1.0f / s1;
        float m2 = 0.0f;
#pragma unroll
        for (int t = 0; t < 32; t++) {
            v[t] = fmaxf(v[t] * inv1 - Tsh[lane + t * 32], 0.0f);
            m2 = fmaxf(m2, v[t]);
        }
#pragma unroll
        for (int o = 16; o; o >>= 1) m2 = fmaxf(m2, __shfl_xor_sync(0xffffffffu, m2, o));
        float s2 = 0.0f;
#pragma unroll
        for (int t = 0; t < 32; t++) { v[t] = __expf(v[t] - m2); s2 += v[t]; }
#pragma unroll
        for (int o = 16; o; o >>= 1) s2 += __shfl_xor_sync(0xffffffffu, s2, o);
        float inv2 = 1.0f / s2;

        // repack fp16 into this (now-dead) S row, then coalesced copy out
        __half* rowh = (__half*)Sr;
#pragma unroll
        for (int t = 0; t < 32; t++) {
            rowh[lane + t * 32] = __float2half_rn(v[t] * inv2);
        }
        __syncwarp();
        size_t Ab = ((size_t)b << 20) + ((size_t)(i0 + r) << 10);
        uint4* gh = (uint4*)&g_Af[Ab];
        const uint4* sh = (const uint4*)rowh;
#pragma unroll
        for (int it = 0; it < 4; it++) gh[lane + it * 32] = sh[lane + it * 32];
    }
}

// ---------------- fp16 tensor-core bmm: out = x + A @ SC (2-term: Af*Shi + Af*Slo) ----------------
#define BMM_OFF_AF 0
#define BMM_OFF_SH 20480
#define BMM_OFF_SL 37888
#define BMM_SMEM   55296
__global__ __launch_bounds__(256, 2) void bmm_kernel(const float* __restrict__ x,
                                                     float* __restrict__ out) {
    extern __shared__ char smc[];
    __half* Af_s = (__half*)(smc + BMM_OFF_AF);  // [2][128][40]
    __half* Sh_s = (__half*)(smc + BMM_OFF_SH);  // [2][32][136]
    __half* Sl_s = (__half*)(smc + BMM_OFF_SL);  // [2][32][136]
    int tid = threadIdx.x, w = tid >> 5, lane = tid & 31;
    int ct = blockIdx.x, mtb = blockIdx.y, b = blockIdx.z;
    int i0 = mtb * 128, c0 = ct * 128;

    const __half* Af = g_Af + ((size_t)b << 20) + (size_t)i0 * 1024;
    const __half* Shi = g_SChi + ((size_t)b << 18) + c0;
    const __half* Slo = g_SClo + ((size_t)b << 18) + c0;

    float acc[4][4][4];
#pragma unroll
    for (int a = 0; a < 4; a++)
#pragma unroll
        for (int n = 0; n < 4; n++)
#pragma unroll
            for (int r = 0; r < 4; r++) acc[a][n][r] = 0.0f;

    int wm = w >> 2, wn = w & 3;
    int lrow = lane & 7, q1 = (lane >> 3) & 1, q2 = lane >> 4;

#define ISSUE(jc, bf_)                                                            \
    {                                                                             \
        for (int u_ = 0; u_ < 2; u_++) {                                          \
            int id_ = tid + u_ * 256;                                             \
            int ar_ = id_ >> 2, aseg_ = id_ & 3;                                  \
            cp16(smem_u32(&Af_s[(bf_) * 5120 + ar_ * 40 + aseg_ * 8]),            \
                 Af + (size_t)ar_ * 1024 + (jc) * 32 + aseg_ * 8);                \
            int sr_ = id_ >> 4, sseg_ = id_ & 15;                                 \
            cp16(smem_u32(&Sh_s[(bf_) * 4352 + sr_ * 136 + sseg_ * 8]),           \
                 Shi + (size_t)((jc) * 32 + sr_) * 256 + sseg_ * 8);              \
            cp16(smem_u32(&Sl_s[(bf_) * 4352 + sr_ * 136 + sseg_ * 8]),           \
                 Slo + (size_t)((jc) * 32 + sr_) * 256 + sseg_ * 8);              \
        }                                                                         \
        cp_commit();                                                              \
    }

    ISSUE(0, 0);
    ISSUE(1, 1);
    for (int cc = 0; cc < 32; cc++) {
        if (cc < 31) cp_wait1(); else cp_wait0();
        __syncthreads();
        int buf = cc & 1;
#pragma unroll
        for (int kk = 0; kk < 2; kk++) {
            uint32_t af[4][4];
#pragma unroll
            for (int mtl = 0; mtl < 4; mtl++) {
                int row = wm * 64 + mtl * 16 + lrow + q1 * 8;
                int col = kk * 16 + q2 * 8;
                ldm_x4(af[mtl], smem_u32(&Af_s[buf * 5120 + row * 40 + col]));
            }
            uint32_t bh[2][4], bl[2][4];
#pragma unroll
            for (int ng = 0; ng < 2; ng++) {
                int row = kk * 16 + lrow + q1 * 8;
                int col = wn * 32 + ng * 16 + q2 * 8;
                ldm_x4_t(bh[ng], smem_u32(&Sh_s[buf * 4352 + row * 136 + col]));
                ldm_x4_t(bl[ng], smem_u32(&Sl_s[buf * 4352 + row * 136 + col]));
            }
#pragma unroll
            for (int mtl = 0; mtl < 4; mtl++)
#pragma unroll
                for (int nt = 0; nt < 4; nt++) {
                    uint32_t h0 = bh[nt >> 1][(nt & 1) * 2], h1 = bh[nt >> 1][(nt & 1) * 2 + 1];
                    uint32_t l0 = bl[nt >> 1][(nt & 1) * 2], l1 = bl[nt >> 1][(nt & 1) * 2 + 1];
                    mma16816h(acc[mtl][nt], af[mtl], h0, h1);
                    mma16816h(acc[mtl][nt], af[mtl], l0, l1);
                }
        }
        __syncthreads();   // all warps done with buf before it is overwritten
        if (cc + 2 < 32) ISSUE(cc + 2, cc & 1);
    }
#undef ISSUE

    int g = lane >> 2, t2 = lane & 3;
#pragma unroll
    for (int mtl = 0; mtl < 4; mtl++) {
#pragma unroll
        for (int nt = 0; nt < 4; nt++) {
            int row = i0 + wm * 64 + mtl * 16 + g;
            int col = c0 + wn * 32 + nt * 8 + 2 * t2;
            size_t o0 = ((size_t)b * 1024 + row) * 256 + col;
            size_t o1 = o0 + 8 * 256;
            float2 xv0 = *(const float2*)&x[o0];
            float2 xv1 = *(const float2*)&x[o1];
            *(float2*)&out[o0] = make_float2(xv0.x + acc[mtl][nt][0], xv0.y + acc[mtl][nt][1]);
            *(float2*)&out[o1] = make_float2(xv1.x + acc[mtl][nt][2], xv1.y + acc[mtl][nt][3]);
        }
    }
}

// ---------------- launch ----------------
extern "C" void kernel_launch(void* const* d_in, const int* in_sizes, int n_in,
                              void* d_out, int out_size) {
    const float* x      = (const float*)d_in[0];
    const float* emb_W  = (const float*)d_in[1];
    const float* emb_b  = (const float*)d_in[2];
    const float* attn_W = (const float*)d_in[3];
    const float* attn_b = (const float*)d_in[4];
    const float* thr_W  = (const float*)d_in[5];
    const float* thr_b  = (const float*)d_in[6];
    float* out = (float*)d_out;

    cudaFuncSetAttribute(emb_kernel, cudaFuncAttributeMaxDynamicSharedMemorySize, EMB_SMEM);
    cudaFuncSetAttribute(shortcut_kernel, cudaFuncAttributeMaxDynamicSharedMemorySize, SC_SMEM);
    cudaFuncSetAttribute(attn_A_kernel, cudaFuncAttributeMaxDynamicSharedMemorySize, ATTN_SMEM);
    cudaFuncSetAttribute(bmm_kernel, cudaFuncAttributeMaxDynamicSharedMemorySize, BMM_SMEM);

    prep_kernel<<<256, 256>>>(attn_W, emb_W);
    emb_kernel<<<BATCH * HW / 32, 256, EMB_SMEM>>>(x, emb_b);
    shortcut_kernel<<<BATCH * HW / 64, 256, SC_SMEM>>>(attn_b, thr_W, thr_b);
    attn_A_kernel<<<dim3(HW / 32, BATCH), 1024, ATTN_SMEM>>>();
    bmm_kernel<<<dim3(CDIM / 128, HW / 128, BATCH), 256, BMM_SMEM>>>(x, out);
}

// round 11
// speedup vs baseline: 1.6274x; 1.1610x over previous
#include <cuda_runtime.h>
#include <cuda_bf16.h>
#include <cuda_fp16.h>
#include <math.h>
#include <stdint.h>

#define BATCH 32
#define HW    1024
#define CDIM  256
#define FDIM  64

// ---------------- scratch (device globals; no allocations) ----------------
__device__ float g_sq[BATCH * HW];
__device__ float g_T[BATCH * HW];
__device__ __nv_bfloat16 g_Ehi[BATCH * HW * FDIM];       // [n][k]
__device__ __nv_bfloat16 g_Elo[BATCH * HW * FDIM];
__device__ __nv_bfloat16 g_EhiT[BATCH * FDIM * HW];      // [b][k][n]
__device__ __nv_bfloat16 g_EloT[BATCH * FDIM * HW];
__device__ __nv_bfloat16 g_xhi[BATCH * HW * CDIM];
__device__ __nv_bfloat16 g_xlo[BATCH * HW * CDIM];
__device__ __half g_SChf[BATCH * HW * CDIM];             // single fp16 SC
__device__ __half g_Af[(size_t)BATCH * HW * HW];         // 64 MB, single fp16 A
__device__ __nv_bfloat16 g_Wthi[CDIM * CDIM];            // attn_W^T split [cin][cout]
__device__ __nv_bfloat16 g_Wtlo[CDIM * CDIM];
__device__ float g_emb_Wt[CDIM * FDIM];

// ---------------- small helpers ----------------
__device__ __forceinline__ uint32_t smem_u32(const void* p) {
    return (uint32_t)__cvta_generic_to_shared(p);
}
__device__ __forceinline__ void cp16(uint32_t dst, const void* src) {
    asm volatile("cp.async.cg.shared.global [%0], [%1], 16;\n" :: "r"(dst), "l"(src));
}
__device__ __forceinline__ void cp_commit() { asm volatile("cp.async.commit_group;\n"); }
__device__ __forceinline__ void cp_wait1() { asm volatile("cp.async.wait_group 1;\n"); }
__device__ __forceinline__ void cp_wait0() { asm volatile("cp.async.wait_group 0;\n"); }
__device__ __forceinline__ void ldm_x4(uint32_t (&r)[4], uint32_t addr) {
    asm volatile("ldmatrix.sync.aligned.m8n8.x4.shared.b16 {%0,%1,%2,%3}, [%4];"
                 : "=r"(r[0]), "=r"(r[1]), "=r"(r[2]), "=r"(r[3]) : "r"(addr));
}
__device__ __forceinline__ void ldm_x4_t(uint32_t (&r)[4], uint32_t addr) {
    asm volatile("ldmatrix.sync.aligned.m8n8.x4.trans.shared.b16 {%0,%1,%2,%3}, [%4];"
                 : "=r"(r[0]), "=r"(r[1]), "=r"(r[2]), "=r"(r[3]) : "r"(addr));
}
__device__ __forceinline__ void ldm_x2_t(uint32_t (&r)[2], uint32_t addr) {
    asm volatile("ldmatrix.sync.aligned.m8n8.x2.trans.shared.b16 {%0,%1}, [%2];"
                 : "=r"(r[0]), "=r"(r[1]) : "r"(addr));
}
// bf16 mma (Gram / shortcut path)
__device__ __forceinline__ void mma16816(float (&d)[4], const uint32_t (&a)[4],
                                         uint32_t b0, uint32_t b1) {
    asm volatile("mma.sync.aligned.m16n8k16.row.col.f32.bf16.bf16.f32 "
                 "{%0,%1,%2,%3}, {%4,%5,%6,%7}, {%8,%9}, {%0,%1,%2,%3};"
                 : "+f"(d[0]), "+f"(d[1]), "+f"(d[2]), "+f"(d[3])
                 : "r"(a[0]), "r"(a[1]), "r"(a[2]), "r"(a[3]), "r"(b0), "r"(b1));
}
// fp16 mma (bmm path)
__device__ __forceinline__ void mma16816h(float (&d)[4], const uint32_t (&a)[4],
                                          uint32_t b0, uint32_t b1) {
    asm volatile("mma.sync.aligned.m16n8k16.row.col.f32.f16.f16.f32 "
                 "{%0,%1,%2,%3}, {%4,%5,%6,%7}, {%8,%9}, {%0,%1,%2,%3};"
                 : "+f"(d[0]), "+f"(d[1]), "+f"(d[2]), "+f"(d[3])
                 : "r"(a[0]), "r"(a[1]), "r"(a[2]), "r"(a[3]), "r"(b0), "r"(b1));
}
union BPack2 { __nv_bfloat16 h[2]; uint32_t u; };
union BPack4 { __nv_bfloat16 h[4]; uint2 u; };
union HPack2 { __half h[2]; uint32_t u; };

// ---------------- prep: weight transposes + bf16 splits ----------------
__global__ void prep_kernel(const float* __restrict__ attn_W,
                            const float* __restrict__ emb_W) {
    int t = blockIdx.x * 256 + threadIdx.x;
    if (t < CDIM * CDIM) {
        int ci = t >> 8, co = t & 255;
        float v = attn_W[co * CDIM + ci];
        __nv_bfloat16 h = __float2bfloat16(v);
        g_Wthi[ci * CDIM + co] = h;
        g_Wtlo[ci * CDIM + co] = __float2bfloat16(v - __bfloat162float(h));
    }
    if (t < FDIM * CDIM) {
        int f = t >> 8, ci = t & 255;
        g_emb_Wt[ci * FDIM + f] = emb_W[f * CDIM + ci];
    }
}

// ---------------- emb: x @ emb_W^T + b -> bf16 hi/lo (+transposed) + sq + x-split ----------------
#define EMB_SMEM ((32 * 256 + 256 * 64) * 4)
__global__ __launch_bounds__(256) void emb_kernel(const float* __restrict__ x,
                                                  const float* __restrict__ emb_b) {
    extern __shared__ float sm[];
    float* xs = sm;              // [32][256]
    float* we = sm + 32 * 256;   // [256][64]
    int tid = threadIdx.x;
    int row0 = blockIdx.x * 32;
    int bb = row0 >> 10, n0 = row0 & 1023;

    const float4* xg = (const float4*)(x + (size_t)row0 * CDIM);
    float4* xs4 = (float4*)xs;
    for (int i = tid; i < 32 * 64; i += 256) xs4[i] = xg[i];
    const float4* wg = (const float4*)g_emb_Wt;
    float4* we4 = (float4*)we;
    for (int i = tid; i < 256 * 16; i += 256) we4[i] = wg[i];
    __syncthreads();

    // fused x -> bf16 hi/lo split
    for (int i = tid; i < 2048; i += 256) {
        float4 v = xs4[i];
        float vv[4] = {v.x, v.y, v.z, v.w};
        BPack4 ph, pl;
#pragma unroll
        for (int q = 0; q < 4; q++) {
            __nv_bfloat16 h = __float2bfloat16(vv[q]);
            ph.h[q] = h;
            pl.h[q] = __float2bfloat16(vv[q] - __bfloat162float(h));
        }
        ((uint2*)g_xhi)[(size_t)row0 * 64 + i] = ph.u;
        ((uint2*)g_xlo)[(size_t)row0 * 64 + i] = pl.u;
    }

    int w = tid >> 5, lane = tid & 31;
    int ig = w * 4, fg = lane * 2;
    float acc[4][2] = {};
#pragma unroll 4
    for (int c = 0; c < 256; c++) {
        float2 wv = *(const float2*)&we[c * 64 + fg];
#pragma unroll
        for (int q = 0; q < 4; q++) {
            float a = xs[(ig + q) * 256 + c];
            acc[q][0] = fmaf(a, wv.x, acc[q][0]);
            acc[q][1] = fmaf(a, wv.y, acc[q][1]);
        }
    }
    float b0 = emb_b[fg], b1 = emb_b[fg + 1];
    float e0r[4], e1r[4];
#pragma unroll
    for (int q = 0; q < 4; q++) {
        float e0 = acc[q][0] + b0, e1 = acc[q][1] + b1;
        e0r[q] = e0; e1r[q] = e1;
        int n = row0 + ig + q;
        BPack2 ph, pl;
        ph.h[0] = __float2bfloat16(e0);
        ph.h[1] = __float2bfloat16(e1);
        pl.h[0] = __float2bfloat16(e0 - __bfloat162float(ph.h[0]));
        pl.h[1] = __float2bfloat16(e1 - __bfloat162float(ph.h[1]));
        *(uint32_t*)&g_Ehi[(size_t)n * FDIM + fg] = ph.u;
        *(uint32_t*)&g_Elo[(size_t)n * FDIM + fg] = pl.u;
        float p = e0 * e0 + e1 * e1;
#pragma unroll
        for (int o = 16; o; o >>= 1) p += __shfl_xor_sync(0xffffffffu, p, o);
        if (lane == 0) g_sq[n] = p;
    }

    // transposed bf16 copies via smem staging: [64][33]
    __nv_bfloat16* st = (__nv_bfloat16*)sm;
    __syncthreads();
#pragma unroll
    for (int q = 0; q < 4; q++) {
        st[fg * 33 + ig + q] = __float2bfloat16(e0r[q]);
        st[(fg + 1) * 33 + ig + q] = __float2bfloat16(e1r[q]);
    }
    __syncthreads();
    for (int idx = tid; idx < 2048; idx += 256) {
        int k = idx >> 5, i2 = idx & 31;
        g_EhiT[(((size_t)bb * 64 + k) << 10) + n0 + i2] = st[k * 33 + i2];
    }
    __syncthreads();
#pragma unroll
    for (int q = 0; q < 4; q++) {
        float h0 = __bfloat162float(__float2bfloat16(e0r[q]));
        float h1 = __bfloat162float(__float2bfloat16(e1r[q]));
        st[fg * 33 + ig + q] = __float2bfloat16(e0r[q] - h0);
        st[(fg + 1) * 33 + ig + q] = __float2bfloat16(e1r[q] - h1);
    }
    __syncthreads();
    for (int idx = tid; idx < 2048; idx += 256) {
        int k = idx >> 5, i2 = idx & 31;
        g_EloT[(((size_t)bb * 64 + k) << 10) + n0 + i2] = st[k * 33 + i2];
    }
}

// ---------------- shortcut: SC = x @ W^T + b (3-term), plus T — 3-stage ring ----------------
// epilogue emits single fp16 SC
#define SC_OFF_A 0
#define SC_OFF_B 15360
#define SC_OFF_T 66048
#define SC_SMEM  66304
__global__ __launch_bounds__(256) void shortcut_kernel(const float* __restrict__ attn_b,
                                                       const float* __restrict__ thr_W,
                                                       const float* __restrict__ thr_b) {
    extern __shared__ char smc[];
    __nv_bfloat16* Asp = (__nv_bfloat16*)(smc + SC_OFF_A);   // [3][64][40]
    __nv_bfloat16* Bsp = (__nv_bfloat16*)(smc + SC_OFF_B);   // [3][32][264]
    float* Tp = (float*)(smc + SC_OFF_T);
    int tid = threadIdx.x, w = tid >> 5, lane = tid & 31;
    int m0 = blockIdx.x * 64;
    int lrow = lane & 7, q1 = (lane >> 3) & 1, q2 = lane >> 4;

    if (tid < 64) Tp[tid] = 0.0f;

    float acc[4][4][4];
#pragma unroll
    for (int a = 0; a < 4; a++)
#pragma unroll
        for (int n = 0; n < 4; n++)
#pragma unroll
            for (int r = 0; r < 4; r++) acc[a][n][r] = 0.0f;

#define SC_ISSUE(s, bf_)                                                          \
    {                                                                             \
        int term_ = (s) >> 3, kc_ = (s) & 7;                                      \
        const __nv_bfloat16* Ap_ = (term_ == 1) ? g_xlo : g_xhi;                  \
        const __nv_bfloat16* Bp_ = (term_ == 2) ? g_Wtlo : g_Wthi;                \
        int ar_ = tid >> 2, aseg_ = tid & 3;                                      \
        cp16(smem_u32(&Asp[(bf_) * 2560 + ar_ * 40 + aseg_ * 8]),                 \
             Ap_ + (size_t)(m0 + ar_) * CDIM + kc_ * 32 + aseg_ * 8);             \
        for (int u_ = 0; u_ < 4; u_++) {                                          \
            int id_ = tid + u_ * 256;                                             \
            int br_ = id_ >> 5, bseg_ = id_ & 31;                                 \
            cp16(smem_u32(&Bsp[(bf_) * 8448 + br_ * 264 + bseg_ * 8]),            \
                 Bp_ + (size_t)(kc_ * 32 + br_) * CDIM + bseg_ * 8);              \
        }                                                                         \
        cp_commit();                                                              \
    }

    SC_ISSUE(0, 0);
    SC_ISSUE(1, 1);
    for (int s = 0; s < 24; s++) {
        if (s < 23) cp_wait1(); else cp_wait0();
        __syncthreads();
        int buf = s % 3;
#pragma unroll
        for (int kk = 0; kk < 2; kk++) {
            uint32_t af[4][4];
#pragma unroll
            for (int mt = 0; mt < 4; mt++)
                ldm_x4(af[mt], smem_u32(&Asp[buf * 2560 + (mt * 16 + lrow + q1 * 8) * 40 + kk * 16 + q2 * 8]));
            uint32_t bfr[2][4];
#pragma unroll
            for (int ng = 0; ng < 2; ng++)
                ldm_x4_t(bfr[ng], smem_u32(&Bsp[buf * 8448 + (kk * 16 + lrow + q1 * 8) * 264 + w * 32 + ng * 16 + q2 * 8]));
#pragma unroll
            for (int mt = 0; mt < 4; mt++)
#pragma unroll
                for (int nt = 0; nt < 4; nt++)
                    mma16816(acc[mt][nt], af[mt],
                             bfr[nt >> 1][(nt & 1) * 2], bfr[nt >> 1][(nt & 1) * 2 + 1]);
        }
        if (s + 2 < 24) SC_ISSUE(s + 2, (s + 2) % 3);
    }
#undef SC_ISSUE

    // epilogue: bias, single fp16 stores, T partials
    float pr0[4] = {}, pr1[4] = {};
#pragma unroll
    for (int nt = 0; nt < 4; nt++) {
        int c0 = w * 32 + nt * 8 + (lane & 3) * 2;
        float bb0 = attn_b[c0], bb1 = attn_b[c0 + 1];
        float tw0 = thr_W[c0], tw1 = thr_W[c0 + 1];
#pragma unroll
        for (int mt = 0; mt < 4; mt++) {
            int r0g = m0 + mt * 16 + (lane >> 2);
            float v00 = acc[mt][nt][0] + bb0, v01 = acc[mt][nt][1] + bb1;
            float v10 = acc[mt][nt][2] + bb0, v11 = acc[mt][nt][3] + bb1;
            HPack2 h;
            h.h[0] = __float2half_rn(v00); h.h[1] = __float2half_rn(v01);
            *(uint32_t*)&g_SChf[(size_t)r0g * CDIM + c0] = h.u;
            h.h[0] = __float2half_rn(v10); h.h[1] = __float2half_rn(v11);
            *(uint32_t*)&g_SChf[(size_t)(r0g + 8) * CDIM + c0] = h.u;
            pr0[mt] += v00 * tw0 + v01 * tw1;
            pr1[mt] += v10 * tw0 + v11 * tw1;
        }
    }
#pragma unroll
    for (int mt = 0; mt < 4; mt++) {
        pr0[mt] += __shfl_xor_sync(0xffffffffu, pr0[mt], 1);
        pr0[mt] += __shfl_xor_sync(0xffffffffu, pr0[mt], 2);
        pr1[mt] += __shfl_xor_sync(0xffffffffu, pr1[mt], 1);
        pr1[mt] += __shfl_xor_sync(0xffffffffu, pr1[mt], 2);
        if ((lane & 3) == 0) {
            atomicAdd(&Tp[mt * 16 + (lane >> 2)], pr0[mt]);
            atomicAdd(&Tp[mt * 16 + (lane >> 2) + 8], pr1[mt]);
        }
    }
    __syncthreads();
    if (tid < 64) g_T[m0 + tid] = Tp[tid] + thr_b[0];
}

// ---------------- attention matrix kernel: 32 rows, 1024 threads / 32 warps ----------------
#define S_PITCH 1044
#define OFF_S    0
#define OFF_EIH  133632
#define OFF_EIL  138240
#define OFF_BH   142848
#define OFF_BL   177664
#define OFF_TSH  212480
#define OFF_SQJ  216576
#define ATTN_SMEM 220672

__global__ __launch_bounds__(1024) void attn_A_kernel() {
    extern __shared__ char smc[];
    float* S = (float*)(smc + OFF_S);                         // [32][1044]
    __nv_bfloat16* Eih = (__nv_bfloat16*)(smc + OFF_EIH);     // [32][72]
    __nv_bfloat16* Eil = (__nv_bfloat16*)(smc + OFF_EIL);
    __nv_bfloat16* BhS = (__nv_bfloat16*)(smc + OFF_BH);      // [2][64][136]
    __nv_bfloat16* BlS = (__nv_bfloat16*)(smc + OFF_BL);
    float* Tsh = (float*)(smc + OFF_TSH);
    float* Sqj = (float*)(smc + OFF_SQJ);

    int tid = threadIdx.x;
    int tile = blockIdx.x, b = blockIdx.y;
    int i0 = tile * 32;
    int base = b * HW;
    int w = tid >> 5, lane = tid & 31;
    int lrow = lane & 7, q1 = (lane >> 3) & 1, q2 = lane >> 4;
    int mt = w & 1, ncol = w >> 1;         // 32 warps: 2 row-halves x 16 col-tiles of 8

    for (int i = tid; i < 1024; i += 1024) {
        Tsh[i] = g_T[base + i];
        Sqj[i] = g_sq[base + i];
    }

#define AT_ISSUE(jc, buf)                                                         \
    {                                                                             \
        for (int u_ = 0; u_ < 2; u_++) {                                          \
            int id_ = tid + u_ * 1024;                                            \
            int arr_ = id_ >> 10, rem_ = id_ & 1023;                              \
            int r_ = rem_ >> 4, seg_ = rem_ & 15;                                 \
            __nv_bfloat16* dst_ = (arr_ ? BlS : BhS) + (buf) * 8704 + r_ * 136 + seg_ * 8; \
            const __nv_bfloat16* src_ = (arr_ ? g_EloT : g_EhiT) +                \
                (((size_t)b * 64 + r_) << 10) + (jc) * 128 + seg_ * 8;            \
            cp16(smem_u32(dst_), src_);                                           \
        }                                                                         \
        cp_commit();                                                              \
    }

    // prologue: Ei hi/lo joins group 0
    if (tid < 512) {
        int arr = tid >> 8, rem = tid & 255;
        int r = rem >> 3, seg = rem & 7;
        __nv_bfloat16* dst = (arr ? Eil : Eih) + r * 72 + seg * 8;
        const __nv_bfloat16* src = (arr ? g_Elo : g_Ehi) + (size_t)(base + i0 + r) * 64 + seg * 8;
        cp16(smem_u32(dst), src);
    }
    AT_ISSUE(0, 0);
    AT_ISSUE(1, 1);
    cp_wait1();
    __syncthreads();

    // hoisted A fragments (each warp: its 16-row half, all k)
    uint32_t Ah[4][4], Al[4][4];
#pragma unroll
    for (int kc = 0; kc < 4; kc++) {
        ldm_x4(Ah[kc], smem_u32(&Eih[(mt * 16 + lrow + q1 * 8) * 72 + kc * 16 + q2 * 8]));
        ldm_x4(Al[kc], smem_u32(&Eil[(mt * 16 + lrow + q1 * 8) * 72 + kc * 16 + q2 * 8]));
    }

    // per-lane row constants
    int r0 = mt * 16 + (lane >> 2);
    int ig0 = i0 + r0, ig1 = ig0 + 8;
    int yi0 = ig0 >> 5, xi0 = ig0 & 31;
    int yi1 = ig1 >> 5, xi1 = ig1 & 31;
    float sqi0 = g_sq[base + ig0];
    float sqi1 = g_sq[base + ig1];
    // B ldmatrix.x2 source row offset (lanes 0-15 supply addresses)
    int brow = (lane & 7) + ((lane >> 3) & 1) * 8;

    // ---- Phase A ----
    for (int jc = 0; jc < 8; jc++) {
        if (jc >= 1) {
            if (jc < 7) cp_wait1(); else cp_wait0();
            __syncthreads();
        }
        int buf = jc & 1;
        float acc[4] = {};
#pragma unroll
        for (int kc = 0; kc < 4; kc++) {
            uint32_t bh[2], bl[2];
            ldm_x2_t(bh, smem_u32(&BhS[buf * 8704 + (kc * 16 + brow) * 136 + ncol * 8]));
            ldm_x2_t(bl, smem_u32(&BlS[buf * 8704 + (kc * 16 + brow) * 136 + ncol * 8]));
            mma16816(acc, Ah[kc], bh[0], bh[1]);
            mma16816(acc, Al[kc], bh[0], bh[1]);
            mma16816(acc, Ah[kc], bl[0], bl[1]);
        }
        int j0 = jc * 128 + ncol * 8 + (lane & 3) * 2;
        int yj0 = j0 >> 5, xj0 = j0 & 31;
        int yj1 = (j0 + 1) >> 5, xj1 = (j0 + 1) & 31;
        float sq0 = Sqj[j0], sq1 = Sqj[j0 + 1];
        {
            float d2a = fmaxf(sqi0 + sq0 - 2.0f * acc[0], 0.0f);
            float d2b = fmaxf(sqi0 + sq1 - 2.0f * acc[1], 0.0f);
            int da = abs(yi0 - yj0) + abs(xi0 - xj0);
            int db = abs(yi0 - yj1) + abs(xi0 - xj1);
            float ma = (da <= 32) ? (float)da * (1.0f / 32.0f) : 0.0f;
            float mb = (db <= 32) ? (float)db * (1.0f / 32.0f) : 0.0f;
            *(float2*)&S[r0 * S_PITCH + j0] =
                make_float2(__expf(-d2a) - 1.0f + ma, __expf(-d2b) - 1.0f + mb);
        }
        {
            float d2a = fmaxf(sqi1 + sq0 - 2.0f * acc[2], 0.0f);
            float d2b = fmaxf(sqi1 + sq1 - 2.0f * acc[3], 0.0f);
            int da = abs(yi1 - yj0) + abs(xi1 - xj0);
            int db = abs(yi1 - yj1) + abs(xi1 - xj1);
            float ma = (da <= 32) ? (float)da * (1.0f / 32.0f) : 0.0f;
            float mb = (db <= 32) ? (float)db * (1.0f / 32.0f) : 0.0f;
            *(float2*)&S[(r0 + 8) * S_PITCH + j0] =
                make_float2(__expf(-d2a) - 1.0f + ma, __expf(-d2b) - 1.0f + mb);
        }
        __syncthreads();
        if (jc < 6) AT_ISSUE(jc + 2, jc & 1);
    }
#undef AT_ISSUE

    // ---- Phase B: register softmax, 1 row per warp, single fp16 A store ----
    {
        int r = w;
        float* Sr = S + r * S_PITCH;
        float v[32];
#pragma unroll
        for (int t = 0; t < 32; t++) v[t] = Sr[lane + t * 32];
        float m = -1e30f;
#pragma unroll
        for (int t = 0; t < 32; t++) m = fmaxf(m, v[t]);
#pragma unroll
        for (int o = 16; o; o >>= 1) m = fmaxf(m, __shfl_xor_sync(0xffffffffu, m, o));
        float s1 = 0.0f;
#pragma unroll
        for (int t = 0; t < 32; t++) { v[t] = __expf(v[t] - m); s1 += v[t]; }
#pragma unroll
        for (int o = 16; o; o >>= 1) s1 += __shfl_xor_sync(0xffffffffu, s1, o);
        float inv1 = 1.0f / s1;
        float m2 = 0.0f;
#pragma unroll
        for (int t = 0; t < 32; t++) {
            v[t] = fmaxf(v[t] * inv1 - Tsh[lane + t * 32], 0.0f);
            m2 = fmaxf(m2, v[t]);
        }
#pragma unroll
        for (int o = 16; o; o >>= 1) m2 = fmaxf(m2, __shfl_xor_sync(0xffffffffu, m2, o));
        float s2 = 0.0f;
#pragma unroll
        for (int t = 0; t < 32; t++) { v[t] = __expf(v[t] - m2); s2 += v[t]; }
#pragma unroll
        for (int o = 16; o; o >>= 1) s2 += __shfl_xor_sync(0xffffffffu, s2, o);
        float inv2 = 1.0f / s2;

        // repack fp16 into this (now-dead) S row, then coalesced copy out
        __half* rowh = (__half*)Sr;
#pragma unroll
        for (int t = 0; t < 32; t++) {
            rowh[lane + t * 32] = __float2half_rn(v[t] * inv2);
        }
        __syncwarp();
        size_t Ab = ((size_t)b << 20) + ((size_t)(i0 + r) << 10);
        uint4* gh = (uint4*)&g_Af[Ab];
        const uint4* sh = (const uint4*)rowh;
#pragma unroll
        for (int it = 0; it < 4; it++) gh[lane + it * 32] = sh[lane + it * 32];
    }
}

// ---------------- fp16 tensor-core bmm: out = x + A @ SC (single term, k=64 stages) ----------------
#define BMM_OFF_AF 0
#define BMM_OFF_SH 36864
#define BMM_SMEM   71680
__global__ __launch_bounds__(256, 2) void bmm_kernel(const float* __restrict__ x,
                                                     float* __restrict__ out) {
    extern __shared__ char smc[];
    __half* Af_s = (__half*)(smc + BMM_OFF_AF);  // [2][128][72]
    __half* Sh_s = (__half*)(smc + BMM_OFF_SH);  // [2][64][136]
    int tid = threadIdx.x, w = tid >> 5, lane = tid & 31;
    int ct = blockIdx.x, mtb = blockIdx.y, b = blockIdx.z;
    int i0 = mtb * 128, c0 = ct * 128;

    const __half* Af = g_Af + ((size_t)b << 20) + (size_t)i0 * 1024;
    const __half* Shf = g_SChf + ((size_t)b << 18) + c0;

    float acc[4][4][4];
#pragma unroll
    for (int a = 0; a < 4; a++)
#pragma unroll
        for (int n = 0; n < 4; n++)
#pragma unroll
            for (int r = 0; r < 4; r++) acc[a][n][r] = 0.0f;

    int wm = w >> 2, wn = w & 3;
    int lrow = lane & 7, q1 = (lane >> 3) & 1, q2 = lane >> 4;

#define ISSUE(jc, bf_)                                                            \
    {                                                                             \
        for (int u_ = 0; u_ < 4; u_++) {                                          \
            int id_ = tid + u_ * 256;                                             \
            int ar_ = id_ >> 3, aseg_ = id_ & 7;                                  \
            cp16(smem_u32(&Af_s[(bf_) * 9216 + ar_ * 72 + aseg_ * 8]),            \
                 Af + (size_t)ar_ * 1024 + (jc) * 64 + aseg_ * 8);                \
            int sr_ = id_ >> 4, sseg_ = id_ & 15;                                 \
            cp16(smem_u32(&Sh_s[(bf_) * 8704 + sr_ * 136 + sseg_ * 8]),           \
                 Shf + (size_t)((jc) * 64 + sr_) * 256 + sseg_ * 8);              \
        }                                                                         \
        cp_commit();                                                              \
    }

    ISSUE(0, 0);
    ISSUE(1, 1);
    for (int cc = 0; cc < 16; cc++) {
        if (cc < 15) cp_wait1(); else cp_wait0();
        __syncthreads();
        int buf = cc & 1;
#pragma unroll
        for (int kk = 0; kk < 4; kk++) {
            uint32_t af[4][4];
#pragma unroll
            for (int mtl = 0; mtl < 4; mtl++) {
                int row = wm * 64 + mtl * 16 + lrow + q1 * 8;
                int col = kk * 16 + q2 * 8;
                ldm_x4(af[mtl], smem_u32(&Af_s[buf * 9216 + row * 72 + col]));
            }
            uint32_t bh[2][4];
#pragma unroll
            for (int ng = 0; ng < 2; ng++) {
                int row = kk * 16 + lrow + q1 * 8;
                int col = wn * 32 + ng * 16 + q2 * 8;
                ldm_x4_t(bh[ng], smem_u32(&Sh_s[buf * 8704 + row * 136 + col]));
            }
#pragma unroll
            for (int mtl = 0; mtl < 4; mtl++)
#pragma unroll
                for (int nt = 0; nt < 4; nt++)
                    mma16816h(acc[mtl][nt], af[mtl],
                              bh[nt >> 1][(nt & 1) * 2], bh[nt >> 1][(nt & 1) * 2 + 1]);
        }
        __syncthreads();   // all warps done with buf before it is overwritten
        if (cc + 2 < 16) ISSUE(cc + 2, cc & 1);
    }
#undef ISSUE

    int g = lane >> 2, t2 = lane & 3;
#pragma unroll
    for (int mtl = 0; mtl < 4; mtl++) {
#pragma unroll
        for (int nt = 0; nt < 4; nt++) {
            int row = i0 + wm * 64 + mtl * 16 + g;
            int col = c0 + wn * 32 + nt * 8 + 2 * t2;
            size_t o0 = ((size_t)b * 1024 + row) * 256 + col;
            size_t o1 = o0 + 8 * 256;
            float2 xv0 = *(const float2*)&x[o0];
            float2 xv1 = *(const float2*)&x[o1];
            *(float2*)&out[o0] = make_float2(xv0.x + acc[mtl][nt][0], xv0.y + acc[mtl][nt][1]);
            *(float2*)&out[o1] = make_float2(xv1.x + acc[mtl][nt][2], xv1.y + acc[mtl][nt][3]);
        }
    }
}

// ---------------- launch ----------------
extern "C" void kernel_launch(void* const* d_in, const int* in_sizes, int n_in,
                              void* d_out, int out_size) {
    const float* x      = (const float*)d_in[0];
    const float* emb_W  = (const float*)d_in[1];
    const float* emb_b  = (const float*)d_in[2];
    const float* attn_W = (const float*)d_in[3];
    const float* attn_b = (const float*)d_in[4];
    const float* thr_W  = (const float*)d_in[5];
    const float* thr_b  = (const float*)d_in[6];
    float* out = (float*)d_out;

    cudaFuncSetAttribute(emb_kernel, cudaFuncAttributeMaxDynamicSharedMemorySize, EMB_SMEM);
    cudaFuncSetAttribute(shortcut_kernel, cudaFuncAttributeMaxDynamicSharedMemorySize, SC_SMEM);
    cudaFuncSetAttribute(attn_A_kernel, cudaFuncAttributeMaxDynamicSharedMemorySize, ATTN_SMEM);
    cudaFuncSetAttribute(bmm_kernel, cudaFuncAttributeMaxDynamicSharedMemorySize, BMM_SMEM);

    prep_kernel<<<256, 256>>>(attn_W, emb_W);
    emb_kernel<<<BATCH * HW / 32, 256, EMB_SMEM>>>(x, emb_b);
    shortcut_kernel<<<BATCH * HW / 64, 256, SC_SMEM>>>(attn_b, thr_W, thr_b);
    attn_A_kernel<<<dim3(HW / 32, BATCH), 1024, ATTN_SMEM>>>();
    bmm_kernel<<<dim3(CDIM / 128, HW / 128, BATCH), 256, BMM_SMEM>>>(x, out);
}

// round 12
// speedup vs baseline: 1.6595x; 1.0197x over previous
#include <cuda_runtime.h>
#include <cuda_bf16.h>
#include <cuda_fp16.h>
#include <math.h>
#include <stdint.h>

#define BATCH 32
#define HW    1024
#define CDIM  256
#define FDIM  64

// ---------------- scratch (device globals; no allocations) ----------------
__device__ float g_sq[BATCH * HW];
__device__ float g_T[BATCH * HW];
__device__ __nv_bfloat16 g_Ehi[BATCH * HW * FDIM];       // [n][k]
__device__ __nv_bfloat16 g_Elo[BATCH * HW * FDIM];
__device__ __nv_bfloat16 g_EhiT[BATCH * FDIM * HW];      // [b][k][n]
__device__ __nv_bfloat16 g_EloT[BATCH * FDIM * HW];
__device__ __nv_bfloat16 g_xhi[BATCH * HW * CDIM];
__device__ __nv_bfloat16 g_xlo[BATCH * HW * CDIM];
__device__ __half g_SChf[BATCH * HW * CDIM];             // single fp16 SC
__device__ __half g_Af[(size_t)BATCH * HW * HW];         // 64 MB, single fp16 A
__device__ __nv_bfloat16 g_Wthi[CDIM * CDIM];            // attn_W^T split [cin][cout]
__device__ __nv_bfloat16 g_Wtlo[CDIM * CDIM];
__device__ float g_emb_Wt[CDIM * FDIM];

// ---------------- small helpers ----------------
__device__ __forceinline__ uint32_t smem_u32(const void* p) {
    return (uint32_t)__cvta_generic_to_shared(p);
}
__device__ __forceinline__ void cp16(uint32_t dst, const void* src) {
    asm volatile("cp.async.cg.shared.global [%0], [%1], 16;\n" :: "r"(dst), "l"(src));
}
__device__ __forceinline__ void cp_commit() { asm volatile("cp.async.commit_group;\n"); }
__device__ __forceinline__ void cp_wait1() { asm volatile("cp.async.wait_group 1;\n"); }
__device__ __forceinline__ void cp_wait0() { asm volatile("cp.async.wait_group 0;\n"); }
__device__ __forceinline__ void ldm_x4(uint32_t (&r)[4], uint32_t addr) {
    asm volatile("ldmatrix.sync.aligned.m8n8.x4.shared.b16 {%0,%1,%2,%3}, [%4];"
                 : "=r"(r[0]), "=r"(r[1]), "=r"(r[2]), "=r"(r[3]) : "r"(addr));
}
__device__ __forceinline__ void ldm_x4_t(uint32_t (&r)[4], uint32_t addr) {
    asm volatile("ldmatrix.sync.aligned.m8n8.x4.trans.shared.b16 {%0,%1,%2,%3}, [%4];"
                 : "=r"(r[0]), "=r"(r[1]), "=r"(r[2]), "=r"(r[3]) : "r"(addr));
}
__device__ __forceinline__ void ldm_x2_t(uint32_t (&r)[2], uint32_t addr) {
    asm volatile("ldmatrix.sync.aligned.m8n8.x2.trans.shared.b16 {%0,%1}, [%2];"
                 : "=r"(r[0]), "=r"(r[1]) : "r"(addr));
}
// bf16 mma (Gram / shortcut path)
__device__ __forceinline__ void mma16816(float (&d)[4], const uint32_t (&a)[4],
                                         uint32_t b0, uint32_t b1) {
    asm volatile("mma.sync.aligned.m16n8k16.row.col.f32.bf16.bf16.f32 "
                 "{%0,%1,%2,%3}, {%4,%5,%6,%7}, {%8,%9}, {%0,%1,%2,%3};"
                 : "+f"(d[0]), "+f"(d[1]), "+f"(d[2]), "+f"(d[3])
                 : "r"(a[0]), "r"(a[1]), "r"(a[2]), "r"(a[3]), "r"(b0), "r"(b1));
}
// fp16 mma (bmm path)
__device__ __forceinline__ void mma16816h(float (&d)[4], const uint32_t (&a)[4],
                                          uint32_t b0, uint32_t b1) {
    asm volatile("mma.sync.aligned.m16n8k16.row.col.f32.f16.f16.f32 "
                 "{%0,%1,%2,%3}, {%4,%5,%6,%7}, {%8,%9}, {%0,%1,%2,%3};"
                 : "+f"(d[0]), "+f"(d[1]), "+f"(d[2]), "+f"(d[3])
                 : "r"(a[0]), "r"(a[1]), "r"(a[2]), "r"(a[3]), "r"(b0), "r"(b1));
}
union BPack2 { __nv_bfloat16 h[2]; uint32_t u; };
union BPack4 { __nv_bfloat16 h[4]; uint2 u; };
union HPack2 { __half h[2]; uint32_t u; };

// ---------------- prep: weight transposes + bf16 splits ----------------
__global__ void prep_kernel(const float* __restrict__ attn_W,
                            const float* __restrict__ emb_W) {
    int t = blockIdx.x * 256 + threadIdx.x;
    if (t < CDIM * CDIM) {
        int ci = t >> 8, co = t & 255;
        float v = attn_W[co * CDIM + ci];
        __nv_bfloat16 h = __float2bfloat16(v);
        g_Wthi[ci * CDIM + co] = h;
        g_Wtlo[ci * CDIM + co] = __float2bfloat16(v - __bfloat162float(h));
    }
    if (t < FDIM * CDIM) {
        int f = t >> 8, ci = t & 255;
        g_emb_Wt[ci * FDIM + f] = emb_W[f * CDIM + ci];
    }
}

// ---------------- emb: x @ emb_W^T + b -> bf16 hi/lo (+transposed) + sq + x-split ----------------
#define EMB_SMEM ((32 * 256 + 256 * 64) * 4)
__global__ __launch_bounds__(256) void emb_kernel(const float* __restrict__ x,
                                                  const float* __restrict__ emb_b) {
    extern __shared__ float sm[];
    float* xs = sm;              // [32][256]
    float* we = sm + 32 * 256;   // [256][64]
    int tid = threadIdx.x;
    int row0 = blockIdx.x * 32;
    int bb = row0 >> 10, n0 = row0 & 1023;

    const float4* xg = (const float4*)(x + (size_t)row0 * CDIM);
    float4* xs4 = (float4*)xs;
    for (int i = tid; i < 32 * 64; i += 256) xs4[i] = xg[i];
    const float4* wg = (const float4*)g_emb_Wt;
    float4* we4 = (float4*)we;
    for (int i = tid; i < 256 * 16; i += 256) we4[i] = wg[i];
    __syncthreads();

    // fused x -> bf16 hi/lo split
    for (int i = tid; i < 2048; i += 256) {
        float4 v = xs4[i];
        float vv[4] = {v.x, v.y, v.z, v.w};
        BPack4 ph, pl;
#pragma unroll
        for (int q = 0; q < 4; q++) {
            __nv_bfloat16 h = __float2bfloat16(vv[q]);
            ph.h[q] = h;
            pl.h[q] = __float2bfloat16(vv[q] - __bfloat162float(h));
        }
        ((uint2*)g_xhi)[(size_t)row0 * 64 + i] = ph.u;
        ((uint2*)g_xlo)[(size_t)row0 * 64 + i] = pl.u;
    }

    int w = tid >> 5, lane = tid & 31;
    int ig = w * 4, fg = lane * 2;
    float acc[4][2] = {};
#pragma unroll 4
    for (int c = 0; c < 256; c++) {
        float2 wv = *(const float2*)&we[c * 64 + fg];
#pragma unroll
        for (int q = 0; q < 4; q++) {
            float a = xs[(ig + q) * 256 + c];
            acc[q][0] = fmaf(a, wv.x, acc[q][0]);
            acc[q][1] = fmaf(a, wv.y, acc[q][1]);
        }
    }
    float b0 = emb_b[fg], b1 = emb_b[fg + 1];
    float e0r[4], e1r[4];
#pragma unroll
    for (int q = 0; q < 4; q++) {
        float e0 = acc[q][0] + b0, e1 = acc[q][1] + b1;
        e0r[q] = e0; e1r[q] = e1;
        int n = row0 + ig + q;
        BPack2 ph, pl;
        ph.h[0] = __float2bfloat16(e0);
        ph.h[1] = __float2bfloat16(e1);
        pl.h[0] = __float2bfloat16(e0 - __bfloat162float(ph.h[0]));
        pl.h[1] = __float2bfloat16(e1 - __bfloat162float(ph.h[1]));
        *(uint32_t*)&g_Ehi[(size_t)n * FDIM + fg] = ph.u;
        *(uint32_t*)&g_Elo[(size_t)n * FDIM + fg] = pl.u;
        float p = e0 * e0 + e1 * e1;
#pragma unroll
        for (int o = 16; o; o >>= 1) p += __shfl_xor_sync(0xffffffffu, p, o);
        if (lane == 0) g_sq[n] = p;
    }

    // transposed bf16 copies via smem staging: [64][33]
    __nv_bfloat16* st = (__nv_bfloat16*)sm;
    __syncthreads();
#pragma unroll
    for (int q = 0; q < 4; q++) {
        st[fg * 33 + ig + q] = __float2bfloat16(e0r[q]);
        st[(fg + 1) * 33 + ig + q] = __float2bfloat16(e1r[q]);
    }
    __syncthreads();
    for (int idx = tid; idx < 2048; idx += 256) {
        int k = idx >> 5, i2 = idx & 31;
        g_EhiT[(((size_t)bb * 64 + k) << 10) + n0 + i2] = st[k * 33 + i2];
    }
    __syncthreads();
#pragma unroll
    for (int q = 0; q < 4; q++) {
        float h0 = __bfloat162float(__float2bfloat16(e0r[q]));
        float h1 = __bfloat162float(__float2bfloat16(e1r[q]));
        st[fg * 33 + ig + q] = __float2bfloat16(e0r[q] - h0);
        st[(fg + 1) * 33 + ig + q] = __float2bfloat16(e1r[q] - h1);
    }
    __syncthreads();
    for (int idx = tid; idx < 2048; idx += 256) {
        int k = idx >> 5, i2 = idx & 31;
        g_EloT[(((size_t)bb * 64 + k) << 10) + n0 + i2] = st[k * 33 + i2];
    }
}

// ---------------- shortcut: SC = x @ W^T + b (3-term), plus T — 3-stage ring ----------------
// epilogue emits single fp16 SC
#define SC_OFF_A 0
#define SC_OFF_B 15360
#define SC_OFF_T 66048
#define SC_SMEM  66304
__global__ __launch_bounds__(256) void shortcut_kernel(const float* __restrict__ attn_b,
                                                       const float* __restrict__ thr_W,
                                                       const float* __restrict__ thr_b) {
    extern __shared__ char smc[];
    __nv_bfloat16* Asp = (__nv_bfloat16*)(smc + SC_OFF_A);   // [3][64][40]
    __nv_bfloat16* Bsp = (__nv_bfloat16*)(smc + SC_OFF_B);   // [3][32][264]
    float* Tp = (float*)(smc + SC_OFF_T);
    int tid = threadIdx.x, w = tid >> 5, lane = tid & 31;
    int m0 = blockIdx.x * 64;
    int lrow = lane & 7, q1 = (lane >> 3) & 1, q2 = lane >> 4;

    if (tid < 64) Tp[tid] = 0.0f;

    float acc[4][4][4];
#pragma unroll
    for (int a = 0; a < 4; a++)
#pragma unroll
        for (int n = 0; n < 4; n++)
#pragma unroll
            for (int r = 0; r < 4; r++) acc[a][n][r] = 0.0f;

#define SC_ISSUE(s, bf_)                                                          \
    {                                                                             \
        int term_ = (s) >> 3, kc_ = (s) & 7;                                      \
        const __nv_bfloat16* Ap_ = (term_ == 1) ? g_xlo : g_xhi;                  \
        const __nv_bfloat16* Bp_ = (term_ == 2) ? g_Wtlo : g_Wthi;                \
        int ar_ = tid >> 2, aseg_ = tid & 3;                                      \
        cp16(smem_u32(&Asp[(bf_) * 2560 + ar_ * 40 + aseg_ * 8]),                 \
             Ap_ + (size_t)(m0 + ar_) * CDIM + kc_ * 32 + aseg_ * 8);             \
        for (int u_ = 0; u_ < 4; u_++) {                                          \
            int id_ = tid + u_ * 256;                                             \
            int br_ = id_ >> 5, bseg_ = id_ & 31;                                 \
            cp16(smem_u32(&Bsp[(bf_) * 8448 + br_ * 264 + bseg_ * 8]),            \
                 Bp_ + (size_t)(kc_ * 32 + br_) * CDIM + bseg_ * 8);              \
        }                                                                         \
        cp_commit();                                                              \
    }

    SC_ISSUE(0, 0);
    SC_ISSUE(1, 1);
    for (int s = 0; s < 24; s++) {
        if (s < 23) cp_wait1(); else cp_wait0();
        __syncthreads();
        int buf = s % 3;
#pragma unroll
        for (int kk = 0; kk < 2; kk++) {
            uint32_t af[4][4];
#pragma unroll
            for (int mt = 0; mt < 4; mt++)
                ldm_x4(af[mt], smem_u32(&Asp[buf * 2560 + (mt * 16 + lrow + q1 * 8) * 40 + kk * 16 + q2 * 8]));
            uint32_t bfr[2][4];
#pragma unroll
            for (int ng = 0; ng < 2; ng++)
                ldm_x4_t(bfr[ng], smem_u32(&Bsp[buf * 8448 + (kk * 16 + lrow + q1 * 8) * 264 + w * 32 + ng * 16 + q2 * 8]));
#pragma unroll
            for (int mt = 0; mt < 4; mt++)
#pragma unroll
                for (int nt = 0; nt < 4; nt++)
                    mma16816(acc[mt][nt], af[mt],
                             bfr[nt >> 1][(nt & 1) * 2], bfr[nt >> 1][(nt & 1) * 2 + 1]);
        }
        if (s + 2 < 24) SC_ISSUE(s + 2, (s + 2) % 3);
    }
#undef SC_ISSUE

    // epilogue: bias, single fp16 stores, T partials
    float pr0[4] = {}, pr1[4] = {};
#pragma unroll
    for (int nt = 0; nt < 4; nt++) {
        int c0 = w * 32 + nt * 8 + (lane & 3) * 2;
        float bb0 = attn_b[c0], bb1 = attn_b[c0 + 1];
        float tw0 = thr_W[c0], tw1 = thr_W[c0 + 1];
#pragma unroll
        for (int mt = 0; mt < 4; mt++) {
            int r0g = m0 + mt * 16 + (lane >> 2);
            float v00 = acc[mt][nt][0] + bb0, v01 = acc[mt][nt][1] + bb1;
            float v10 = acc[mt][nt][2] + bb0, v11 = acc[mt][nt][3] + bb1;
            HPack2 h;
            h.h[0] = __float2half_rn(v00); h.h[1] = __float2half_rn(v01);
            *(uint32_t*)&g_SChf[(size_t)r0g * CDIM + c0] = h.u;
            h.h[0] = __float2half_rn(v10); h.h[1] = __float2half_rn(v11);
            *(uint32_t*)&g_SChf[(size_t)(r0g + 8) * CDIM + c0] = h.u;
            pr0[mt] += v00 * tw0 + v01 * tw1;
            pr1[mt] += v10 * tw0 + v11 * tw1;
        }
    }
#pragma unroll
    for (int mt = 0; mt < 4; mt++) {
        pr0[mt] += __shfl_xor_sync(0xffffffffu, pr0[mt], 1);
        pr0[mt] += __shfl_xor_sync(0xffffffffu, pr0[mt], 2);
        pr1[mt] += __shfl_xor_sync(0xffffffffu, pr1[mt], 1);
        pr1[mt] += __shfl_xor_sync(0xffffffffu, pr1[mt], 2);
        if ((lane & 3) == 0) {
            atomicAdd(&Tp[mt * 16 + (lane >> 2)], pr0[mt]);
            atomicAdd(&Tp[mt * 16 + (lane >> 2) + 8], pr1[mt]);
        }
    }
    __syncthreads();
    if (tid < 64) g_T[m0 + tid] = Tp[tid] + thr_b[0];
}

// ---------------- attention matrix kernel: 32 rows, 1024 threads, hoisted addressing ----------------
#define S_PITCH 1044
#define OFF_S    0
#define OFF_EIH  133632
#define OFF_EIL  138240
#define OFF_BH   142848
#define OFF_BL   177664
#define OFF_TSH  212480
#define OFF_SQJ  216576
#define ATTN_SMEM 220672

__global__ __launch_bounds__(1024) void attn_A_kernel() {
    extern __shared__ char smc[];
    float* S = (float*)(smc + OFF_S);                         // [32][1044]
    __nv_bfloat16* Eih = (__nv_bfloat16*)(smc + OFF_EIH);     // [32][72]
    __nv_bfloat16* Eil = (__nv_bfloat16*)(smc + OFF_EIL);
    __nv_bfloat16* BhS = (__nv_bfloat16*)(smc + OFF_BH);      // [2][64][136]
    __nv_bfloat16* BlS = (__nv_bfloat16*)(smc + OFF_BL);
    float* Tsh = (float*)(smc + OFF_TSH);
    float* Sqj = (float*)(smc + OFF_SQJ);

    int tid = threadIdx.x;
    int tile = blockIdx.x, b = blockIdx.y;
    int i0 = tile * 32;
    int base = b * HW;
    int w = tid >> 5, lane = tid & 31;
    int lrow = lane & 7, q1 = (lane >> 3) & 1, q2 = lane >> 4;
    int mt = w & 1, ncol = w >> 1;         // 32 warps: 2 row-halves x 16 col-tiles of 8

    for (int i = tid; i < 1024; i += 1024) {
        Tsh[i] = g_T[base + i];
        Sqj[i] = g_sq[base + i];
    }

    // hoisted cp.async addresses (affine in jc, buf)
    uint32_t dA = smem_u32(BhS) + ((tid >> 4) * 136 + (tid & 15) * 8) * 2;
    uint32_t dB = smem_u32(BlS) + ((tid >> 4) * 136 + (tid & 15) * 8) * 2;
    const __nv_bfloat16* sA = g_EhiT + (((size_t)b * 64 + (tid >> 4)) << 10) + (tid & 15) * 8;
    const __nv_bfloat16* sB = g_EloT + (((size_t)b * 64 + (tid >> 4)) << 10) + (tid & 15) * 8;

#define AT_ISSUE(jc, buf)                                                         \
    {                                                                             \
        cp16(dA + (buf) * 17408, sA + (jc) * 128);                                \
        cp16(dB + (buf) * 17408, sB + (jc) * 128);                                \
        cp_commit();                                                              \
    }

    // prologue: Ei hi/lo joins group 0
    if (tid < 512) {
        int arr = tid >> 8, rem = tid & 255;
        int r = rem >> 3, seg = rem & 7;
        __nv_bfloat16* dst = (arr ? Eil : Eih) + r * 72 + seg * 8;
        const __nv_bfloat16* src = (arr ? g_Elo : g_Ehi) + (size_t)(base + i0 + r) * 64 + seg * 8;
        cp16(smem_u32(dst), src);
    }
    AT_ISSUE(0, 0);
    AT_ISSUE(1, 1);
    cp_wait1();
    __syncthreads();

    // hoisted A fragments (each warp: its 16-row half, all k)
    uint32_t Ah[4][4], Al[4][4];
#pragma unroll
    for (int kc = 0; kc < 4; kc++) {
        ldm_x4(Ah[kc], smem_u32(&Eih[(mt * 16 + lrow + q1 * 8) * 72 + kc * 16 + q2 * 8]));
        ldm_x4(Al[kc], smem_u32(&Eil[(mt * 16 + lrow + q1 * 8) * 72 + kc * 16 + q2 * 8]));
    }

    // per-lane constants (float-domain mask math; all values integer-exact)
    int r0 = mt * 16 + (lane >> 2);
    int ig0 = i0 + r0, ig1 = ig0 + 8;
    float yi0f = (float)(ig0 >> 5), xi0f = (float)(ig0 & 31);
    float yi1f = (float)(ig1 >> 5), xi1f = (float)(ig1 & 31);
    float sqi0 = g_sq[base + ig0];
    float sqi1 = g_sq[base + ig1];
    int brow = (lane & 7) + ((lane >> 3) & 1) * 8;
    int jlow = ncol * 8 + (lane & 3) * 2;
    float yjf = (float)(jlow >> 5);           // += 4 per jc
    float xjf = (float)(jlow & 31);           // constant across jc (128 % 32 == 0)
    float dx00 = fabsf(xi0f - xjf), dx01 = fabsf(xi0f - xjf - 1.0f);
    float dx10 = fabsf(xi1f - xjf), dx11 = fabsf(xi1f - xjf - 1.0f);
    const float* Sqjb = Sqj + jlow;
    float* Srow0 = S + r0 * S_PITCH + jlow;
    float* Srow1 = Srow0 + 8 * S_PITCH;
    uint32_t bhl = smem_u32(BhS) + (brow * 136 + ncol * 8) * 2;
    uint32_t bll = smem_u32(BlS) + (brow * 136 + ncol * 8) * 2;

    // ---- Phase A ----
    for (int jc = 0; jc < 8; jc++) {
        if (jc >= 1) {
            if (jc < 7) cp_wait1(); else cp_wait0();
            __syncthreads();
        }
        uint32_t bufoff = (jc & 1) * 17408;
        float acc[4] = {};
#pragma unroll
        for (int kc = 0; kc < 4; kc++) {
            uint32_t bh[2], bl[2];
            ldm_x2_t(bh, bhl + bufoff + kc * 4352);
            ldm_x2_t(bl, bll + bufoff + kc * 4352);
            mma16816(acc, Ah[kc], bh[0], bh[1]);
            mma16816(acc, Al[kc], bh[0], bh[1]);
            mma16816(acc, Ah[kc], bl[0], bl[1]);
        }
        float sq0 = Sqjb[0], sq1 = Sqjb[1];
        float dy0 = fabsf(yi0f - yjf);
        float dy1 = fabsf(yi1f - yjf);
        {
            float d2a = fmaxf(sqi0 + sq0 - 2.0f * acc[0], 0.0f);
            float d2b = fmaxf(sqi0 + sq1 - 2.0f * acc[1], 0.0f);
            float da = dy0 + dx00, db = dy0 + dx01;
            float ma = (da <= 32.0f) ? da * (1.0f / 32.0f) : 0.0f;
            float mb = (db <= 32.0f) ? db * (1.0f / 32.0f) : 0.0f;
            *(float2*)Srow0 = make_float2(__expf(-d2a) - 1.0f + ma, __expf(-d2b) - 1.0f + mb);
        }
        {
            float d2a = fmaxf(sqi1 + sq0 - 2.0f * acc[2], 0.0f);
            float d2b = fmaxf(sqi1 + sq1 - 2.0f * acc[3], 0.0f);
            float da = dy1 + dx10, db = dy1 + dx11;
            float ma = (da <= 32.0f) ? da * (1.0f / 32.0f) : 0.0f;
            float mb = (db <= 32.0f) ? db * (1.0f / 32.0f) : 0.0f;
            *(float2*)Srow1 = make_float2(__expf(-d2a) - 1.0f + ma, __expf(-d2b) - 1.0f + mb);
        }
        yjf += 4.0f;
        Sqjb += 128; Srow0 += 128; Srow1 += 128;
        __syncthreads();
        if (jc < 6) AT_ISSUE(jc + 2, jc & 1);
    }
#undef AT_ISSUE

    // ---- Phase B: register softmax, 1 row per warp, single fp16 A store ----
    {
        int r = w;
        float* Sr = S + r * S_PITCH;
        float v[32];
#pragma unroll
        for (int t = 0; t < 32; t++) v[t] = Sr[lane + t * 32];
        float m = -1e30f;
#pragma unroll
        for (int t = 0; t < 32; t++) m = fmaxf(m, v[t]);
#pragma unroll
        for (int o = 16; o; o >>= 1) m = fmaxf(m, __shfl_xor_sync(0xffffffffu, m, o));
        float s1 = 0.0f;
#pragma unroll
        for (int t = 0; t < 32; t++) { v[t] = __expf(v[t] - m); s1 += v[t]; }
#pragma unroll
        for (int o = 16; o; o >>= 1) s1 += __shfl_xor_sync(0xffffffffu, s1, o);
        float inv1 = 1.0f / s1;
        float m2 = 0.0f;
#pragma unroll
        for (int t = 0; t < 32; t++) {
            v[t] = fmaxf(v[t] * inv1 - Tsh[lane + t * 32], 0.0f);
            m2 = fmaxf(m2, v[t]);
        }
#pragma unroll
        for (int o = 16; o; o >>= 1) m2 = fmaxf(m2, __shfl_xor_sync(0xffffffffu, m2, o));
        float s2 = 0.0f;
#pragma unroll
        for (int t = 0; t < 32; t++) { v[t] = __expf(v[t] - m2); s2 += v[t]; }
#pragma unroll
        for (int o = 16; o; o >>= 1) s2 += __shfl_xor_sync(0xffffffffu, s2, o);
        float inv2 = 1.0f / s2;

        // repack fp16 into this (now-dead) S row, then coalesced copy out
        __half* rowh = (__half*)Sr;
#pragma unroll
        for (int t = 0; t < 32; t++) {
            rowh[lane + t * 32] = __float2half_rn(v[t] * inv2);
        }
        __syncwarp();
        size_t Ab = ((size_t)b << 20) + ((size_t)(i0 + r) << 10);
        uint4* gh = (uint4*)&g_Af[Ab];
        const uint4* sh = (const uint4*)rowh;
#pragma unroll
        for (int it = 0; it < 4; it++) gh[lane + it * 32] = sh[lane + it * 32];
    }
}

// ---------------- fp16 tensor-core bmm: out = x + A @ SC (single term, k=64 stages) ----------------
#define BMM_OFF_AF 0
#define BMM_OFF_SH 36864
#define BMM_SMEM   71680
__global__ __launch_bounds__(256, 2) void bmm_kernel(const float* __restrict__ x,
                                                     float* __restrict__ out) {
    extern __shared__ char smc[];
    __half* Af_s = (__half*)(smc + BMM_OFF_AF);  // [2][128][72]
    __half* Sh_s = (__half*)(smc + BMM_OFF_SH);  // [2][64][136]
    int tid = threadIdx.x, w = tid >> 5, lane = tid & 31;
    int ct = blockIdx.x, mtb = blockIdx.y, b = blockIdx.z;
    int i0 = mtb * 128, c0 = ct * 128;

    const __half* Af = g_Af + ((size_t)b << 20) + (size_t)i0 * 1024;
    const __half* Shf = g_SChf + ((size_t)b << 18) + c0;

    float acc[4][4][4];
#pragma unroll
    for (int a = 0; a < 4; a++)
#pragma unroll
        for (int n = 0; n < 4; n++)
#pragma unroll
            for (int r = 0; r < 4; r++) acc[a][n][r] = 0.0f;

    int wm = w >> 2, wn = w & 3;
    int lrow = lane & 7, q1 = (lane >> 3) & 1, q2 = lane >> 4;

#define ISSUE(jc, bf_)                                                            \
    {                                                                             \
        for (int u_ = 0; u_ < 4; u_++) {                                          \
            int id_ = tid + u_ * 256;                                             \
            int ar_ = id_ >> 3, aseg_ = id_ & 7;                                  \
            cp16(smem_u32(&Af_s[(bf_) * 9216 + ar_ * 72 + aseg_ * 8]),            \
                 Af + (size_t)ar_ * 1024 + (jc) * 64 + aseg_ * 8);                \
            int sr_ = id_ >> 4, sseg_ = id_ & 15;                                 \
            cp16(smem_u32(&Sh_s[(bf_) * 8704 + sr_ * 136 + sseg_ * 8]),           \
                 Shf + (size_t)((jc) * 64 + sr_) * 256 + sseg_ * 8);              \
        }                                                                         \
        cp_commit();                                                              \
    }

    ISSUE(0, 0);
    ISSUE(1, 1);
    for (int cc = 0; cc < 16; cc++) {
        if (cc < 15) cp_wait1(); else cp_wait0();
        __syncthreads();
        int buf = cc & 1;
#pragma unroll
        for (int kk = 0; kk < 4; kk++) {
            uint32_t af[4][4];
#pragma unroll
            for (int mtl = 0; mtl < 4; mtl++) {
                int row = wm * 64 + mtl * 16 + lrow + q1 * 8;
                int col = kk * 16 + q2 * 8;
                ldm_x4(af[mtl], smem_u32(&Af_s[buf * 9216 + row * 72 + col]));
            }
            uint32_t bh[2][4];
#pragma unroll
            for (int ng = 0; ng < 2; ng++) {
                int row = kk * 16 + lrow + q1 * 8;
                int col = wn * 32 + ng * 16 + q2 * 8;
                ldm_x4_t(bh[ng], smem_u32(&Sh_s[buf * 8704 + row * 136 + col]));
            }
#pragma unroll
            for (int mtl = 0; mtl < 4; mtl++)
#pragma unroll
                for (int nt = 0; nt < 4; nt++)
                    mma16816h(acc[mtl][nt], af[mtl],
                              bh[nt >> 1][(nt & 1) * 2], bh[nt >> 1][(nt & 1) * 2 + 1]);
        }
        __syncthreads();   // all warps done with buf before it is overwritten
        if (cc + 2 < 16) ISSUE(cc + 2, cc & 1);
    }
#undef ISSUE

    int g = lane >> 2, t2 = lane & 3;
#pragma unroll
    for (int mtl = 0; mtl < 4; mtl++) {
#pragma unroll
        for (int nt = 0; nt < 4; nt++) {
            int row = i0 + wm * 64 + mtl * 16 + g;
            int col = c0 + wn * 32 + nt * 8 + 2 * t2;
            size_t o0 = ((size_t)b * 1024 + row) * 256 + col;
            size_t o1 = o0 + 8 * 256;
            float2 xv0 = *(const float2*)&x[o0];
            float2 xv1 = *(const float2*)&x[o1];
            *(float2*)&out[o0] = make_float2(xv0.x + acc[mtl][nt][0], xv0.y + acc[mtl][nt][1]);
            *(float2*)&out[o1] = make_float2(xv1.x + acc[mtl][nt][2], xv1.y + acc[mtl][nt][3]);
        }
    }
}

// ---------------- launch ----------------
extern "C" void kernel_launch(void* const* d_in, const int* in_sizes, int n_in,
                              void* d_out, int out_size) {
    const float* x      = (const float*)d_in[0];
    const float* emb_W  = (const float*)d_in[1];
    const float* emb_b  = (const float*)d_in[2];
    const float* attn_W = (const float*)d_in[3];
    const float* attn_b = (const float*)d_in[4];
    const float* thr_W  = (const float*)d_in[5];
    const float* thr_b  = (const float*)d_in[6];
    float* out = (float*)d_out;

    cudaFuncSetAttribute(emb_kernel, cudaFuncAttributeMaxDynamicSharedMemorySize, EMB_SMEM);
    cudaFuncSetAttribute(shortcut_kernel, cudaFuncAttributeMaxDynamicSharedMemorySize, SC_SMEM);
    cudaFuncSetAttribute(attn_A_kernel, cudaFuncAttributeMaxDynamicSharedMemorySize, ATTN_SMEM);
    cudaFuncSetAttribute(bmm_kernel, cudaFuncAttributeMaxDynamicSharedMemorySize, BMM_SMEM);

    prep_kernel<<<256, 256>>>(attn_W, emb_W);
    emb_kernel<<<BATCH * HW / 32, 256, EMB_SMEM>>>(x, emb_b);
    shortcut_kernel<<<BATCH * HW / 64, 256, SC_SMEM>>>(attn_b, thr_W, thr_b);
    attn_A_kernel<<<dim3(HW / 32, BATCH), 1024, ATTN_SMEM>>>();
    bmm_kernel<<<dim3(CDIM / 128, HW / 128, BATCH), 256, BMM_SMEM>>>(x, out);
}

// round 13
// speedup vs baseline: 1.8796x; 1.1327x over previous
#include <cuda_runtime.h>
#include <cuda_bf16.h>
#include <cuda_fp16.h>
#include <math.h>
#include <stdint.h>

#define BATCH 32
#define HW    1024
#define CDIM  256
#define FDIM  64

// ---------------- scratch (device globals; no allocations) ----------------
__device__ float g_sq[BATCH * HW];
__device__ float g_T[BATCH * HW];
__device__ __nv_bfloat16 g_Ebf[BATCH * HW * FDIM];       // bf16(emb) [n][k]
__device__ __nv_bfloat16 g_EbfT[BATCH * FDIM * HW];      // [b][k][n]
__device__ __nv_bfloat16 g_xhi[BATCH * HW * CDIM];
__device__ __nv_bfloat16 g_xlo[BATCH * HW * CDIM];
__device__ __half g_SChf[BATCH * HW * CDIM];             // single fp16 SC
__device__ __half g_Af[(size_t)BATCH * HW * HW];         // 64 MB, single fp16 A
__device__ __nv_bfloat16 g_Wthi[CDIM * CDIM];            // attn_W^T split [cin][cout]
__device__ __nv_bfloat16 g_Wtlo[CDIM * CDIM];
__device__ float g_emb_Wt[CDIM * FDIM];

// ---------------- small helpers ----------------
__device__ __forceinline__ uint32_t smem_u32(const void* p) {
    return (uint32_t)__cvta_generic_to_shared(p);
}
__device__ __forceinline__ void cp16(uint32_t dst, const void* src) {
    asm volatile("cp.async.cg.shared.global [%0], [%1], 16;\n" :: "r"(dst), "l"(src));
}
__device__ __forceinline__ void cp_commit() { asm volatile("cp.async.commit_group;\n"); }
__device__ __forceinline__ void cp_wait2() { asm volatile("cp.async.wait_group 2;\n"); }
__device__ __forceinline__ void cp_wait1() { asm volatile("cp.async.wait_group 1;\n"); }
__device__ __forceinline__ void cp_wait0() { asm volatile("cp.async.wait_group 0;\n"); }
__device__ __forceinline__ void ldm_x4(uint32_t (&r)[4], uint32_t addr) {
    asm volatile("ldmatrix.sync.aligned.m8n8.x4.shared.b16 {%0,%1,%2,%3}, [%4];"
                 : "=r"(r[0]), "=r"(r[1]), "=r"(r[2]), "=r"(r[3]) : "r"(addr));
}
__device__ __forceinline__ void ldm_x4_t(uint32_t (&r)[4], uint32_t addr) {
    asm volatile("ldmatrix.sync.aligned.m8n8.x4.trans.shared.b16 {%0,%1,%2,%3}, [%4];"
                 : "=r"(r[0]), "=r"(r[1]), "=r"(r[2]), "=r"(r[3]) : "r"(addr));
}
__device__ __forceinline__ void ldm_x2_t(uint32_t (&r)[2], uint32_t addr) {
    asm volatile("ldmatrix.sync.aligned.m8n8.x2.trans.shared.b16 {%0,%1}, [%2];"
                 : "=r"(r[0]), "=r"(r[1]) : "r"(addr));
}
// bf16 mma (Gram / shortcut path)
__device__ __forceinline__ void mma16816(float (&d)[4], const uint32_t (&a)[4],
                                         uint32_t b0, uint32_t b1) {
    asm volatile("mma.sync.aligned.m16n8k16.row.col.f32.bf16.bf16.f32 "
                 "{%0,%1,%2,%3}, {%4,%5,%6,%7}, {%8,%9}, {%0,%1,%2,%3};"
                 : "+f"(d[0]), "+f"(d[1]), "+f"(d[2]), "+f"(d[3])
                 : "r"(a[0]), "r"(a[1]), "r"(a[2]), "r"(a[3]), "r"(b0), "r"(b1));
}
// fp16 mma (bmm path)
__device__ __forceinline__ void mma16816h(float (&d)[4], const uint32_t (&a)[4],
                                          uint32_t b0, uint32_t b1) {
    asm volatile("mma.sync.aligned.m16n8k16.row.col.f32.f16.f16.f32 "
                 "{%0,%1,%2,%3}, {%4,%5,%6,%7}, {%8,%9}, {%0,%1,%2,%3};"
                 : "+f"(d[0]), "+f"(d[1]), "+f"(d[2]), "+f"(d[3])
                 : "r"(a[0]), "r"(a[1]), "r"(a[2]), "r"(a[3]), "r"(b0), "r"(b1));
}
union BPack2 { __nv_bfloat16 h[2]; uint32_t u; };
union BPack4 { __nv_bfloat16 h[4]; uint2 u; };
union HPack2 { __half h[2]; uint32_t u; };

// ---------------- prep: weight transposes + bf16 splits ----------------
__global__ void prep_kernel(const float* __restrict__ attn_W,
                            const float* __restrict__ emb_W) {
    int t = blockIdx.x * 256 + threadIdx.x;
    if (t < CDIM * CDIM) {
        int ci = t >> 8, co = t & 255;
        float v = attn_W[co * CDIM + ci];
        __nv_bfloat16 h = __float2bfloat16(v);
        g_Wthi[ci * CDIM + co] = h;
        g_Wtlo[ci * CDIM + co] = __float2bfloat16(v - __bfloat162float(h));
    }
    if (t < FDIM * CDIM) {
        int f = t >> 8, ci = t & 255;
        g_emb_Wt[ci * FDIM + f] = emb_W[f * CDIM + ci];
    }
}

// ---------------- emb: x @ emb_W^T + b -> bf16 (+transposed) + sq + x-split ----------------
#define EMB_SMEM ((32 * 256 + 256 * 64) * 4)
__global__ __launch_bounds__(256) void emb_kernel(const float* __restrict__ x,
                                                  const float* __restrict__ emb_b) {
    extern __shared__ float sm[];
    float* xs = sm;              // [32][256]
    float* we = sm + 32 * 256;   // [256][64]
    int tid = threadIdx.x;
    int row0 = blockIdx.x * 32;
    int bb = row0 >> 10, n0 = row0 & 1023;

    const float4* xg = (const float4*)(x + (size_t)row0 * CDIM);
    float4* xs4 = (float4*)xs;
    for (int i = tid; i < 32 * 64; i += 256) xs4[i] = xg[i];
    const float4* wg = (const float4*)g_emb_Wt;
    float4* we4 = (float4*)we;
    for (int i = tid; i < 256 * 16; i += 256) we4[i] = wg[i];
    __syncthreads();

    // fused x -> bf16 hi/lo split (for shortcut)
    for (int i = tid; i < 2048; i += 256) {
        float4 v = xs4[i];
        float vv[4] = {v.x, v.y, v.z, v.w};
        BPack4 ph, pl;
#pragma unroll
        for (int q = 0; q < 4; q++) {
            __nv_bfloat16 h = __float2bfloat16(vv[q]);
            ph.h[q] = h;
            pl.h[q] = __float2bfloat16(vv[q] - __bfloat162float(h));
        }
        ((uint2*)g_xhi)[(size_t)row0 * 64 + i] = ph.u;
        ((uint2*)g_xlo)[(size_t)row0 * 64 + i] = pl.u;
    }

    int w = tid >> 5, lane = tid & 31;
    int ig = w * 4, fg = lane * 2;
    float acc[4][2] = {};
#pragma unroll 4
    for (int c = 0; c < 256; c++) {
        float2 wv = *(const float2*)&we[c * 64 + fg];
#pragma unroll
        for (int q = 0; q < 4; q++) {
            float a = xs[(ig + q) * 256 + c];
            acc[q][0] = fmaf(a, wv.x, acc[q][0]);
            acc[q][1] = fmaf(a, wv.y, acc[q][1]);
        }
    }
    float b0 = emb_b[fg], b1 = emb_b[fg + 1];
    float e0r[4], e1r[4];
#pragma unroll
    for (int q = 0; q < 4; q++) {
        float e0 = acc[q][0] + b0, e1 = acc[q][1] + b1;
        e0r[q] = e0; e1r[q] = e1;
        int n = row0 + ig + q;
        BPack2 ph;
        ph.h[0] = __float2bfloat16(e0);
        ph.h[1] = __float2bfloat16(e1);
        *(uint32_t*)&g_Ebf[(size_t)n * FDIM + fg] = ph.u;
        float p = e0 * e0 + e1 * e1;
#pragma unroll
        for (int o = 16; o; o >>= 1) p += __shfl_xor_sync(0xffffffffu, p, o);
        if (lane == 0) g_sq[n] = p;
    }

    // transposed bf16 copy via smem staging: [64][33]
    __nv_bfloat16* st = (__nv_bfloat16*)sm;
    __syncthreads();
#pragma unroll
    for (int q = 0; q < 4; q++) {
        st[fg * 33 + ig + q] = __float2bfloat16(e0r[q]);
        st[(fg + 1) * 33 + ig + q] = __float2bfloat16(e1r[q]);
    }
    __syncthreads();
    for (int idx = tid; idx < 2048; idx += 256) {
        int k = idx >> 5, i2 = idx & 31;
        g_EbfT[(((size_t)bb * 64 + k) << 10) + n0 + i2] = st[k * 33 + i2];
    }
}

// ---------------- shortcut: SC = x @ W^T + b (3-term), plus T — 3-stage ring ----------------
#define SC_OFF_A 0
#define SC_OFF_B 15360
#define SC_OFF_T 66048
#define SC_SMEM  66304
__global__ __launch_bounds__(256) void shortcut_kernel(const float* __restrict__ attn_b,
                                                       const float* __restrict__ thr_W,
                                                       const float* __restrict__ thr_b) {
    extern __shared__ char smc[];
    __nv_bfloat16* Asp = (__nv_bfloat16*)(smc + SC_OFF_A);   // [3][64][40]
    __nv_bfloat16* Bsp = (__nv_bfloat16*)(smc + SC_OFF_B);   // [3][32][264]
    float* Tp = (float*)(smc + SC_OFF_T);
    int tid = threadIdx.x, w = tid >> 5, lane = tid & 31;
    int m0 = blockIdx.x * 64;
    int lrow = lane & 7, q1 = (lane >> 3) & 1, q2 = lane >> 4;

    if (tid < 64) Tp[tid] = 0.0f;

    float acc[4][4][4];
#pragma unroll
    for (int a = 0; a < 4; a++)
#pragma unroll
        for (int n = 0; n < 4; n++)
#pragma unroll
            for (int r = 0; r < 4; r++) acc[a][n][r] = 0.0f;

#define SC_ISSUE(s, bf_)                                                          \
    {                                                                             \
        int term_ = (s) >> 3, kc_ = (s) & 7;                                      \
        const __nv_bfloat16* Ap_ = (term_ == 1) ? g_xlo : g_xhi;                  \
        const __nv_bfloat16* Bp_ = (term_ == 2) ? g_Wtlo : g_Wthi;                \
        int ar_ = tid >> 2, aseg_ = tid & 3;                                      \
        cp16(smem_u32(&Asp[(bf_) * 2560 + ar_ * 40 + aseg_ * 8]),                 \
             Ap_ + (size_t)(m0 + ar_) * CDIM + kc_ * 32 + aseg_ * 8);             \
        for (int u_ = 0; u_ < 4; u_++) {                                          \
            int id_ = tid + u_ * 256;                                             \
            int br_ = id_ >> 5, bseg_ = id_ & 31;                                 \
            cp16(smem_u32(&Bsp[(bf_) * 8448 + br_ * 264 + bseg_ * 8]),            \
                 Bp_ + (size_t)(kc_ * 32 + br_) * CDIM + bseg_ * 8);              \
        }                                                                         \
        cp_commit();                                                              \
    }

    SC_ISSUE(0, 0);
    SC_ISSUE(1, 1);
    for (int s = 0; s < 24; s++) {
        if (s < 23) cp_wait1(); else cp_wait0();
        __syncthreads();
        int buf = s % 3;
#pragma unroll
        for (int kk = 0; kk < 2; kk++) {
            uint32_t af[4][4];
#pragma unroll
            for (int mt = 0; mt < 4; mt++)
                ldm_x4(af[mt], smem_u32(&Asp[buf * 2560 + (mt * 16 + lrow + q1 * 8) * 40 + kk * 16 + q2 * 8]));
            uint32_t bfr[2][4];
#pragma unroll
            for (int ng = 0; ng < 2; ng++)
                ldm_x4_t(bfr[ng], smem_u32(&Bsp[buf * 8448 + (kk * 16 + lrow + q1 * 8) * 264 + w * 32 + ng * 16 + q2 * 8]));
#pragma unroll
            for (int mt = 0; mt < 4; mt++)
#pragma unroll
                for (int nt = 0; nt < 4; nt++)
                    mma16816(acc[mt][nt], af[mt],
                             bfr[nt >> 1][(nt & 1) * 2], bfr[nt >> 1][(nt & 1) * 2 + 1]);
        }
        if (s + 2 < 24) SC_ISSUE(s + 2, (s + 2) % 3);
    }
#undef SC_ISSUE

    // epilogue: bias, single fp16 stores, T partials
    float pr0[4] = {}, pr1[4] = {};
#pragma unroll
    for (int nt = 0; nt < 4; nt++) {
        int c0 = w * 32 + nt * 8 + (lane & 3) * 2;
        float bb0 = attn_b[c0], bb1 = attn_b[c0 + 1];
        float tw0 = thr_W[c0], tw1 = thr_W[c0 + 1];
#pragma unroll
        for (int mt = 0; mt < 4; mt++) {
            int r0g = m0 + mt * 16 + (lane >> 2);
            float v00 = acc[mt][nt][0] + bb0, v01 = acc[mt][nt][1] + bb1;
            float v10 = acc[mt][nt][2] + bb0, v11 = acc[mt][nt][3] + bb1;
            HPack2 h;
            h.h[0] = __float2half_rn(v00); h.h[1] = __float2half_rn(v01);
            *(uint32_t*)&g_SChf[(size_t)r0g * CDIM + c0] = h.u;
            h.h[0] = __float2half_rn(v10); h.h[1] = __float2half_rn(v11);
            *(uint32_t*)&g_SChf[(size_t)(r0g + 8) * CDIM + c0] = h.u;
            pr0[mt] += v00 * tw0 + v01 * tw1;
            pr1[mt] += v10 * tw0 + v11 * tw1;
        }
    }
#pragma unroll
    for (int mt = 0; mt < 4; mt++) {
        pr0[mt] += __shfl_xor_sync(0xffffffffu, pr0[mt], 1);
        pr0[mt] += __shfl_xor_sync(0xffffffffu, pr0[mt], 2);
        pr1[mt] += __shfl_xor_sync(0xffffffffu, pr1[mt], 1);
        pr1[mt] += __shfl_xor_sync(0xffffffffu, pr1[mt], 2);
        if ((lane & 3) == 0) {
            atomicAdd(&Tp[mt * 16 + (lane >> 2)], pr0[mt]);
            atomicAdd(&Tp[mt * 16 + (lane >> 2) + 8], pr1[mt]);
        }
    }
    __syncthreads();
    if (tid < 64) g_T[m0 + tid] = Tp[tid] + thr_b[0];
}

// ---------------- attention matrix kernel: single-term bf16 Gram, 4-deep ring, 1 barrier/stage ----------------
#define S_PITCH 1044
#define OFF_S    0
#define OFF_EIH  133632
#define OFF_BH   138240
#define OFF_TSH  207872
#define OFF_SQJ  211968
#define ATTN_SMEM 216064

__global__ __launch_bounds__(1024) void attn_A_kernel() {
    extern __shared__ char smc[];
    float* S = (float*)(smc + OFF_S);                         // [32][1044]
    __nv_bfloat16* Eih = (__nv_bfloat16*)(smc + OFF_EIH);     // [32][72]
    __nv_bfloat16* BhS = (__nv_bfloat16*)(smc + OFF_BH);      // [4][64][136]
    float* Tsh = (float*)(smc + OFF_TSH);
    float* Sqj = (float*)(smc + OFF_SQJ);

    int tid = threadIdx.x;
    int tile = blockIdx.x, b = blockIdx.y;
    int i0 = tile * 32;
    int base = b * HW;
    int w = tid >> 5, lane = tid & 31;
    int lrow = lane & 7, q1 = (lane >> 3) & 1, q2 = lane >> 4;
    int mt = w & 1, ncol = w >> 1;         // 32 warps: 2 row-halves x 16 col-tiles of 8

    Tsh[tid] = g_T[base + tid];
    Sqj[tid] = g_sq[base + tid];

    // hoisted cp.async addresses (affine in jc, buf)
    uint32_t dA = smem_u32(BhS) + ((tid >> 4) * 136 + (tid & 15) * 8) * 2;
    const __nv_bfloat16* sA = g_EbfT + (((size_t)b * 64 + (tid >> 4)) << 10) + (tid & 15) * 8;

#define AT_ISSUE(jc)                                                              \
    {                                                                             \
        cp16(dA + ((jc) & 3) * 17408, sA + (jc) * 128);                           \
        cp_commit();                                                              \
    }

    // prologue: Ei joins group 0; issue stages 0,1,2
    if (tid < 256) {
        int r = tid >> 3, seg = tid & 7;
        cp16(smem_u32(Eih + r * 72 + seg * 8),
             g_Ebf + (size_t)(base + i0 + r) * 64 + seg * 8);
    }
    AT_ISSUE(0);
    AT_ISSUE(1);
    AT_ISSUE(2);

    // per-lane constants (float-domain mask math; all values integer-exact)
    int r0 = mt * 16 + (lane >> 2);
    int ig0 = i0 + r0, ig1 = ig0 + 8;
    float yi0f = (float)(ig0 >> 5), xi0f = (float)(ig0 & 31);
    float yi1f = (float)(ig1 >> 5), xi1f = (float)(ig1 & 31);
    float sqi0 = g_sq[base + ig0];
    float sqi1 = g_sq[base + ig1];
    int brow = (lane & 7) + ((lane >> 3) & 1) * 8;
    int jlow = ncol * 8 + (lane & 3) * 2;
    float yjf = (float)(jlow >> 5);           // += 4 per jc
    float xjf = (float)(jlow & 31);           // constant across jc
    float dx00 = fabsf(xi0f - xjf), dx01 = fabsf(xi0f - xjf - 1.0f);
    float dx10 = fabsf(xi1f - xjf), dx11 = fabsf(xi1f - xjf - 1.0f);
    const float* Sqjb = Sqj + jlow;
    float* Srow0 = S + r0 * S_PITCH + jlow;
    float* Srow1 = Srow0 + 8 * S_PITCH;
    uint32_t bhl = smem_u32(BhS) + (brow * 136 + ncol * 8) * 2;

    uint32_t Ah[4][4];

    // ---- Phase A: 8 stages, one barrier per stage (4-deep ring) ----
    for (int jc = 0; jc < 8; jc++) {
        if (jc <= 5) cp_wait2(); else if (jc == 6) cp_wait1(); else cp_wait0();
        __syncthreads();
        if (jc == 0) {
#pragma unroll
            for (int kc = 0; kc < 4; kc++)
                ldm_x4(Ah[kc], smem_u32(&Eih[(mt * 16 + lrow + q1 * 8) * 72 + kc * 16 + q2 * 8]));
        }
        if (jc < 5) AT_ISSUE(jc + 3);   // targets buffer consumed at jc-1 (safe post-barrier)
        uint32_t bufoff = (jc & 3) * 17408;
        float acc[4] = {};
#pragma unroll
        for (int kc = 0; kc < 4; kc++) {
            uint32_t bh[2];
            ldm_x2_t(bh, bhl + bufoff + kc * 4352);
            mma16816(acc, Ah[kc], bh[0], bh[1]);
        }
        float sq0 = Sqjb[0], sq1 = Sqjb[1];
        float dy0 = fabsf(yi0f - yjf);
        float dy1 = fabsf(yi1f - yjf);
        {
            float d2a = fmaxf(sqi0 + sq0 - 2.0f * acc[0], 0.0f);
            float d2b = fmaxf(sqi0 + sq1 - 2.0f * acc[1], 0.0f);
            float da = dy0 + dx00, db = dy0 + dx01;
            float ma = (da <= 32.0f) ? da * (1.0f / 32.0f) : 0.0f;
            float mb = (db <= 32.0f) ? db * (1.0f / 32.0f) : 0.0f;
            *(float2*)Srow0 = make_float2(__expf(-d2a) - 1.0f + ma, __expf(-d2b) - 1.0f + mb);
        }
        {
            float d2a = fmaxf(sqi1 + sq0 - 2.0f * acc[2], 0.0f);
            float d2b = fmaxf(sqi1 + sq1 - 2.0f * acc[3], 0.0f);
            float da = dy1 + dx10, db = dy1 + dx11;
            float ma = (da <= 32.0f) ? da * (1.0f / 32.0f) : 0.0f;
            float mb = (db <= 32.0f) ? db * (1.0f / 32.0f) : 0.0f;
            *(float2*)Srow1 = make_float2(__expf(-d2a) - 1.0f + ma, __expf(-d2b) - 1.0f + mb);
        }
        yjf += 4.0f;
        Sqjb += 128; Srow0 += 128; Srow1 += 128;
    }
#undef AT_ISSUE
    __syncthreads();   // all of S written before cross-warp phase B reads

    // ---- Phase B: register softmax, 1 row per warp, single fp16 A store ----
    {
        int r = w;
        float* Sr = S + r * S_PITCH;
        float v[32];
#pragma unroll
        for (int t = 0; t < 32; t++) v[t] = Sr[lane + t * 32];
        float m = -1e30f;
#pragma unroll
        for (int t = 0; t < 32; t++) m = fmaxf(m, v[t]);
#pragma unroll
        for (int o = 16; o; o >>= 1) m = fmaxf(m, __shfl_xor_sync(0xffffffffu, m, o));
        float s1 = 0.0f;
#pragma unroll
        for (int t = 0; t < 32; t++) { v[t] = __expf(v[t] - m); s1 += v[t]; }
#pragma unroll
        for (int o = 16; o; o >>= 1) s1 += __shfl_xor_sync(0xffffffffu, s1, o);
        float inv1 = 1.0f / s1;
        float m2 = 0.0f;
#pragma unroll
        for (int t = 0; t < 32; t++) {
            v[t] = fmaxf(v[t] * inv1 - Tsh[lane + t * 32], 0.0f);
            m2 = fmaxf(m2, v[t]);
        }
#pragma unroll
        for (int o = 16; o; o >>= 1) m2 = fmaxf(m2, __shfl_xor_sync(0xffffffffu, m2, o));
        float s2 = 0.0f;
#pragma unroll
        for (int t = 0; t < 32; t++) { v[t] = __expf(v[t] - m2); s2 += v[t]; }
#pragma unroll
        for (int o = 16; o; o >>= 1) s2 += __shfl_xor_sync(0xffffffffu, s2, o);
        float inv2 = 1.0f / s2;

        // repack fp16 into this (now-dead) S row, then coalesced copy out
        __half* rowh = (__half*)Sr;
#pragma unroll
        for (int t = 0; t < 32; t++) {
            rowh[lane + t * 32] = __float2half_rn(v[t] * inv2);
        }
        __syncwarp();
        size_t Ab = ((size_t)b << 20) + ((size_t)(i0 + r) << 10);
        uint4* gh = (uint4*)&g_Af[Ab];
        const uint4* sh = (const uint4*)rowh;
#pragma unroll
        for (int it = 0; it < 4; it++) gh[lane + it * 32] = sh[lane + it * 32];
    }
}

// ---------------- fp16 tensor-core bmm: out = x + A @ SC (single term, k=64 stages) ----------------
#define BMM_OFF_AF 0
#define BMM_OFF_SH 36864
#define BMM_SMEM   71680
__global__ __launch_bounds__(256, 2) void bmm_kernel(const float* __restrict__ x,
                                                     float* __restrict__ out) {
    extern __shared__ char smc[];
    __half* Af_s = (__half*)(smc + BMM_OFF_AF);  // [2][128][72]
    __half* Sh_s = (__half*)(smc + BMM_OFF_SH);  // [2][64][136]
    int tid = threadIdx.x, w = tid >> 5, lane = tid & 31;
    int ct = blockIdx.x, mtb = blockIdx.y, b = blockIdx.z;
    int i0 = mtb * 128, c0 = ct * 128;

    const __half* Af = g_Af + ((size_t)b << 20) + (size_t)i0 * 1024;
    const __half* Shf = g_SChf + ((size_t)b << 18) + c0;

    float acc[4][4][4];
#pragma unroll
    for (int a = 0; a < 4; a++)
#pragma unroll
        for (int n = 0; n < 4; n++)
#pragma unroll
            for (int r = 0; r < 4; r++) acc[a][n][r] = 0.0f;

    int wm = w >> 2, wn = w & 3;
    int lrow = lane & 7, q1 = (lane >> 3) & 1, q2 = lane >> 4;

#define ISSUE(jc, bf_)                                                            \
    {                                                                             \
        for (int u_ = 0; u_ < 4; u_++) {                                          \
            int id_ = tid + u_ * 256;                                             \
            int ar_ = id_ >> 3, aseg_ = id_ & 7;                                  \
            cp16(smem_u32(&Af_s[(bf_) * 9216 + ar_ * 72 + aseg_ * 8]),            \
                 Af + (size_t)ar_ * 1024 + (jc) * 64 + aseg_ * 8);                \
            int sr_ = id_ >> 4, sseg_ = id_ & 15;                                 \
            cp16(smem_u32(&Sh_s[(bf_) * 8704 + sr_ * 136 + sseg_ * 8]),           \
                 Shf + (size_t)((jc) * 64 + sr_) * 256 + sseg_ * 8);              \
        }                                                                         \
        cp_commit();                                                              \
    }

    ISSUE(0, 0);
    ISSUE(1, 1);
    for (int cc = 0; cc < 16; cc++) {
        if (cc < 15) cp_wait1(); else cp_wait0();
        __syncthreads();
        int buf = cc & 1;
#pragma unroll
        for (int kk = 0; kk < 4; kk++) {
            uint32_t af[4][4];
#pragma unroll
            for (int mtl = 0; mtl < 4; mtl++) {
                int row = wm * 64 + mtl * 16 + lrow + q1 * 8;
                int col = kk * 16 + q2 * 8;
                ldm_x4(af[mtl], smem_u32(&Af_s[buf * 9216 + row * 72 + col]));
            }
            uint32_t bh[2][4];
#pragma unroll
            for (int ng = 0; ng < 2; ng++) {
                int row = kk * 16 + lrow + q1 * 8;
                int col = wn * 32 + ng * 16 + q2 * 8;
                ldm_x4_t(bh[ng], smem_u32(&Sh_s[buf * 8704 + row * 136 + col]));
            }
#pragma unroll
            for (int mtl = 0; mtl < 4; mtl++)
#pragma unroll
                for (int nt = 0; nt < 4; nt++)
                    mma16816h(acc[mtl][nt], af[mtl],
                              bh[nt >> 1][(nt & 1) * 2], bh[nt >> 1][(nt & 1) * 2 + 1]);
        }
        __syncthreads();   // all warps done with buf before it is overwritten
        if (cc + 2 < 16) ISSUE(cc + 2, cc & 1);
    }
#undef ISSUE

    int g = lane >> 2, t2 = lane & 3;
#pragma unroll
    for (int mtl = 0; mtl < 4; mtl++) {
#pragma unroll
        for (int nt = 0; nt < 4; nt++) {
            int row = i0 + wm * 64 + mtl * 16 + g;
            int col = c0 + wn * 32 + nt * 8 + 2 * t2;
            size_t o0 = ((size_t)b * 1024 + row) * 256 + col;
            size_t o1 = o0 + 8 * 256;
            float2 xv0 = *(const float2*)&x[o0];
            float2 xv1 = *(const float2*)&x[o1];
            *(float2*)&out[o0] = make_float2(xv0.x + acc[mtl][nt][0], xv0.y + acc[mtl][nt][1]);
            *(float2*)&out[o1] = make_float2(xv1.x + acc[mtl][nt][2], xv1.y + acc[mtl][nt][3]);
        }
    }
}

// ---------------- launch ----------------
extern "C" void kernel_launch(void* const* d_in, const int* in_sizes, int n_in,
                              void* d_out, int out_size) {
    const float* x      = (const float*)d_in[0];
    const float* emb_W  = (const float*)d_in[1];
    const float* emb_b  = (const float*)d_in[2];
    const float* attn_W = (const float*)d_in[3];
    const float* attn_b = (const float*)d_in[4];
    const float* thr_W  = (const float*)d_in[5];
    const float* thr_b  = (const float*)d_in[6];
    float* out = (float*)d_out;

    cudaFuncSetAttribute(emb_kernel, cudaFuncAttributeMaxDynamicSharedMemorySize, EMB_SMEM);
    cudaFuncSetAttribute(shortcut_kernel, cudaFuncAttributeMaxDynamicSharedMemorySize, SC_SMEM);
    cudaFuncSetAttribute(attn_A_kernel, cudaFuncAttributeMaxDynamicSharedMemorySize, ATTN_SMEM);
    cudaFuncSetAttribute(bmm_kernel, cudaFuncAttributeMaxDynamicSharedMemorySize, BMM_SMEM);

    prep_kernel<<<256, 256>>>(attn_W, emb_W);
    emb_kernel<<<BATCH * HW / 32, 256, EMB_SMEM>>>(x, emb_b);
    shortcut_kernel<<<BATCH * HW / 64, 256, SC_SMEM>>>(attn_b, thr_W, thr_b);
    attn_A_kernel<<<dim3(HW / 32, BATCH), 1024, ATTN_SMEM>>>();
    bmm_kernel<<<dim3(CDIM / 128, HW / 128, BATCH), 256, BMM_SMEM>>>(x, out);
}

// round 15
// speedup vs baseline: 2.2542x; 1.1993x over previous
#include <cuda_runtime.h>
#include <cuda_bf16.h>
#include <cuda_fp16.h>
#include <math.h>
#include <stdint.h>

#define BATCH 32
#define HW    1024
#define CDIM  256
#define FDIM  64

// ---------------- scratch (device globals; no allocations) ----------------
__device__ float g_sq[BATCH * HW];
__device__ float g_T[BATCH * HW];
__device__ __nv_bfloat16 g_Ebf[BATCH * HW * FDIM];       // bf16(emb) [n][k]
__device__ __nv_bfloat16 g_EbfT[BATCH * FDIM * HW];      // [b][k][n]
__device__ __nv_bfloat16 g_xhi[BATCH * HW * CDIM];
__device__ __nv_bfloat16 g_xlo[BATCH * HW * CDIM];
__device__ __half g_SChf[BATCH * HW * CDIM];             // single fp16 SC
__device__ __half g_Af[(size_t)BATCH * HW * HW];         // 64 MB, single fp16 A
__device__ __nv_bfloat16 g_Wthi[CDIM * CDIM];            // attn_W^T split [cin][cout]
__device__ __nv_bfloat16 g_Wtlo[CDIM * CDIM];
__device__ __nv_bfloat16 g_Wembf[CDIM * FDIM];           // bf16(emb_W^T) [ci][f]

// ---------------- small helpers ----------------
__device__ __forceinline__ uint32_t smem_u32(const void* p) {
    return (uint32_t)__cvta_generic_to_shared(p);
}
__device__ __forceinline__ void cp16(uint32_t dst, const void* src) {
    asm volatile("cp.async.cg.shared.global [%0], [%1], 16;\n" :: "r"(dst), "l"(src));
}
__device__ __forceinline__ void cp_commit() { asm volatile("cp.async.commit_group;\n"); }
__device__ __forceinline__ void cp_wait2() { asm volatile("cp.async.wait_group 2;\n"); }
__device__ __forceinline__ void cp_wait1() { asm volatile("cp.async.wait_group 1;\n"); }
__device__ __forceinline__ void cp_wait0() { asm volatile("cp.async.wait_group 0;\n"); }
__device__ __forceinline__ void ldm_x4(uint32_t (&r)[4], uint32_t addr) {
    asm volatile("ldmatrix.sync.aligned.m8n8.x4.shared.b16 {%0,%1,%2,%3}, [%4];"
                 : "=r"(r[0]), "=r"(r[1]), "=r"(r[2]), "=r"(r[3]) : "r"(addr));
}
__device__ __forceinline__ void ldm_x4_t(uint32_t (&r)[4], uint32_t addr) {
    asm volatile("ldmatrix.sync.aligned.m8n8.x4.trans.shared.b16 {%0,%1,%2,%3}, [%4];"
                 : "=r"(r[0]), "=r"(r[1]), "=r"(r[2]), "=r"(r[3]) : "r"(addr));
}
__device__ __forceinline__ void ldm_x2_t(uint32_t (&r)[2], uint32_t addr) {
    asm volatile("ldmatrix.sync.aligned.m8n8.x2.trans.shared.b16 {%0,%1}, [%2];"
                 : "=r"(r[0]), "=r"(r[1]) : "r"(addr));
}
// bf16 mma
__device__ __forceinline__ void mma16816(float (&d)[4], const uint32_t (&a)[4],
                                         uint32_t b0, uint32_t b1) {
    asm volatile("mma.sync.aligned.m16n8k16.row.col.f32.bf16.bf16.f32 "
                 "{%0,%1,%2,%3}, {%4,%5,%6,%7}, {%8,%9}, {%0,%1,%2,%3};"
                 : "+f"(d[0]), "+f"(d[1]), "+f"(d[2]), "+f"(d[3])
                 : "r"(a[0]), "r"(a[1]), "r"(a[2]), "r"(a[3]), "r"(b0), "r"(b1));
}
// fp16 mma
__device__ __forceinline__ void mma16816h(float (&d)[4], const uint32_t (&a)[4],
                                          uint32_t b0, uint32_t b1) {
    asm volatile("mma.sync.aligned.m16n8k16.row.col.f32.f16.f16.f32 "
                 "{%0,%1,%2,%3}, {%4,%5,%6,%7}, {%8,%9}, {%0,%1,%2,%3};"
                 : "+f"(d[0]), "+f"(d[1]), "+f"(d[2]), "+f"(d[3])
                 : "r"(a[0]), "r"(a[1]), "r"(a[2]), "r"(a[3]), "r"(b0), "r"(b1));
}
union BPack2 { __nv_bfloat16 h[2]; uint32_t u; };
union BPack4 { __nv_bfloat16 h[4]; uint2 u; };
union HPack2 { __half h[2]; uint32_t u; };

// ---------------- prep: weight transposes + bf16 splits ----------------
__global__ void prep_kernel(const float* __restrict__ attn_W,
                            const float* __restrict__ emb_W) {
    int t = blockIdx.x * 256 + threadIdx.x;
    if (t < CDIM * CDIM) {
        int ci = t >> 8, co = t & 255;
        float v = attn_W[co * CDIM + ci];
        __nv_bfloat16 h = __float2bfloat16(v);
        g_Wthi[ci * CDIM + co] = h;
        g_Wtlo[ci * CDIM + co] = __float2bfloat16(v - __bfloat162float(h));
    }
    if (t < FDIM * CDIM) {
        int f = t >> 8, ci = t & 255;
        g_Wembf[ci * FDIM + f] = __float2bfloat16(emb_W[f * CDIM + ci]);
    }
}

// ---------------- x split kernel ----------------
__global__ __launch_bounds__(256) void xsplit_kernel(const float* __restrict__ x) {
    int i4 = blockIdx.x * 256 + threadIdx.x;        // over N/4
    float4 v = ((const float4*)x)[i4];
    float vv[4] = {v.x, v.y, v.z, v.w};
    BPack4 ph, pl;
#pragma unroll
    for (int q = 0; q < 4; q++) {
        __nv_bfloat16 h = __float2bfloat16(vv[q]);
        ph.h[q] = h;
        pl.h[q] = __float2bfloat16(vv[q] - __bfloat162float(h));
    }
    ((uint2*)g_xhi)[i4] = ph.u;
    ((uint2*)g_xlo)[i4] = pl.u;
}

// ---------------- emb via tensor cores: E = xhi @ Wembf + b; Ebf, EbfT, sq ----------------
// 256 threads, 128-row tiles, W resident (pitch 72: rows 16B-aligned for ldmatrix),
// 3-buffer A ring (1 barrier/stage).
#define EM_OFF_W 0
#define EM_OFF_A 36864
#define EM_SMEM  67584
__global__ __launch_bounds__(256) void emb_mma_kernel(const float* __restrict__ emb_b) {
    extern __shared__ char smc[];
    __nv_bfloat16* Wsm = (__nv_bfloat16*)(smc + EM_OFF_W);   // [256][72]
    __nv_bfloat16* Asp = (__nv_bfloat16*)(smc + EM_OFF_A);   // [3][128][40]
    __nv_bfloat16* Est = (__nv_bfloat16*)(smc + EM_OFF_A);   // [64][136] (reused post-loop)
    int tid = threadIdx.x, w = tid >> 5, lane = tid & 31;
    int blk = blockIdx.x;
    int row0 = blk * 128;                 // flattened b*HW+n
    int b = blk >> 3, n0 = (blk & 7) * 128;
    int lrow = lane & 7, q1 = (lane >> 3) & 1, q2 = lane >> 4;

    // resident W load (overlaps cp.async ring fill)
    for (int i = tid; i < 256 * 16; i += 256) {
        int k = i >> 4, seg = i & 15;
        *(uint2*)&Wsm[k * 72 + seg * 4] = ((const uint2*)g_Wembf)[k * 16 + seg];
    }

#define EM_ISSUE(s, bf_)                                                          \
    {                                                                             \
        for (int u_ = 0; u_ < 2; u_++) {                                          \
            int id_ = tid + u_ * 256;                                             \
            int ar_ = id_ >> 2, aseg_ = id_ & 3;                                  \
            cp16(smem_u32(&Asp[(bf_) * 5120 + ar_ * 40 + aseg_ * 8]),             \
                 g_xhi + (size_t)(row0 + ar_) * CDIM + (s) * 32 + aseg_ * 8);     \
        }                                                                         \
        cp_commit();                                                              \
    }

    EM_ISSUE(0, 0);
    EM_ISSUE(1, 1);

    float acc[4][2][4];
#pragma unroll
    for (int nt = 0; nt < 4; nt++)
#pragma unroll
        for (int h = 0; h < 2; h++)
#pragma unroll
            for (int r = 0; r < 4; r++) acc[nt][h][r] = 0.0f;

    for (int s = 0; s < 8; s++) {
        if (s < 7) cp_wait1(); else cp_wait0();
        __syncthreads();
        int buf = s % 3;
#pragma unroll
        for (int kk = 0; kk < 2; kk++) {
            uint32_t af[4];
            ldm_x4(af, smem_u32(&Asp[buf * 5120 + (w * 16 + lrow + q1 * 8) * 40 + kk * 16 + q2 * 8]));
#pragma unroll
            for (int nt = 0; nt < 4; nt++) {
                uint32_t bf[4];
                ldm_x4_t(bf, smem_u32(&Wsm[(s * 32 + kk * 16 + lrow + q1 * 8) * 72 + nt * 16 + q2 * 8]));
                mma16816(acc[nt][0], af, bf[0], bf[1]);
                mma16816(acc[nt][1], af, bf[2], bf[3]);
            }
        }
        if (s + 2 < 8) EM_ISSUE(s + 2, (s + 2) % 3);
    }
#undef EM_ISSUE

    // epilogue: bias, Ebf stores, sq; then staged transpose
    int r0 = w * 16 + (lane >> 2);
    int rl1 = r0 + 8;
    float sq0 = 0.0f, sq1 = 0.0f;
    float e0s[4][2][2], e1s[4][2][2];
#pragma unroll
    for (int nt = 0; nt < 4; nt++) {
#pragma unroll
        for (int h = 0; h < 2; h++) {
            int c = nt * 16 + h * 8 + (lane & 3) * 2;
            float bb0 = emb_b[c], bb1 = emb_b[c + 1];
            float e00 = acc[nt][h][0] + bb0, e01 = acc[nt][h][1] + bb1;
            float e10 = acc[nt][h][2] + bb0, e11 = acc[nt][h][3] + bb1;
            e0s[nt][h][0] = e00; e0s[nt][h][1] = e01;
            e1s[nt][h][0] = e10; e1s[nt][h][1] = e11;
            sq0 += e00 * e00 + e01 * e01;
            sq1 += e10 * e10 + e11 * e11;
            BPack2 p;
            p.h[0] = __float2bfloat16(e00); p.h[1] = __float2bfloat16(e01);
            *(uint32_t*)&g_Ebf[(size_t)(row0 + r0) * FDIM + c] = p.u;
            p.h[0] = __float2bfloat16(e10); p.h[1] = __float2bfloat16(e11);
            *(uint32_t*)&g_Ebf[(size_t)(row0 + rl1) * FDIM + c] = p.u;
        }
    }
    sq0 += __shfl_xor_sync(0xffffffffu, sq0, 1);
    sq0 += __shfl_xor_sync(0xffffffffu, sq0, 2);
    sq1 += __shfl_xor_sync(0xffffffffu, sq1, 1);
    sq1 += __shfl_xor_sync(0xffffffffu, sq1, 2);
    if ((lane & 3) == 0) {
        g_sq[row0 + r0] = sq0;
        g_sq[row0 + rl1] = sq1;
    }

    __syncthreads();   // all warps done reading Asp before Est overwrites it
#pragma unroll
    for (int nt = 0; nt < 4; nt++)
#pragma unroll
        for (int h = 0; h < 2; h++) {
            int c = nt * 16 + h * 8 + (lane & 3) * 2;
            Est[c * 136 + r0] = __float2bfloat16(e0s[nt][h][0]);
            Est[(c + 1) * 136 + r0] = __float2bfloat16(e0s[nt][h][1]);
            Est[c * 136 + rl1] = __float2bfloat16(e1s[nt][h][0]);
            Est[(c + 1) * 136 + rl1] = __float2bfloat16(e1s[nt][h][1]);
        }
    __syncthreads();
    for (int i = tid; i < 1024; i += 256) {
        int k = i >> 4, seg = i & 15;
        *(uint4*)&g_EbfT[(((size_t)b * 64 + k) << 10) + n0 + seg * 8] =
            *(const uint4*)&Est[k * 136 + seg * 8];
    }
}

// ---------------- shortcut: SC = x @ W^T + b (3-term), plus T — 3-stage ring ----------------
#define SC_OFF_A 0
#define SC_OFF_B 15360
#define SC_OFF_T 66048
#define SC_SMEM  66304
__global__ __launch_bounds__(256) void shortcut_kernel(const float* __restrict__ attn_b,
                                                       const float* __restrict__ thr_W,
                                                       const float* __restrict__ thr_b) {
    extern __shared__ char smc[];
    __nv_bfloat16* Asp = (__nv_bfloat16*)(smc + SC_OFF_A);   // [3][64][40]
    __nv_bfloat16* Bsp = (__nv_bfloat16*)(smc + SC_OFF_B);   // [3][32][264]
    float* Tp = (float*)(smc + SC_OFF_T);
    int tid = threadIdx.x, w = tid >> 5, lane = tid & 31;
    int m0 = blockIdx.x * 64;
    int lrow = lane & 7, q1 = (lane >> 3) & 1, q2 = lane >> 4;

    if (tid < 64) Tp[tid] = 0.0f;

    float acc[4][4][4];
#pragma unroll
    for (int a = 0; a < 4; a++)
#pragma unroll
        for (int n = 0; n < 4; n++)
#pragma unroll
            for (int r = 0; r < 4; r++) acc[a][n][r] = 0.0f;

#define SC_ISSUE(s, bf_)                                                          \
    {                                                                             \
        int term_ = (s) >> 3, kc_ = (s) & 7;                                      \
        const __nv_bfloat16* Ap_ = (term_ == 1) ? g_xlo : g_xhi;                  \
        const __nv_bfloat16* Bp_ = (term_ == 2) ? g_Wtlo : g_Wthi;                \
        int ar_ = tid >> 2, aseg_ = tid & 3;                                      \
        cp16(smem_u32(&Asp[(bf_) * 2560 + ar_ * 40 + aseg_ * 8]),                 \
             Ap_ + (size_t)(m0 + ar_) * CDIM + kc_ * 32 + aseg_ * 8);             \
        for (int u_ = 0; u_ < 4; u_++) {                                          \
            int id_ = tid + u_ * 256;                                             \
            int br_ = id_ >> 5, bseg_ = id_ & 31;                                 \
            cp16(smem_u32(&Bsp[(bf_) * 8448 + br_ * 264 + bseg_ * 8]),            \
                 Bp_ + (size_t)(kc_ * 32 + br_) * CDIM + bseg_ * 8);              \
        }                                                                         \
        cp_commit();                                                              \
    }

    SC_ISSUE(0, 0);
    SC_ISSUE(1, 1);
    for (int s = 0; s < 24; s++) {
        if (s < 23) cp_wait1(); else cp_wait0();
        __syncthreads();
        int buf = s % 3;
#pragma unroll
        for (int kk = 0; kk < 2; kk++) {
            uint32_t af[4][4];
#pragma unroll
            for (int mt = 0; mt < 4; mt++)
                ldm_x4(af[mt], smem_u32(&Asp[buf * 2560 + (mt * 16 + lrow + q1 * 8) * 40 + kk * 16 + q2 * 8]));
            uint32_t bfr[2][4];
#pragma unroll
            for (int ng = 0; ng < 2; ng++)
                ldm_x4_t(bfr[ng], smem_u32(&Bsp[buf * 8448 + (kk * 16 + lrow + q1 * 8) * 264 + w * 32 + ng * 16 + q2 * 8]));
#pragma unroll
            for (int mt = 0; mt < 4; mt++)
#pragma unroll
                for (int nt = 0; nt < 4; nt++)
                    mma16816(acc[mt][nt], af[mt],
                             bfr[nt >> 1][(nt & 1) * 2], bfr[nt >> 1][(nt & 1) * 2 + 1]);
        }
        if (s + 2 < 24) SC_ISSUE(s + 2, (s + 2) % 3);
    }
#undef SC_ISSUE

    // epilogue: bias, single fp16 stores, T partials
    float pr0[4] = {}, pr1[4] = {};
#pragma unroll
    for (int nt = 0; nt < 4; nt++) {
        int c0 = w * 32 + nt * 8 + (lane & 3) * 2;
        float bb0 = attn_b[c0], bb1 = attn_b[c0 + 1];
        float tw0 = thr_W[c0], tw1 = thr_W[c0 + 1];
#pragma unroll
        for (int mt = 0; mt < 4; mt++) {
            int r0g = m0 + mt * 16 + (lane >> 2);
            float v00 = acc[mt][nt][0] + bb0, v01 = acc[mt][nt][1] + bb1;
            float v10 = acc[mt][nt][2] + bb0, v11 = acc[mt][nt][3] + bb1;
            HPack2 h;
            h.h[0] = __float2half_rn(v00); h.h[1] = __float2half_rn(v01);
            *(uint32_t*)&g_SChf[(size_t)r0g * CDIM + c0] = h.u;
            h.h[0] = __float2half_rn(v10); h.h[1] = __float2half_rn(v11);
            *(uint32_t*)&g_SChf[(size_t)(r0g + 8) * CDIM + c0] = h.u;
            pr0[mt] += v00 * tw0 + v01 * tw1;
            pr1[mt] += v10 * tw0 + v11 * tw1;
        }
    }
#pragma unroll
    for (int mt = 0; mt < 4; mt++) {
        pr0[mt] += __shfl_xor_sync(0xffffffffu, pr0[mt], 1);
        pr0[mt] += __shfl_xor_sync(0xffffffffu, pr0[mt], 2);
        pr1[mt] += __shfl_xor_sync(0xffffffffu, pr1[mt], 1);
        pr1[mt] += __shfl_xor_sync(0xffffffffu, pr1[mt], 2);
        if ((lane & 3) == 0) {
            atomicAdd(&Tp[mt * 16 + (lane >> 2)], pr0[mt]);
            atomicAdd(&Tp[mt * 16 + (lane >> 2) + 8], pr1[mt]);
        }
    }
    __syncthreads();
    if (tid < 64) g_T[m0 + tid] = Tp[tid] + thr_b[0];
}

// ---------------- attention matrix kernel: single-term bf16 Gram, 4-deep ring, 1 barrier/stage ----------------
#define S_PITCH 1044
#define OFF_S    0
#define OFF_EIH  133632
#define OFF_BH   138240
#define OFF_TSH  207872
#define OFF_SQJ  211968
#define ATTN_SMEM 216064

__global__ __launch_bounds__(1024) void attn_A_kernel() {
    extern __shared__ char smc[];
    float* S = (float*)(smc + OFF_S);                         // [32][1044]
    __nv_bfloat16* Eih = (__nv_bfloat16*)(smc + OFF_EIH);     // [32][72]
    __nv_bfloat16* BhS = (__nv_bfloat16*)(smc + OFF_BH);      // [4][64][136]
    float* Tsh = (float*)(smc + OFF_TSH);
    float* Sqj = (float*)(smc + OFF_SQJ);

    int tid = threadIdx.x;
    int tile = blockIdx.x, b = blockIdx.y;
    int i0 = tile * 32;
    int base = b * HW;
    int w = tid >> 5, lane = tid & 31;
    int lrow = lane & 7, q1 = (lane >> 3) & 1, q2 = lane >> 4;
    int mt = w & 1, ncol = w >> 1;

    Tsh[tid] = g_T[base + tid];
    Sqj[tid] = g_sq[base + tid];

    uint32_t dA = smem_u32(BhS) + ((tid >> 4) * 136 + (tid & 15) * 8) * 2;
    const __nv_bfloat16* sA = g_EbfT + (((size_t)b * 64 + (tid >> 4)) << 10) + (tid & 15) * 8;

#define AT_ISSUE(jc)                                                              \
    {                                                                             \
        cp16(dA + ((jc) & 3) * 17408, sA + (jc) * 128);                           \
        cp_commit();                                                              \
    }

    if (tid < 256) {
        int r = tid >> 3, seg = tid & 7;
        cp16(smem_u32(Eih + r * 72 + seg * 8),
             g_Ebf + (size_t)(base + i0 + r) * 64 + seg * 8);
    }
    AT_ISSUE(0);
    AT_ISSUE(1);
    AT_ISSUE(2);

    int r0 = mt * 16 + (lane >> 2);
    int ig0 = i0 + r0, ig1 = ig0 + 8;
    float yi0f = (float)(ig0 >> 5), xi0f = (float)(ig0 & 31);
    float yi1f = (float)(ig1 >> 5), xi1f = (float)(ig1 & 31);
    float sqi0 = g_sq[base + ig0];
    float sqi1 = g_sq[base + ig1];
    int brow = (lane & 7) + ((lane >> 3) & 1) * 8;
    int jlow = ncol * 8 + (lane & 3) * 2;
    float yjf = (float)(jlow >> 5);
    float xjf = (float)(jlow & 31);
    float dx00 = fabsf(xi0f - xjf), dx01 = fabsf(xi0f - xjf - 1.0f);
    float dx10 = fabsf(xi1f - xjf), dx11 = fabsf(xi1f - xjf - 1.0f);
    const float* Sqjb = Sqj + jlow;
    float* Srow0 = S + r0 * S_PITCH + jlow;
    float* Srow1 = Srow0 + 8 * S_PITCH;
    uint32_t bhl = smem_u32(BhS) + (brow * 136 + ncol * 8) * 2;

    uint32_t Ah[4][4];

    for (int jc = 0; jc < 8; jc++) {
        if (jc <= 5) cp_wait2(); else if (jc == 6) cp_wait1(); else cp_wait0();
        __syncthreads();
        if (jc == 0) {
#pragma unroll
            for (int kc = 0; kc < 4; kc++)
                ldm_x4(Ah[kc], smem_u32(&Eih[(mt * 16 + lrow + q1 * 8) * 72 + kc * 16 + q2 * 8]));
        }
        if (jc < 5) AT_ISSUE(jc + 3);
        uint32_t bufoff = (jc & 3) * 17408;
        float acc[4] = {};
#pragma unroll
        for (int kc = 0; kc < 4; kc++) {
            uint32_t bh[2];
            ldm_x2_t(bh, bhl + bufoff + kc * 4352);
            mma16816(acc, Ah[kc], bh[0], bh[1]);
        }
        float sq0 = Sqjb[0], sq1 = Sqjb[1];
        float dy0 = fabsf(yi0f - yjf);
        float dy1 = fabsf(yi1f - yjf);
        {
            float d2a = fmaxf(sqi0 + sq0 - 2.0f * acc[0], 0.0f);
            float d2b = fmaxf(sqi0 + sq1 - 2.0f * acc[1], 0.0f);
            float da = dy0 + dx00, db = dy0 + dx01;
            float ma = (da <= 32.0f) ? da * (1.0f / 32.0f) : 0.0f;
            float mb = (db <= 32.0f) ? db * (1.0f / 32.0f) : 0.0f;
            *(float2*)Srow0 = make_float2(__expf(-d2a) - 1.0f + ma, __expf(-d2b) - 1.0f + mb);
        }
        {
            float d2a = fmaxf(sqi1 + sq0 - 2.0f * acc[2], 0.0f);
            float d2b = fmaxf(sqi1 + sq1 - 2.0f * acc[3], 0.0f);
            float da = dy1 + dx10, db = dy1 + dx11;
            float ma = (da <= 32.0f) ? da * (1.0f / 32.0f) : 0.0f;
            float mb = (db <= 32.0f) ? db * (1.0f / 32.0f) : 0.0f;
            *(float2*)Srow1 = make_float2(__expf(-d2a) - 1.0f + ma, __expf(-d2b) - 1.0f + mb);
        }
        yjf += 4.0f;
        Sqjb += 128; Srow0 += 128; Srow1 += 128;
    }
#undef AT_ISSUE
    __syncthreads();

    // ---- Phase B: register softmax, 1 row per warp, single fp16 A store ----
    {
        int r = w;
        float* Sr = S + r * S_PITCH;
        float v[32];
#pragma unroll
        for (int t = 0; t < 32; t++) v[t] = Sr[lane + t * 32];
        float m = -1e30f;
#pragma unroll
        for (int t = 0; t < 32; t++) m = fmaxf(m, v[t]);
#pragma unroll
        for (int o = 16; o; o >>= 1) m = fmaxf(m, __shfl_xor_sync(0xffffffffu, m, o));
        float s1 = 0.0f;
#pragma unroll
        for (int t = 0; t < 32; t++) { v[t] = __expf(v[t] - m); s1 += v[t]; }
#pragma unroll
        for (int o = 16; o; o >>= 1) s1 += __shfl_xor_sync(0xffffffffu, s1, o);
        float inv1 = 1.0f / s1;
        float m2 = 0.0f;
#pragma unroll
        for (int t = 0; t < 32; t++) {
            v[t] = fmaxf(v[t] * inv1 - Tsh[lane + t * 32], 0.0f);
            m2 = fmaxf(m2, v[t]);
        }
#pragma unroll
        for (int o = 16; o; o >>= 1) m2 = fmaxf(m2, __shfl_xor_sync(0xffffffffu, m2, o));
        float s2 = 0.0f;
#pragma unroll
        for (int t = 0; t < 32; t++) { v[t] = __expf(v[t] - m2); s2 += v[t]; }
#pragma unroll
        for (int o = 16; o; o >>= 1) s2 += __shfl_xor_sync(0xffffffffu, s2, o);
        float inv2 = 1.0f / s2;

        __half* rowh = (__half*)Sr;
#pragma unroll
        for (int t = 0; t < 32; t++) {
            rowh[lane + t * 32] = __float2half_rn(v[t] * inv2);
        }
        __syncwarp();
        size_t Ab = ((size_t)b << 20) + ((size_t)(i0 + r) << 10);
        uint4* gh = (uint4*)&g_Af[Ab];
        const uint4* sh = (const uint4*)rowh;
#pragma unroll
        for (int it = 0; it < 4; it++) gh[lane + it * 32] = sh[lane + it * 32];
    }
}

// ---------------- fp16 tensor-core bmm: out = x + A @ SC (single term, k=64 stages) ----------------
#define BMM_OFF_AF 0
#define BMM_OFF_SH 36864
#define BMM_SMEM   71680
__global__ __launch_bounds__(256, 2) void bmm_kernel(const float* __restrict__ x,
                                                     float* __restrict__ out) {
    extern __shared__ char smc[];
    __half* Af_s = (__half*)(smc + BMM_OFF_AF);  // [2][128][72]
    __half* Sh_s = (__half*)(smc + BMM_OFF_SH);  // [2][64][136]
    int tid = threadIdx.x, w = tid >> 5, lane = tid & 31;
    int ct = blockIdx.x, mtb = blockIdx.y, b = blockIdx.z;
    int i0 = mtb * 128, c0 = ct * 128;

    const __half* Af = g_Af + ((size_t)b << 20) + (size_t)i0 * 1024;
    const __half* Shf = g_SChf + ((size_t)b << 18) + c0;

    float acc[4][4][4];
#pragma unroll
    for (int a = 0; a < 4; a++)
#pragma unroll
        for (int n = 0; n < 4; n++)
#pragma unroll
            for (int r = 0; r < 4; r++) acc[a][n][r] = 0.0f;

    int wm = w >> 2, wn = w & 3;
    int lrow = lane & 7, q1 = (lane >> 3) & 1, q2 = lane >> 4;

#define ISSUE(jc, bf_)                                                            \
    {                                                                             \
        for (int u_ = 0; u_ < 4; u_++) {                                          \
            int id_ = tid + u_ * 256;                                             \
            int ar_ = id_ >> 3, aseg_ = id_ & 7;                                  \
            cp16(smem_u32(&Af_s[(bf_) * 9216 + ar_ * 72 + aseg_ * 8]),            \
                 Af + (size_t)ar_ * 1024 + (jc) * 64 + aseg_ * 8);                \
            int sr_ = id_ >> 4, sseg_ = id_ & 15;                                 \
            cp16(smem_u32(&Sh_s[(bf_) * 8704 + sr_ * 136 + sseg_ * 8]),           \
                 Shf + (size_t)((jc) * 64 + sr_) * 256 + sseg_ * 8);              \
        }                                                                         \
        cp_commit();                                                              \
    }

    ISSUE(0, 0);
    ISSUE(1, 1);
    for (int cc = 0; cc < 16; cc++) {
        if (cc < 15) cp_wait1(); else cp_wait0();
        __syncthreads();
        int buf = cc & 1;
#pragma unroll
        for (int kk = 0; kk < 4; kk++) {
            uint32_t af[4][4];
#pragma unroll
            for (int mtl = 0; mtl < 4; mtl++) {
                int row = wm * 64 + mtl * 16 + lrow + q1 * 8;
                int col = kk * 16 + q2 * 8;
                ldm_x4(af[mtl], smem_u32(&Af_s[buf * 9216 + row * 72 + col]));
            }
            uint32_t bh[2][4];
#pragma unroll
            for (int ng = 0; ng < 2; ng++) {
                int row = kk * 16 + lrow + q1 * 8;
                int col = wn * 32 + ng * 16 + q2 * 8;
                ldm_x4_t(bh[ng], smem_u32(&Sh_s[buf * 8704 + row * 136 + col]));
            }
#pragma unroll
            for (int mtl = 0; mtl < 4; mtl++)
#pragma unroll
                for (int nt = 0; nt < 4; nt++)
                    mma16816h(acc[mtl][nt], af[mtl],
                              bh[nt >> 1][(nt & 1) * 2], bh[nt >> 1][(nt & 1) * 2 + 1]);
        }
        __syncthreads();
        if (cc + 2 < 16) ISSUE(cc + 2, cc & 1);
    }
#undef ISSUE

    int g = lane >> 2, t2 = lane & 3;
#pragma unroll
    for (int mtl = 0; mtl < 4; mtl++) {
#pragma unroll
        for (int nt = 0; nt < 4; nt++) {
            int row = i0 + wm * 64 + mtl * 16 + g;
            int col = c0 + wn * 32 + nt * 8 + 2 * t2;
            size_t o0 = ((size_t)b * 1024 + row) * 256 + col;
            size_t o1 = o0 + 8 * 256;
            float2 xv0 = *(const float2*)&x[o0];
            float2 xv1 = *(const float2*)&x[o1];
            *(float2*)&out[o0] = make_float2(xv0.x + acc[mtl][nt][0], xv0.y + acc[mtl][nt][1]);
            *(float2*)&out[o1] = make_float2(xv1.x + acc[mtl][nt][2], xv1.y + acc[mtl][nt][3]);
        }
    }
}

// ---------------- launch ----------------
extern "C" void kernel_launch(void* const* d_in, const int* in_sizes, int n_in,
                              void* d_out, int out_size) {
    const float* x      = (const float*)d_in[0];
    const float* emb_W  = (const float*)d_in[1];
    const float* emb_b  = (const float*)d_in[2];
    const float* attn_W = (const float*)d_in[3];
    const float* attn_b = (const float*)d_in[4];
    const float* thr_W  = (const float*)d_in[5];
    const float* thr_b  = (const float*)d_in[6];
    float* out = (float*)d_out;

    cudaFuncSetAttribute(emb_mma_kernel, cudaFuncAttributeMaxDynamicSharedMemorySize, EM_SMEM);
    cudaFuncSetAttribute(shortcut_kernel, cudaFuncAttributeMaxDynamicSharedMemorySize, SC_SMEM);
    cudaFuncSetAttribute(attn_A_kernel, cudaFuncAttributeMaxDynamicSharedMemorySize, ATTN_SMEM);
    cudaFuncSetAttribute(bmm_kernel, cudaFuncAttributeMaxDynamicSharedMemorySize, BMM_SMEM);

    prep_kernel<<<256, 256>>>(attn_W, emb_W);
    xsplit_kernel<<<BATCH * HW * CDIM / 4 / 256, 256>>>(x);
    emb_mma_kernel<<<BATCH * HW / 128, 256, EM_SMEM>>>(emb_b);
    shortcut_kernel<<<BATCH * HW / 64, 256, SC_SMEM>>>(attn_b, thr_W, thr_b);
    attn_A_kernel<<<dim3(HW / 32, BATCH), 1024, ATTN_SMEM>>>();
    bmm_kernel<<<dim3(CDIM / 128, HW / 128, BATCH), 256, BMM_SMEM>>>(x, out);
}

// round 16
// speedup vs baseline: 2.4267x; 1.0765x over previous
#include <cuda_runtime.h>
#include <cuda_bf16.h>
#include <cuda_fp16.h>
#include <math.h>
#include <stdint.h>

#define BATCH 32
#define HW    1024
#define CDIM  256
#define FDIM  64

// ---------------- scratch (device globals; no allocations) ----------------
__device__ float g_sq[BATCH * HW];
__device__ float g_T[BATCH * HW];
__device__ float g_tvec[CDIM];
__device__ float g_tconst;
__device__ __nv_bfloat16 g_Ebf[BATCH * HW * FDIM];       // bf16(emb) [n][k]
__device__ __nv_bfloat16 g_EbfT[BATCH * FDIM * HW];      // [b][k][n]
__device__ __half g_xf[BATCH * HW * CDIM];               // fp16(x)
__device__ __half g_SChf[BATCH * HW * CDIM];             // fp16 SC
__device__ __half g_Af[(size_t)BATCH * HW * HW];         // 64 MB, fp16 A
__device__ __half g_Wtf[CDIM * CDIM];                    // fp16(attn_W^T) [cin][cout]
__device__ __half g_Wembf[CDIM * FDIM];                  // fp16(emb_W^T) [ci][f]

// ---------------- small helpers ----------------
__device__ __forceinline__ uint32_t smem_u32(const void* p) {
    return (uint32_t)__cvta_generic_to_shared(p);
}
__device__ __forceinline__ void cp16(uint32_t dst, const void* src) {
    asm volatile("cp.async.cg.shared.global [%0], [%1], 16;\n" :: "r"(dst), "l"(src));
}
__device__ __forceinline__ void cp_commit() { asm volatile("cp.async.commit_group;\n"); }
__device__ __forceinline__ void cp_wait2() { asm volatile("cp.async.wait_group 2;\n"); }
__device__ __forceinline__ void cp_wait1() { asm volatile("cp.async.wait_group 1;\n"); }
__device__ __forceinline__ void cp_wait0() { asm volatile("cp.async.wait_group 0;\n"); }
__device__ __forceinline__ void ldm_x4(uint32_t (&r)[4], uint32_t addr) {
    asm volatile("ldmatrix.sync.aligned.m8n8.x4.shared.b16 {%0,%1,%2,%3}, [%4];"
                 : "=r"(r[0]), "=r"(r[1]), "=r"(r[2]), "=r"(r[3]) : "r"(addr));
}
__device__ __forceinline__ void ldm_x4_t(uint32_t (&r)[4], uint32_t addr) {
    asm volatile("ldmatrix.sync.aligned.m8n8.x4.trans.shared.b16 {%0,%1,%2,%3}, [%4];"
                 : "=r"(r[0]), "=r"(r[1]), "=r"(r[2]), "=r"(r[3]) : "r"(addr));
}
__device__ __forceinline__ void ldm_x2_t(uint32_t (&r)[2], uint32_t addr) {
    asm volatile("ldmatrix.sync.aligned.m8n8.x2.trans.shared.b16 {%0,%1}, [%2];"
                 : "=r"(r[0]), "=r"(r[1]) : "r"(addr));
}
// bf16 mma (Gram)
__device__ __forceinline__ void mma16816(float (&d)[4], const uint32_t (&a)[4],
                                         uint32_t b0, uint32_t b1) {
    asm volatile("mma.sync.aligned.m16n8k16.row.col.f32.bf16.bf16.f32 "
                 "{%0,%1,%2,%3}, {%4,%5,%6,%7}, {%8,%9}, {%0,%1,%2,%3};"
                 : "+f"(d[0]), "+f"(d[1]), "+f"(d[2]), "+f"(d[3])
                 : "r"(a[0]), "r"(a[1]), "r"(a[2]), "r"(a[3]), "r"(b0), "r"(b1));
}
// fp16 mma
__device__ __forceinline__ void mma16816h(float (&d)[4], const uint32_t (&a)[4],
                                          uint32_t b0, uint32_t b1) {
    asm volatile("mma.sync.aligned.m16n8k16.row.col.f32.f16.f16.f32 "
                 "{%0,%1,%2,%3}, {%4,%5,%6,%7}, {%8,%9}, {%0,%1,%2,%3};"
                 : "+f"(d[0]), "+f"(d[1]), "+f"(d[2]), "+f"(d[3])
                 : "r"(a[0]), "r"(a[1]), "r"(a[2]), "r"(a[3]), "r"(b0), "r"(b1));
}
union BPack2 { __nv_bfloat16 h[2]; uint32_t u; };
union HPack2 { __half h[2]; uint32_t u; };
union HPack8 { __half h[8]; uint4 u; };

// ---------------- prep: fp16 weights + exact T functional ----------------
__global__ void prep_kernel(const float* __restrict__ attn_W,
                            const float* __restrict__ emb_W,
                            const float* __restrict__ thr_W,
                            const float* __restrict__ attn_b,
                            const float* __restrict__ thr_b) {
    int t = blockIdx.x * 256 + threadIdx.x;
    if (t < CDIM * CDIM) {
        int ci = t >> 8, co = t & 255;
        g_Wtf[ci * CDIM + co] = __float2half_rn(attn_W[co * CDIM + ci]);
    }
    if (t < FDIM * CDIM) {
        int f = t >> 8, ci = t & 255;
        g_Wembf[ci * FDIM + f] = __float2half_rn(emb_W[f * CDIM + ci]);
    }
    if (blockIdx.x == 0) {
        int ci = threadIdx.x;
        float s = 0.0f;
        for (int co = 0; co < CDIM; co++)
            s = fmaf(attn_W[co * CDIM + ci], thr_W[co], s);
        g_tvec[ci] = s;
        if (ci == 0) {
            float c = thr_b[0];
            for (int co = 0; co < CDIM; co++) c = fmaf(attn_b[co], thr_W[co], c);
            g_tconst = c;
        }
    }
}

// ---------------- xprep: x -> fp16 copy + exact fp32 T per pixel ----------------
__global__ __launch_bounds__(256) void xprep_kernel(const float* __restrict__ x) {
    __shared__ float tv[CDIM];
    int tid = threadIdx.x, w = tid >> 5, lane = tid & 31;
    tv[tid] = g_tvec[tid];
    __syncthreads();
    int row = blockIdx.x * 8 + w;
    const float4* xr = (const float4*)(x + (size_t)row * CDIM) + lane * 2;
    float4 v0 = xr[0], v1 = xr[1];
    HPack8 p;
    p.h[0] = __float2half_rn(v0.x); p.h[1] = __float2half_rn(v0.y);
    p.h[2] = __float2half_rn(v0.z); p.h[3] = __float2half_rn(v0.w);
    p.h[4] = __float2half_rn(v1.x); p.h[5] = __float2half_rn(v1.y);
    p.h[6] = __float2half_rn(v1.z); p.h[7] = __float2half_rn(v1.w);
    *(uint4*)&g_xf[(size_t)row * CDIM + lane * 8] = p.u;
    const float* tvl = tv + lane * 8;
    float tp = v0.x * tvl[0] + v0.y * tvl[1] + v0.z * tvl[2] + v0.w * tvl[3] +
               v1.x * tvl[4] + v1.y * tvl[5] + v1.z * tvl[6] + v1.w * tvl[7];
#pragma unroll
    for (int o = 16; o; o >>= 1) tp += __shfl_xor_sync(0xffffffffu, tp, o);
    if (lane == 0) g_T[row] = tp + g_tconst;
}

// ---------------- emb via tensor cores (fp16 operands): Ebf, EbfT, sq ----------------
#define EM_OFF_W 0
#define EM_OFF_A 36864
#define EM_SMEM  67584
__global__ __launch_bounds__(256) void emb_mma_kernel(const float* __restrict__ emb_b) {
    extern __shared__ char smc[];
    __half* Wsm = (__half*)(smc + EM_OFF_W);               // [256][72]
    __half* Asp = (__half*)(smc + EM_OFF_A);               // [3][128][40]
    __nv_bfloat16* Est = (__nv_bfloat16*)(smc + EM_OFF_A); // [64][136] (reused post-loop)
    int tid = threadIdx.x, w = tid >> 5, lane = tid & 31;
    int blk = blockIdx.x;
    int row0 = blk * 128;
    int b = blk >> 3, n0 = (blk & 7) * 128;
    int lrow = lane & 7, q1 = (lane >> 3) & 1, q2 = lane >> 4;

    for (int i = tid; i < 256 * 16; i += 256) {
        int k = i >> 4, seg = i & 15;
        *(uint2*)&Wsm[k * 72 + seg * 4] = ((const uint2*)g_Wembf)[k * 16 + seg];
    }

#define EM_ISSUE(s, bf_)                                                          \
    {                                                                             \
        for (int u_ = 0; u_ < 2; u_++) {                                          \
            int id_ = tid + u_ * 256;                                             \
            int ar_ = id_ >> 2, aseg_ = id_ & 3;                                  \
            cp16(smem_u32(&Asp[(bf_) * 5120 + ar_ * 40 + aseg_ * 8]),             \
                 g_xf + (size_t)(row0 + ar_) * CDIM + (s) * 32 + aseg_ * 8);      \
        }                                                                         \
        cp_commit();                                                              \
    }

    EM_ISSUE(0, 0);
    EM_ISSUE(1, 1);

    float acc[4][2][4];
#pragma unroll
    for (int nt = 0; nt < 4; nt++)
#pragma unroll
        for (int h = 0; h < 2; h++)
#pragma unroll
            for (int r = 0; r < 4; r++) acc[nt][h][r] = 0.0f;

    for (int s = 0; s < 8; s++) {
        if (s < 7) cp_wait1(); else cp_wait0();
        __syncthreads();
        int buf = s % 3;
#pragma unroll
        for (int kk = 0; kk < 2; kk++) {
            uint32_t af[4];
            ldm_x4(af, smem_u32(&Asp[buf * 5120 + (w * 16 + lrow + q1 * 8) * 40 + kk * 16 + q2 * 8]));
#pragma unroll
            for (int nt = 0; nt < 4; nt++) {
                uint32_t bf[4];
                ldm_x4_t(bf, smem_u32(&Wsm[(s * 32 + kk * 16 + lrow + q1 * 8) * 72 + nt * 16 + q2 * 8]));
                mma16816h(acc[nt][0], af, bf[0], bf[1]);
                mma16816h(acc[nt][1], af, bf[2], bf[3]);
            }
        }
        if (s + 2 < 8) EM_ISSUE(s + 2, (s + 2) % 3);
    }
#undef EM_ISSUE

    // epilogue: bias, Ebf stores, sq; then staged transpose
    int r0 = w * 16 + (lane >> 2);
    int rl1 = r0 + 8;
    float sq0 = 0.0f, sq1 = 0.0f;
    float e0s[4][2][2], e1s[4][2][2];
#pragma unroll
    for (int nt = 0; nt < 4; nt++) {
#pragma unroll
        for (int h = 0; h < 2; h++) {
            int c = nt * 16 + h * 8 + (lane & 3) * 2;
            float bb0 = emb_b[c], bb1 = emb_b[c + 1];
            float e00 = acc[nt][h][0] + bb0, e01 = acc[nt][h][1] + bb1;
            float e10 = acc[nt][h][2] + bb0, e11 = acc[nt][h][3] + bb1;
            e0s[nt][h][0] = e00; e0s[nt][h][1] = e01;
            e1s[nt][h][0] = e10; e1s[nt][h][1] = e11;
            sq0 += e00 * e00 + e01 * e01;
            sq1 += e10 * e10 + e11 * e11;
            BPack2 p;
            p.h[0] = __float2bfloat16(e00); p.h[1] = __float2bfloat16(e01);
            *(uint32_t*)&g_Ebf[(size_t)(row0 + r0) * FDIM + c] = p.u;
            p.h[0] = __float2bfloat16(e10); p.h[1] = __float2bfloat16(e11);
            *(uint32_t*)&g_Ebf[(size_t)(row0 + rl1) * FDIM + c] = p.u;
        }
    }
    sq0 += __shfl_xor_sync(0xffffffffu, sq0, 1);
    sq0 += __shfl_xor_sync(0xffffffffu, sq0, 2);
    sq1 += __shfl_xor_sync(0xffffffffu, sq1, 1);
    sq1 += __shfl_xor_sync(0xffffffffu, sq1, 2);
    if ((lane & 3) == 0) {
        g_sq[row0 + r0] = sq0;
        g_sq[row0 + rl1] = sq1;
    }

    __syncthreads();
#pragma unroll
    for (int nt = 0; nt < 4; nt++)
#pragma unroll
        for (int h = 0; h < 2; h++) {
            int c = nt * 16 + h * 8 + (lane & 3) * 2;
            Est[c * 136 + r0] = __float2bfloat16(e0s[nt][h][0]);
            Est[(c + 1) * 136 + r0] = __float2bfloat16(e0s[nt][h][1]);
            Est[c * 136 + rl1] = __float2bfloat16(e1s[nt][h][0]);
            Est[(c + 1) * 136 + rl1] = __float2bfloat16(e1s[nt][h][1]);
        }
    __syncthreads();
    for (int i = tid; i < 1024; i += 256) {
        int k = i >> 4, seg = i & 15;
        *(uint4*)&g_EbfT[(((size_t)b * 64 + k) << 10) + n0 + seg * 8] =
            *(const uint4*)&Est[k * 136 + seg * 8];
    }
}

// ---------------- shortcut: SC = xf @ Wtf + b — single fp16 term, 8 stages ----------------
#define SC_OFF_A 0
#define SC_OFF_B 15360
#define SC_SMEM  66048
__global__ __launch_bounds__(256) void shortcut_kernel(const float* __restrict__ attn_b) {
    extern __shared__ char smc[];
    __half* Asp = (__half*)(smc + SC_OFF_A);   // [3][64][40]
    __half* Bsp = (__half*)(smc + SC_OFF_B);   // [3][32][264]
    int tid = threadIdx.x, w = tid >> 5, lane = tid & 31;
    int m0 = blockIdx.x * 64;
    int lrow = lane & 7, q1 = (lane >> 3) & 1, q2 = lane >> 4;

    float acc[4][4][4];
#pragma unroll
    for (int a = 0; a < 4; a++)
#pragma unroll
        for (int n = 0; n < 4; n++)
#pragma unroll
            for (int r = 0; r < 4; r++) acc[a][n][r] = 0.0f;

#define SC_ISSUE(s, bf_)                                                          \
    {                                                                             \
        int ar_ = tid >> 2, aseg_ = tid & 3;                                      \
        cp16(smem_u32(&Asp[(bf_) * 2560 + ar_ * 40 + aseg_ * 8]),                 \
             g_xf + (size_t)(m0 + ar_) * CDIM + (s) * 32 + aseg_ * 8);            \
        for (int u_ = 0; u_ < 4; u_++) {                                          \
            int id_ = tid + u_ * 256;                                             \
            int br_ = id_ >> 5, bseg_ = id_ & 31;                                 \
            cp16(smem_u32(&Bsp[(bf_) * 8448 + br_ * 264 + bseg_ * 8]),            \
                 g_Wtf + (size_t)((s) * 32 + br_) * CDIM + bseg_ * 8);            \
        }                                                                         \
        cp_commit();                                                              \
    }

    SC_ISSUE(0, 0);
    SC_ISSUE(1, 1);
    for (int s = 0; s < 8; s++) {
        if (s < 7) cp_wait1(); else cp_wait0();
        __syncthreads();
        int buf = s % 3;
#pragma unroll
        for (int kk = 0; kk < 2; kk++) {
            uint32_t af[4][4];
#pragma unroll
            for (int mt = 0; mt < 4; mt++)
                ldm_x4(af[mt], smem_u32(&Asp[buf * 2560 + (mt * 16 + lrow + q1 * 8) * 40 + kk * 16 + q2 * 8]));
            uint32_t bfr[2][4];
#pragma unroll
            for (int ng = 0; ng < 2; ng++)
                ldm_x4_t(bfr[ng], smem_u32(&Bsp[buf * 8448 + (kk * 16 + lrow + q1 * 8) * 264 + w * 32 + ng * 16 + q2 * 8]));
#pragma unroll
            for (int mt = 0; mt < 4; mt++)
#pragma unroll
                for (int nt = 0; nt < 4; nt++)
                    mma16816h(acc[mt][nt], af[mt],
                              bfr[nt >> 1][(nt & 1) * 2], bfr[nt >> 1][(nt & 1) * 2 + 1]);
        }
        if (s + 2 < 8) SC_ISSUE(s + 2, (s + 2) % 3);
    }
#undef SC_ISSUE

    // epilogue: bias + fp16 stores
#pragma unroll
    for (int nt = 0; nt < 4; nt++) {
        int c0 = w * 32 + nt * 8 + (lane & 3) * 2;
        float bb0 = attn_b[c0], bb1 = attn_b[c0 + 1];
#pragma unroll
        for (int mt = 0; mt < 4; mt++) {
            int r0g = m0 + mt * 16 + (lane >> 2);
            HPack2 h;
            h.h[0] = __float2half_rn(acc[mt][nt][0] + bb0);
            h.h[1] = __float2half_rn(acc[mt][nt][1] + bb1);
            *(uint32_t*)&g_SChf[(size_t)r0g * CDIM + c0] = h.u;
            h.h[0] = __float2half_rn(acc[mt][nt][2] + bb0);
            h.h[1] = __float2half_rn(acc[mt][nt][3] + bb1);
            *(uint32_t*)&g_SChf[(size_t)(r0g + 8) * CDIM + c0] = h.u;
        }
    }
}

// ---------------- attention matrix kernel: single-term bf16 Gram, 4-deep ring ----------------
#define S_PITCH 1044
#define OFF_S    0
#define OFF_EIH  133632
#define OFF_BH   138240
#define OFF_TSH  207872
#define OFF_SQJ  211968
#define ATTN_SMEM 216064

__global__ __launch_bounds__(1024) void attn_A_kernel() {
    extern __shared__ char smc[];
    float* S = (float*)(smc + OFF_S);                         // [32][1044]
    __nv_bfloat16* Eih = (__nv_bfloat16*)(smc + OFF_EIH);     // [32][72]
    __nv_bfloat16* BhS = (__nv_bfloat16*)(smc + OFF_BH);      // [4][64][136]
    float* Tsh = (float*)(smc + OFF_TSH);
    float* Sqj = (float*)(smc + OFF_SQJ);

    int tid = threadIdx.x;
    int tile = blockIdx.x, b = blockIdx.y;
    int i0 = tile * 32;
    int base = b * HW;
    int w = tid >> 5, lane = tid & 31;
    int lrow = lane & 7, q1 = (lane >> 3) & 1, q2 = lane >> 4;
    int mt = w & 1, ncol = w >> 1;

    Tsh[tid] = g_T[base + tid];
    Sqj[tid] = g_sq[base + tid];

    uint32_t dA = smem_u32(BhS) + ((tid >> 4) * 136 + (tid & 15) * 8) * 2;
    const __nv_bfloat16* sA = g_EbfT + (((size_t)b * 64 + (tid >> 4)) << 10) + (tid & 15) * 8;

#define AT_ISSUE(jc)                                                              \
    {                                                                             \
        cp16(dA + ((jc) & 3) * 17408, sA + (jc) * 128);                           \
        cp_commit();                                                              \
    }

    if (tid < 256) {
        int r = tid >> 3, seg = tid & 7;
        cp16(smem_u32(Eih + r * 72 + seg * 8),
             g_Ebf + (size_t)(base + i0 + r) * 64 + seg * 8);
    }
    AT_ISSUE(0);
    AT_ISSUE(1);
    AT_ISSUE(2);

    int r0 = mt * 16 + (lane >> 2);
    int ig0 = i0 + r0, ig1 = ig0 + 8;
    float yi0f = (float)(ig0 >> 5), xi0f = (float)(ig0 & 31);
    float yi1f = (float)(ig1 >> 5), xi1f = (float)(ig1 & 31);
    float sqi0 = g_sq[base + ig0];
    float sqi1 = g_sq[base + ig1];
    int brow = (lane & 7) + ((lane >> 3) & 1) * 8;
    int jlow = ncol * 8 + (lane & 3) * 2;
    float yjf = (float)(jlow >> 5);
    float xjf = (float)(jlow & 31);
    float dx00 = fabsf(xi0f - xjf), dx01 = fabsf(xi0f - xjf - 1.0f);
    float dx10 = fabsf(xi1f - xjf), dx11 = fabsf(xi1f - xjf - 1.0f);
    const float* Sqjb = Sqj + jlow;
    float* Srow0 = S + r0 * S_PITCH + jlow;
    float* Srow1 = Srow0 + 8 * S_PITCH;
    uint32_t bhl = smem_u32(BhS) + (brow * 136 + ncol * 8) * 2;

    uint32_t Ah[4][4];

    for (int jc = 0; jc < 8; jc++) {
        if (jc <= 5) cp_wait2(); else if (jc == 6) cp_wait1(); else cp_wait0();
        __syncthreads();
        if (jc == 0) {
#pragma unroll
            for (int kc = 0; kc < 4; kc++)
                ldm_x4(Ah[kc], smem_u32(&Eih[(mt * 16 + lrow + q1 * 8) * 72 + kc * 16 + q2 * 8]));
        }
        if (jc < 5) AT_ISSUE(jc + 3);
        uint32_t bufoff = (jc & 3) * 17408;
        float acc[4] = {};
#pragma unroll
        for (int kc = 0; kc < 4; kc++) {
            uint32_t bh[2];
            ldm_x2_t(bh, bhl + bufoff + kc * 4352);
            mma16816(acc, Ah[kc], bh[0], bh[1]);
        }
        float sq0 = Sqjb[0], sq1 = Sqjb[1];
        float dy0 = fabsf(yi0f - yjf);
        float dy1 = fabsf(yi1f - yjf);
        {
            float d2a = fmaxf(sqi0 + sq0 - 2.0f * acc[0], 0.0f);
            float d2b = fmaxf(sqi0 + sq1 - 2.0f * acc[1], 0.0f);
            float da = dy0 + dx00, db = dy0 + dx01;
            float ma = (da <= 32.0f) ? da * (1.0f / 32.0f) : 0.0f;
            float mb = (db <= 32.0f) ? db * (1.0f / 32.0f) : 0.0f;
            *(float2*)Srow0 = make_float2(__expf(-d2a) - 1.0f + ma, __expf(-d2b) - 1.0f + mb);
        }
        {
            float d2a = fmaxf(sqi1 + sq0 - 2.0f * acc[2], 0.0f);
            float d2b = fmaxf(sqi1 + sq1 - 2.0f * acc[3], 0.0f);
            float da = dy1 + dx10, db = dy1 + dx11;
            float ma = (da <= 32.0f) ? da * (1.0f / 32.0f) : 0.0f;
            float mb = (db <= 32.0f) ? db * (1.0f / 32.0f) : 0.0f;
            *(float2*)Srow1 = make_float2(__expf(-d2a) - 1.0f + ma, __expf(-d2b) - 1.0f + mb);
        }
        yjf += 4.0f;
        Sqjb += 128; Srow0 += 128; Srow1 += 128;
    }
#undef AT_ISSUE
    __syncthreads();

    // ---- Phase B: register softmax, 1 row per warp, fp16 A store ----
    {
        int r = w;
        float* Sr = S + r * S_PITCH;
        float v[32];
#pragma unroll
        for (int t = 0; t < 32; t++) v[t] = Sr[lane + t * 32];
        float m = -1e30f;
#pragma unroll
        for (int t = 0; t < 32; t++) m = fmaxf(m, v[t]);
#pragma unroll
        for (int o = 16; o; o >>= 1) m = fmaxf(m, __shfl_xor_sync(0xffffffffu, m, o));
        float s1 = 0.0f;
#pragma unroll
        for (int t = 0; t < 32; t++) { v[t] = __expf(v[t] - m); s1 += v[t]; }
#pragma unroll
        for (int o = 16; o; o >>= 1) s1 += __shfl_xor_sync(0xffffffffu, s1, o);
        float inv1 = 1.0f / s1;
        float m2 = 0.0f;
#pragma unroll
        for (int t = 0; t < 32; t++) {
            v[t] = fmaxf(v[t] * inv1 - Tsh[lane + t * 32], 0.0f);
            m2 = fmaxf(m2, v[t]);
        }
#pragma unroll
        for (int o = 16; o; o >>= 1) m2 = fmaxf(m2, __shfl_xor_sync(0xffffffffu, m2, o));
        float s2 = 0.0f;
#pragma unroll
        for (int t = 0; t < 32; t++) { v[t] = __expf(v[t] - m2); s2 += v[t]; }
#pragma unroll
        for (int o = 16; o; o >>= 1) s2 += __shfl_xor_sync(0xffffffffu, s2, o);
        float inv2 = 1.0f / s2;

        __half* rowh = (__half*)Sr;
#pragma unroll
        for (int t = 0; t < 32; t++) {
            rowh[lane + t * 32] = __float2half_rn(v[t] * inv2);
        }
        __syncwarp();
        size_t Ab = ((size_t)b << 20) + ((size_t)(i0 + r) << 10);
        uint4* gh = (uint4*)&g_Af[Ab];
        const uint4* sh = (const uint4*)rowh;
#pragma unroll
        for (int it = 0; it < 4; it++) gh[lane + it * 32] = sh[lane + it * 32];
    }
}

// ---------------- fp16 tensor-core bmm: out = x + A @ SC (single term, k=64 stages) ----------------
#define BMM_OFF_AF 0
#define BMM_OFF_SH 36864
#define BMM_SMEM   71680
__global__ __launch_bounds__(256, 2) void bmm_kernel(const float* __restrict__ x,
                                                     float* __restrict__ out) {
    extern __shared__ char smc[];
    __half* Af_s = (__half*)(smc + BMM_OFF_AF);  // [2][128][72]
    __half* Sh_s = (__half*)(smc + BMM_OFF_SH);  // [2][64][136]
    int tid = threadIdx.x, w = tid >> 5, lane = tid & 31;
    int ct = blockIdx.x, mtb = blockIdx.y, b = blockIdx.z;
    int i0 = mtb * 128, c0 = ct * 128;

    const __half* Af = g_Af + ((size_t)b << 20) + (size_t)i0 * 1024;
    const __half* Shf = g_SChf + ((size_t)b << 18) + c0;

    float acc[4][4][4];
#pragma unroll
    for (int a = 0; a < 4; a++)
#pragma unroll
        for (int n = 0; n < 4; n++)
#pragma unroll
            for (int r = 0; r < 4; r++) acc[a][n][r] = 0.0f;

    int wm = w >> 2, wn = w & 3;
    int lrow = lane & 7, q1 = (lane >> 3) & 1, q2 = lane >> 4;

#define ISSUE(jc, bf_)                                                            \
    {                                                                             \
        for (int u_ = 0; u_ < 4; u_++) {                                          \
            int id_ = tid + u_ * 256;                                             \
            int ar_ = id_ >> 3, aseg_ = id_ & 7;                                  \
            cp16(smem_u32(&Af_s[(bf_) * 9216 + ar_ * 72 + aseg_ * 8]),            \
                 Af + (size_t)ar_ * 1024 + (jc) * 64 + aseg_ * 8);                \
            int sr_ = id_ >> 4, sseg_ = id_ & 15;                                 \
            cp16(smem_u32(&Sh_s[(bf_) * 8704 + sr_ * 136 + sseg_ * 8]),           \
                 Shf + (size_t)((jc) * 64 + sr_) * 256 + sseg_ * 8);              \
        }                                                                         \
        cp_commit();                                                              \
    }

    ISSUE(0, 0);
    ISSUE(1, 1);
    for (int cc = 0; cc < 16; cc++) {
        if (cc < 15) cp_wait1(); else cp_wait0();
        __syncthreads();
        int buf = cc & 1;
#pragma unroll
        for (int kk = 0; kk < 4; kk++) {
            uint32_t af[4][4];
#pragma unroll
            for (int mtl = 0; mtl < 4; mtl++) {
                int row = wm * 64 + mtl * 16 + lrow + q1 * 8;
                int col = kk * 16 + q2 * 8;
                ldm_x4(af[mtl], smem_u32(&Af_s[buf * 9216 + row * 72 + col]));
            }
            uint32_t bh[2][4];
#pragma unroll
            for (int ng = 0; ng < 2; ng++) {
                int row = kk * 16 + lrow + q1 * 8;
                int col = wn * 32 + ng * 16 + q2 * 8;
                ldm_x4_t(bh[ng], smem_u32(&Sh_s[buf * 8704 + row * 136 + col]));
            }
#pragma unroll
            for (int mtl = 0; mtl < 4; mtl++)
#pragma unroll
                for (int nt = 0; nt < 4; nt++)
                    mma16816h(acc[mtl][nt], af[mtl],
                              bh[nt >> 1][(nt & 1) * 2], bh[nt >> 1][(nt & 1) * 2 + 1]);
        }
        __syncthreads();
        if (cc + 2 < 16) ISSUE(cc + 2, cc & 1);
    }
#undef ISSUE

    int g = lane >> 2, t2 = lane & 3;
#pragma unroll
    for (int mtl = 0; mtl < 4; mtl++) {
#pragma unroll
        for (int nt = 0; nt < 4; nt++) {
            int row = i0 + wm * 64 + mtl * 16 + g;
            int col = c0 + wn * 32 + nt * 8 + 2 * t2;
            size_t o0 = ((size_t)b * 1024 + row) * 256 + col;
            size_t o1 = o0 + 8 * 256;
            float2 xv0 = *(const float2*)&x[o0];
            float2 xv1 = *(const float2*)&x[o1];
            *(float2*)&out[o0] = make_float2(xv0.x + acc[mtl][nt][0], xv0.y + acc[mtl][nt][1]);
            *(float2*)&out[o1] = make_float2(xv1.x + acc[mtl][nt][2], xv1.y + acc[mtl][nt][3]);
        }
    }
}

// ---------------- launch ----------------
extern "C" void kernel_launch(void* const* d_in, const int* in_sizes, int n_in,
                              void* d_out, int out_size) {
    const float* x      = (const float*)d_in[0];
    const float* emb_W  = (const float*)d_in[1];
    const float* emb_b  = (const float*)d_in[2];
    const float* attn_W = (const float*)d_in[3];
    const float* attn_b = (const float*)d_in[4];
    const float* thr_W  = (const float*)d_in[5];
    const float* thr_b  = (const float*)d_in[6];
    float* out = (float*)d_out;

    cudaFuncSetAttribute(emb_mma_kernel, cudaFuncAttributeMaxDynamicSharedMemorySize, EM_SMEM);
    cudaFuncSetAttribute(shortcut_kernel, cudaFuncAttributeMaxDynamicSharedMemorySize, SC_SMEM);
    cudaFuncSetAttribute(attn_A_kernel, cudaFuncAttributeMaxDynamicSharedMemorySize, ATTN_SMEM);
    cudaFuncSetAttribute(bmm_kernel, cudaFuncAttributeMaxDynamicSharedMemorySize, BMM_SMEM);

    prep_kernel<<<256, 256>>>(attn_W, emb_W, thr_W, attn_b, thr_b);
    xprep_kernel<<<BATCH * HW / 8, 256>>>(x);
    emb_mma_kernel<<<BATCH * HW / 128, 256, EM_SMEM>>>(emb_b);
    shortcut_kernel<<<BATCH * HW / 64, 256, SC_SMEM>>>(attn_b);
    attn_A_kernel<<<dim3(HW / 32, BATCH), 1024, ATTN_SMEM>>>();
    bmm_kernel<<<dim3(CDIM / 128, HW / 128, BATCH), 256, BMM_SMEM>>>(x, out);
}

// round 17
// speedup vs baseline: 2.4511x; 1.0100x over previous
#include <cuda_runtime.h>
#include <cuda_bf16.h>
#include <cuda_fp16.h>
#include <math.h>
#include <stdint.h>

#define BATCH 32
#define HW    1024
#define CDIM  256
#define FDIM  64

// ---------------- scratch (device globals; no allocations) ----------------
__device__ float g_sq[BATCH * HW];
__device__ float g_T[BATCH * HW];
__device__ float g_tvec[CDIM];
__device__ float g_tconst;
__device__ __nv_bfloat16 g_Ebf[BATCH * HW * FDIM];       // bf16(emb) [n][k]
__device__ __nv_bfloat16 g_EbfT[BATCH * FDIM * HW];      // [b][k][n]
__device__ __half g_xf[BATCH * HW * CDIM];               // fp16(x)
__device__ __half g_SChf[BATCH * HW * CDIM];             // fp16 SC
__device__ __half g_Af[(size_t)BATCH * HW * HW];         // 64 MB, fp16 A
__device__ __half g_Wcat[CDIM * 320];                    // fp16 [ci][ attn_W^T cols 0-255 | emb_W^T cols 256-319 ]

// ---------------- small helpers ----------------
__device__ __forceinline__ uint32_t smem_u32(const void* p) {
    return (uint32_t)__cvta_generic_to_shared(p);
}
__device__ __forceinline__ void cp16(uint32_t dst, const void* src) {
    asm volatile("cp.async.cg.shared.global [%0], [%1], 16;\n" :: "r"(dst), "l"(src));
}
__device__ __forceinline__ void cp_commit() { asm volatile("cp.async.commit_group;\n"); }
__device__ __forceinline__ void cp_wait2() { asm volatile("cp.async.wait_group 2;\n"); }
__device__ __forceinline__ void cp_wait1() { asm volatile("cp.async.wait_group 1;\n"); }
__device__ __forceinline__ void cp_wait0() { asm volatile("cp.async.wait_group 0;\n"); }
__device__ __forceinline__ void ldm_x4(uint32_t (&r)[4], uint32_t addr) {
    asm volatile("ldmatrix.sync.aligned.m8n8.x4.shared.b16 {%0,%1,%2,%3}, [%4];"
                 : "=r"(r[0]), "=r"(r[1]), "=r"(r[2]), "=r"(r[3]) : "r"(addr));
}
__device__ __forceinline__ void ldm_x4_t(uint32_t (&r)[4], uint32_t addr) {
    asm volatile("ldmatrix.sync.aligned.m8n8.x4.trans.shared.b16 {%0,%1,%2,%3}, [%4];"
                 : "=r"(r[0]), "=r"(r[1]), "=r"(r[2]), "=r"(r[3]) : "r"(addr));
}
__device__ __forceinline__ void ldm_x2_t(uint32_t (&r)[2], uint32_t addr) {
    asm volatile("ldmatrix.sync.aligned.m8n8.x2.trans.shared.b16 {%0,%1}, [%2];"
                 : "=r"(r[0]), "=r"(r[1]) : "r"(addr));
}
// bf16 mma (Gram)
__device__ __forceinline__ void mma16816(float (&d)[4], const uint32_t (&a)[4],
                                         uint32_t b0, uint32_t b1) {
    asm volatile("mma.sync.aligned.m16n8k16.row.col.f32.bf16.bf16.f32 "
                 "{%0,%1,%2,%3}, {%4,%5,%6,%7}, {%8,%9}, {%0,%1,%2,%3};"
                 : "+f"(d[0]), "+f"(d[1]), "+f"(d[2]), "+f"(d[3])
                 : "r"(a[0]), "r"(a[1]), "r"(a[2]), "r"(a[3]), "r"(b0), "r"(b1));
}
// fp16 mma
__device__ __forceinline__ void mma16816h(float (&d)[4], const uint32_t (&a)[4],
                                          uint32_t b0, uint32_t b1) {
    asm volatile("mma.sync.aligned.m16n8k16.row.col.f32.f16.f16.f32 "
                 "{%0,%1,%2,%3}, {%4,%5,%6,%7}, {%8,%9}, {%0,%1,%2,%3};"
                 : "+f"(d[0]), "+f"(d[1]), "+f"(d[2]), "+f"(d[3])
                 : "r"(a[0]), "r"(a[1]), "r"(a[2]), "r"(a[3]), "r"(b0), "r"(b1));
}
union BPack2 { __nv_bfloat16 h[2]; uint32_t u; };
union HPack2 { __half h[2]; uint32_t u; };
union HPack8 { __half h[8]; uint4 u; };

// ---------------- prep: concatenated fp16 weights + exact T functional ----------------
__global__ void prep_kernel(const float* __restrict__ attn_W,
                            const float* __restrict__ emb_W,
                            const float* __restrict__ thr_W,
                            const float* __restrict__ attn_b,
                            const float* __restrict__ thr_b) {
    int t = blockIdx.x * 256 + threadIdx.x;
    if (t < CDIM * 320) {
        int ci = t / 320, co = t % 320;
        float v = (co < CDIM) ? attn_W[co * CDIM + ci] : emb_W[(co - CDIM) * CDIM + ci];
        g_Wcat[t] = __float2half_rn(v);
    }
    if (blockIdx.x == 0) {
        int ci = threadIdx.x;
        float s = 0.0f;
        for (int co = 0; co < CDIM; co++)
            s = fmaf(attn_W[co * CDIM + ci], thr_W[co], s);
        g_tvec[ci] = s;
        if (ci == 0) {
            float c = thr_b[0];
            for (int co = 0; co < CDIM; co++) c = fmaf(attn_b[co], thr_W[co], c);
            g_tconst = c;
        }
    }
}

// ---------------- xprep: x -> fp16 copy + exact fp32 T per pixel ----------------
__global__ __launch_bounds__(256) void xprep_kernel(const float* __restrict__ x) {
    __shared__ float tv[CDIM];
    int tid = threadIdx.x, w = tid >> 5, lane = tid & 31;
    tv[tid] = g_tvec[tid];
    __syncthreads();
    int row = blockIdx.x * 8 + w;
    const float4* xr = (const float4*)(x + (size_t)row * CDIM) + lane * 2;
    float4 v0 = xr[0], v1 = xr[1];
    HPack8 p;
    p.h[0] = __float2half_rn(v0.x); p.h[1] = __float2half_rn(v0.y);
    p.h[2] = __float2half_rn(v0.z); p.h[3] = __float2half_rn(v0.w);
    p.h[4] = __float2half_rn(v1.x); p.h[5] = __float2half_rn(v1.y);
    p.h[6] = __float2half_rn(v1.z); p.h[7] = __float2half_rn(v1.w);
    *(uint4*)&g_xf[(size_t)row * CDIM + lane * 8] = p.u;
    const float* tvl = tv + lane * 8;
    float tp = v0.x * tvl[0] + v0.y * tvl[1] + v0.z * tvl[2] + v0.w * tvl[3] +
               v1.x * tvl[4] + v1.y * tvl[5] + v1.z * tvl[6] + v1.w * tvl[7];
#pragma unroll
    for (int o = 16; o; o >>= 1) tp += __shfl_xor_sync(0xffffffffu, tp, o);
    if (lane == 0) g_T[row] = tp + g_tconst;
}

// ---------------- front: SC = xf@Wt + b AND E = xf@Wemb + b (fused, shared A frags) ----------------
// 64-row tiles, 8 k-stages, 3-buffer ring, 1 barrier/stage.
#define FR_OFF_A  0
#define FR_OFF_B  15360
#define FR_OFF_SQ 78336
#define FR_SMEM   78592
__global__ __launch_bounds__(256) void front_kernel(const float* __restrict__ attn_b,
                                                    const float* __restrict__ emb_b) {
    extern __shared__ char smc[];
    __half* Asp = (__half*)(smc + FR_OFF_A);    // [3][64][40]
    __half* Bsp = (__half*)(smc + FR_OFF_B);    // [3][32][328]
    float* sqs = (float*)(smc + FR_OFF_SQ);     // [64]
    __nv_bfloat16* Est = (__nv_bfloat16*)(smc + FR_OFF_A);  // [64][72] reused post-loop
    int tid = threadIdx.x, w = tid >> 5, lane = tid & 31;
    int blk = blockIdx.x;
    int m0 = blk * 64;
    int b = blk >> 4, n0 = (blk & 15) * 64;
    int lrow = lane & 7, q1 = (lane >> 3) & 1, q2 = lane >> 4;
    int brow = (lane & 7) + ((lane >> 3) & 1) * 8;

    if (tid < 64) sqs[tid] = 0.0f;

#define FR_ISSUE(s, bf_)                                                          \
    {                                                                             \
        int ar_ = tid >> 2, aseg_ = tid & 3;                                      \
        cp16(smem_u32(&Asp[(bf_) * 2560 + ar_ * 40 + aseg_ * 8]),                 \
             g_xf + (size_t)(m0 + ar_) * CDIM + (s) * 32 + aseg_ * 8);            \
        for (int u_ = 0; u_ < 5; u_++) {                                          \
            int id_ = tid + u_ * 256;                                             \
            int br_ = id_ / 40, bseg_ = id_ % 40;                                 \
            cp16(smem_u32(&Bsp[(bf_) * 10496 + br_ * 328 + bseg_ * 8]),           \
                 g_Wcat + ((s) * 32 + br_) * 320 + bseg_ * 8);                    \
        }                                                                         \
        cp_commit();                                                              \
    }

    FR_ISSUE(0, 0);
    FR_ISSUE(1, 1);

    float acc[4][4][4];
    float acce[4][4];
#pragma unroll
    for (int a = 0; a < 4; a++) {
#pragma unroll
        for (int n = 0; n < 4; n++)
#pragma unroll
            for (int r = 0; r < 4; r++) acc[a][n][r] = 0.0f;
#pragma unroll
        for (int r = 0; r < 4; r++) acce[a][r] = 0.0f;
    }

    for (int s = 0; s < 8; s++) {
        if (s < 7) cp_wait1(); else cp_wait0();
        __syncthreads();
        int buf = s % 3;
#pragma unroll
        for (int kk = 0; kk < 2; kk++) {
            uint32_t af[4][4];
#pragma unroll
            for (int mt = 0; mt < 4; mt++)
                ldm_x4(af[mt], smem_u32(&Asp[buf * 2560 + (mt * 16 + lrow + q1 * 8) * 40 + kk * 16 + q2 * 8]));
            uint32_t bfr[2][4];
#pragma unroll
            for (int ng = 0; ng < 2; ng++)
                ldm_x4_t(bfr[ng], smem_u32(&Bsp[buf * 10496 + (kk * 16 + lrow + q1 * 8) * 328 + w * 32 + ng * 16 + q2 * 8]));
            uint32_t be[2];
            ldm_x2_t(be, smem_u32(&Bsp[buf * 10496 + (kk * 16 + brow) * 328 + 256 + w * 8]));
#pragma unroll
            for (int mt = 0; mt < 4; mt++) {
#pragma unroll
                for (int nt = 0; nt < 4; nt++)
                    mma16816h(acc[mt][nt], af[mt],
                              bfr[nt >> 1][(nt & 1) * 2], bfr[nt >> 1][(nt & 1) * 2 + 1]);
                mma16816h(acce[mt], af[mt], be[0], be[1]);
            }
        }
        if (s + 2 < 8) FR_ISSUE(s + 2, (s + 2) % 3);
    }
#undef FR_ISSUE

    // ---- SC epilogue: bias + fp16 stores ----
#pragma unroll
    for (int nt = 0; nt < 4; nt++) {
        int c0 = w * 32 + nt * 8 + (lane & 3) * 2;
        float bb0 = attn_b[c0], bb1 = attn_b[c0 + 1];
#pragma unroll
        for (int mt = 0; mt < 4; mt++) {
            int r0g = m0 + mt * 16 + (lane >> 2);
            HPack2 h;
            h.h[0] = __float2half_rn(acc[mt][nt][0] + bb0);
            h.h[1] = __float2half_rn(acc[mt][nt][1] + bb1);
            *(uint32_t*)&g_SChf[(size_t)r0g * CDIM + c0] = h.u;
            h.h[0] = __float2half_rn(acc[mt][nt][2] + bb0);
            h.h[1] = __float2half_rn(acc[mt][nt][3] + bb1);
            *(uint32_t*)&g_SChf[(size_t)(r0g + 8) * CDIM + c0] = h.u;
        }
    }

    // ---- E epilogue: bias, Ebf stores, sq partials ----
    int ecol = w * 8 + (lane & 3) * 2;
    float eb0 = emb_b[ecol], eb1 = emb_b[ecol + 1];
    float e0s[4][2], e1s[4][2];
#pragma unroll
    for (int mt = 0; mt < 4; mt++) {
        int rl0 = mt * 16 + (lane >> 2), rl1 = rl0 + 8;
        float e00 = acce[mt][0] + eb0, e01 = acce[mt][1] + eb1;
        float e10 = acce[mt][2] + eb0, e11 = acce[mt][3] + eb1;
        e0s[mt][0] = e00; e0s[mt][1] = e01;
        e1s[mt][0] = e10; e1s[mt][1] = e11;
        BPack2 p;
        p.h[0] = __float2bfloat16(e00); p.h[1] = __float2bfloat16(e01);
        *(uint32_t*)&g_Ebf[(size_t)(m0 + rl0) * FDIM + ecol] = p.u;
        p.h[0] = __float2bfloat16(e10); p.h[1] = __float2bfloat16(e11);
        *(uint32_t*)&g_Ebf[(size_t)(m0 + rl1) * FDIM + ecol] = p.u;
        float pr0 = e00 * e00 + e01 * e01;
        float pr1 = e10 * e10 + e11 * e11;
        pr0 += __shfl_xor_sync(0xffffffffu, pr0, 1);
        pr0 += __shfl_xor_sync(0xffffffffu, pr0, 2);
        pr1 += __shfl_xor_sync(0xffffffffu, pr1, 1);
        pr1 += __shfl_xor_sync(0xffffffffu, pr1, 2);
        if ((lane & 3) == 0) {
            atomicAdd(&sqs[rl0], pr0);
            atomicAdd(&sqs[rl1], pr1);
        }
    }
    __syncthreads();
    if (tid < 64) g_sq[m0 + tid] = sqs[tid];

    // ---- EbfT staged transpose (reuses Asp region) ----
#pragma unroll
    for (int mt = 0; mt < 4; mt++) {
        int rl0 = mt * 16 + (lane >> 2), rl1 = rl0 + 8;
        Est[ecol * 72 + rl0] = __float2bfloat16(e0s[mt][0]);
        Est[(ecol + 1) * 72 + rl0] = __float2bfloat16(e0s[mt][1]);
        Est[ecol * 72 + rl1] = __float2bfloat16(e1s[mt][0]);
        Est[(ecol + 1) * 72 + rl1] = __float2bfloat16(e1s[mt][1]);
    }
    __syncthreads();
    for (int i = tid; i < 512; i += 256) {
        int k = i >> 3, seg = i & 7;
        *(uint4*)&g_EbfT[(((size_t)b * 64 + k) << 10) + n0 + seg * 8] =
            *(const uint4*)&Est[k * 72 + seg * 8];
    }
}

// ---------------- attention matrix kernel: single-term bf16 Gram, 4-deep ring ----------------
#define S_PITCH 1044
#define OFF_S    0
#define OFF_EIH  133632
#define OFF_BH   138240
#define OFF_TSH  207872
#define OFF_SQJ  211968
#define ATTN_SMEM 216064

__global__ __launch_bounds__(1024) void attn_A_kernel() {
    extern __shared__ char smc[];
    float* S = (float*)(smc + OFF_S);                         // [32][1044]
    __nv_bfloat16* Eih = (__nv_bfloat16*)(smc + OFF_EIH);     // [32][72]
    __nv_bfloat16* BhS = (__nv_bfloat16*)(smc + OFF_BH);      // [4][64][136]
    float* Tsh = (float*)(smc + OFF_TSH);
    float* Sqj = (float*)(smc + OFF_SQJ);

    int tid = threadIdx.x;
    int tile = blockIdx.x, b = blockIdx.y;
    int i0 = tile * 32;
    int base = b * HW;
    int w = tid >> 5, lane = tid & 31;
    int lrow = lane & 7, q1 = (lane >> 3) & 1, q2 = lane >> 4;
    int mt = w & 1, ncol = w >> 1;

    Tsh[tid] = g_T[base + tid];
    Sqj[tid] = g_sq[base + tid];

    uint32_t dA = smem_u32(BhS) + ((tid >> 4) * 136 + (tid & 15) * 8) * 2;
    const __nv_bfloat16* sA = g_EbfT + (((size_t)b * 64 + (tid >> 4)) << 10) + (tid & 15) * 8;

#define AT_ISSUE(jc)                                                              \
    {                                                                             \
        cp16(dA + ((jc) & 3) * 17408, sA + (jc) * 128);                           \
        cp_commit();                                                              \
    }

    if (tid < 256) {
        int r = tid >> 3, seg = tid & 7;
        cp16(smem_u32(Eih + r * 72 + seg * 8),
             g_Ebf + (size_t)(base + i0 + r) * 64 + seg * 8);
    }
    AT_ISSUE(0);
    AT_ISSUE(1);
    AT_ISSUE(2);

    int r0 = mt * 16 + (lane >> 2);
    int ig0 = i0 + r0, ig1 = ig0 + 8;
    float yi0f = (float)(ig0 >> 5), xi0f = (float)(ig0 & 31);
    float yi1f = (float)(ig1 >> 5), xi1f = (float)(ig1 & 31);
    float sqi0 = g_sq[base + ig0];
    float sqi1 = g_sq[base + ig1];
    int brow = (lane & 7) + ((lane >> 3) & 1) * 8;
    int jlow = ncol * 8 + (lane & 3) * 2;
    float yjf = (float)(jlow >> 5);
    float xjf = (float)(jlow & 31);
    float dx00 = fabsf(xi0f - xjf), dx01 = fabsf(xi0f - xjf - 1.0f);
    float dx10 = fabsf(xi1f - xjf), dx11 = fabsf(xi1f - xjf - 1.0f);
    const float* Sqjb = Sqj + jlow;
    float* Srow0 = S + r0 * S_PITCH + jlow;
    float* Srow1 = Srow0 + 8 * S_PITCH;
    uint32_t bhl = smem_u32(BhS) + (brow * 136 + ncol * 8) * 2;

    uint32_t Ah[4][4];

    for (int jc = 0; jc < 8; jc++) {
        if (jc <= 5) cp_wait2(); else if (jc == 6) cp_wait1(); else cp_wait0();
        __syncthreads();
        if (jc == 0) {
#pragma unroll
            for (int kc = 0; kc < 4; kc++)
                ldm_x4(Ah[kc], smem_u32(&Eih[(mt * 16 + lrow + q1 * 8) * 72 + kc * 16 + q2 * 8]));
        }
        if (jc < 5) AT_ISSUE(jc + 3);
        uint32_t bufoff = (jc & 3) * 17408;
        float acc[4] = {};
#pragma unroll
        for (int kc = 0; kc < 4; kc++) {
            uint32_t bh[2];
            ldm_x2_t(bh, bhl + bufoff + kc * 4352);
            mma16816(acc, Ah[kc], bh[0], bh[1]);
        }
        float sq0 = Sqjb[0], sq1 = Sqjb[1];
        float dy0 = fabsf(yi0f - yjf);
        float dy1 = fabsf(yi1f - yjf);
        {
            float d2a = fmaxf(sqi0 + sq0 - 2.0f * acc[0], 0.0f);
            float d2b = fmaxf(sqi0 + sq1 - 2.0f * acc[1], 0.0f);
            float da = dy0 + dx00, db = dy0 + dx01;
            float ma = (da <= 32.0f) ? da * (1.0f / 32.0f) : 0.0f;
            float mb = (db <= 32.0f) ? db * (1.0f / 32.0f) : 0.0f;
            *(float2*)Srow0 = make_float2(__expf(-d2a) - 1.0f + ma, __expf(-d2b) - 1.0f + mb);
        }
        {
            float d2a = fmaxf(sqi1 + sq0 - 2.0f * acc[2], 0.0f);
            float d2b = fmaxf(sqi1 + sq1 - 2.0f * acc[3], 0.0f);
            float da = dy1 + dx10, db = dy1 + dx11;
            float ma = (da <= 32.0f) ? da * (1.0f / 32.0f) : 0.0f;
            float mb = (db <= 32.0f) ? db * (1.0f / 32.0f) : 0.0f;
            *(float2*)Srow1 = make_float2(__expf(-d2a) - 1.0f + ma, __expf(-d2b) - 1.0f + mb);
        }
        yjf += 4.0f;
        Sqjb += 128; Srow0 += 128; Srow1 += 128;
    }
#undef AT_ISSUE
    __syncthreads();

    // ---- Phase B: register softmax, 1 row per warp, fp16 A store ----
    {
        int r = w;
        float* Sr = S + r * S_PITCH;
        float v[32];
#pragma unroll
        for (int t = 0; t < 32; t++) v[t] = Sr[lane + t * 32];
        float m = -1e30f;
#pragma unroll
        for (int t = 0; t < 32; t++) m = fmaxf(m, v[t]);
#pragma unroll
        for (int o = 16; o; o >>= 1) m = fmaxf(m, __shfl_xor_sync(0xffffffffu, m, o));
        float s1 = 0.0f;
#pragma unroll
        for (int t = 0; t < 32; t++) { v[t] = __expf(v[t] - m); s1 += v[t]; }
#pragma unroll
        for (int o = 16; o; o >>= 1) s1 += __shfl_xor_sync(0xffffffffu, s1, o);
        float inv1 = 1.0f / s1;
        float m2 = 0.0f;
#pragma unroll
        for (int t = 0; t < 32; t++) {
            v[t] = fmaxf(v[t] * inv1 - Tsh[lane + t * 32], 0.0f);
            m2 = fmaxf(m2, v[t]);
        }
#pragma unroll
        for (int o = 16; o; o >>= 1) m2 = fmaxf(m2, __shfl_xor_sync(0xffffffffu, m2, o));
        float s2 = 0.0f;
#pragma unroll
        for (int t = 0; t < 32; t++) { v[t] = __expf(v[t] - m2); s2 += v[t]; }
#pragma unroll
        for (int o = 16; o; o >>= 1) s2 += __shfl_xor_sync(0xffffffffu, s2, o);
        float inv2 = 1.0f / s2;

        __half* rowh = (__half*)Sr;
#pragma unroll
        for (int t = 0; t < 32; t++) {
            rowh[lane + t * 32] = __float2half_rn(v[t] * inv2);
        }
        __syncwarp();
        size_t Ab = ((size_t)b << 20) + ((size_t)(i0 + r) << 10);
        uint4* gh = (uint4*)&g_Af[Ab];
        const uint4* sh = (const uint4*)rowh;
#pragma unroll
        for (int it = 0; it < 4; it++) gh[lane + it * 32] = sh[lane + it * 32];
    }
}

// ---------------- fp16 tensor-core bmm: out = x + A @ SC (single term, k=64 stages) ----------------
#define BMM_OFF_AF 0
#define BMM_OFF_SH 36864
#define BMM_SMEM   71680
__global__ __launch_bounds__(256, 2) void bmm_kernel(const float* __restrict__ x,
                                                     float* __restrict__ out) {
    extern __shared__ char smc[];
    __half* Af_s = (__half*)(smc + BMM_OFF_AF);  // [2][128][72]
    __half* Sh_s = (__half*)(smc + BMM_OFF_SH);  // [2][64][136]
    int tid = threadIdx.x, w = tid >> 5, lane = tid & 31;
    int ct = blockIdx.x, mtb = blockIdx.y, b = blockIdx.z;
    int i0 = mtb * 128, c0 = ct * 128;

    const __half* Af = g_Af + ((size_t)b << 20) + (size_t)i0 * 1024;
    const __half* Shf = g_SChf + ((size_t)b << 18) + c0;

    float acc[4][4][4];
#pragma unroll
    for (int a = 0; a < 4; a++)
#pragma unroll
        for (int n = 0; n < 4; n++)
#pragma unroll
            for (int r = 0; r < 4; r++) acc[a][n][r] = 0.0f;

    int wm = w >> 2, wn = w & 3;
    int lrow = lane & 7, q1 = (lane >> 3) & 1, q2 = lane >> 4;

#define ISSUE(jc, bf_)                                                            \
    {                                                                             \
        for (int u_ = 0; u_ < 4; u_++) {                                          \
            int id_ = tid + u_ * 256;                                             \
            int ar_ = id_ >> 3, aseg_ = id_ & 7;                                  \
            cp16(smem_u32(&Af_s[(bf_) * 9216 + ar_ * 72 + aseg_ * 8]),            \
                 Af + (size_t)ar_ * 1024 + (jc) * 64 + aseg_ * 8);                \
            int sr_ = id_ >> 4, sseg_ = id_ & 15;                                 \
            cp16(smem_u32(&Sh_s[(bf_) * 8704 + sr_ * 136 + sseg_ * 8]),           \
                 Shf + (size_t)((jc) * 64 + sr_) * 256 + sseg_ * 8);              \
        }                                                                         \
        cp_commit();                                                              \
    }

    ISSUE(0, 0);
    ISSUE(1, 1);
    for (int cc = 0; cc < 16; cc++) {
        if (cc < 15) cp_wait1(); else cp_wait0();
        __syncthreads();
        int buf = cc & 1;
#pragma unroll
        for (int kk = 0; kk < 4; kk++) {
            uint32_t af[4][4];
#pragma unroll
            for (int mtl = 0; mtl < 4; mtl++) {
                int row = wm * 64 + mtl * 16 + lrow + q1 * 8;
                int col = kk * 16 + q2 * 8;
                ldm_x4(af[mtl], smem_u32(&Af_s[buf * 9216 + row * 72 + col]));
            }
            uint32_t bh[2][4];
#pragma unroll
            for (int ng = 0; ng < 2; ng++) {
                int row = kk * 16 + lrow + q1 * 8;
                int col = wn * 32 + ng * 16 + q2 * 8;
                ldm_x4_t(bh[ng], smem_u32(&Sh_s[buf * 8704 + row * 136 + col]));
            }
#pragma unroll
            for (int mtl = 0; mtl < 4; mtl++)
#pragma unroll
                for (int nt = 0; nt < 4; nt++)
                    mma16816h(acc[mtl][nt], af[mtl],
                              bh[nt >> 1][(nt & 1) * 2], bh[nt >> 1][(nt & 1) * 2 + 1]);
        }
        __syncthreads();
        if (cc + 2 < 16) ISSUE(cc + 2, cc & 1);
    }
#undef ISSUE

    int g = lane >> 2, t2 = lane & 3;
#pragma unroll
    for (int mtl = 0; mtl < 4; mtl++) {
#pragma unroll
        for (int nt = 0; nt < 4; nt++) {
            int row = i0 + wm * 64 + mtl * 16 + g;
            int col = c0 + wn * 32 + nt * 8 + 2 * t2;
            size_t o0 = ((size_t)b * 1024 + row) * 256 + col;
            size_t o1 = o0 + 8 * 256;
            float2 xv0 = *(const float2*)&x[o0];
            float2 xv1 = *(const float2*)&x[o1];
            *(float2*)&out[o0] = make_float2(xv0.x + acc[mtl][nt][0], xv0.y + acc[mtl][nt][1]);
            *(float2*)&out[o1] = make_float2(xv1.x + acc[mtl][nt][2], xv1.y + acc[mtl][nt][3]);
        }
    }
}

// ---------------- launch ----------------
extern "C" void kernel_launch(void* const* d_in, const int* in_sizes, int n_in,
                              void* d_out, int out_size) {
    const float* x      = (const float*)d_in[0];
    const float* emb_W  = (const float*)d_in[1];
    const float* emb_b  = (const float*)d_in[2];
    const float* attn_W = (const float*)d_in[3];
    const float* attn_b = (const float*)d_in[4];
    const float* thr_W  = (const float*)d_in[5];
    const float* thr_b  = (const float*)d_in[6];
    float* out = (float*)d_out;

    cudaFuncSetAttribute(front_kernel, cudaFuncAttributeMaxDynamicSharedMemorySize, FR_SMEM);
    cudaFuncSetAttribute(attn_A_kernel, cudaFuncAttributeMaxDynamicSharedMemorySize, ATTN_SMEM);
    cudaFuncSetAttribute(bmm_kernel, cudaFuncAttributeMaxDynamicSharedMemorySize, BMM_SMEM);

    prep_kernel<<<320, 256>>>(attn_W, emb_W, thr_W, attn_b, thr_b);
    xprep_kernel<<<BATCH * HW / 8, 256>>>(x);
    front_kernel<<<BATCH * HW / 64, 256, FR_SMEM>>>(attn_b, emb_b);
    attn_A_kernel<<<dim3(HW / 32, BATCH), 1024, ATTN_SMEM>>>();
    bmm_kernel<<<dim3(CDIM / 128, HW / 128, BATCH), 256, BMM_SMEM>>>(x, out);
}